// round 1
// baseline (speedup 1.0000x reference)
#include <cuda_runtime.h>
#include <cuda_bf16.h>
#include <cstdint>

#define N_NODES_MAX 100000
#define IN_CH 128
#define HIDDEN 256
#define N_EDGES_MAX 1600000

// ---------------- scratch (static device globals; no allocation) ----------------
__device__ float g_agg1[(size_t)N_NODES_MAX * IN_CH];    // 51.2 MB
__device__ float g_h   [(size_t)N_NODES_MAX * HIDDEN];   // 102.4 MB
__device__ float g_agg2[(size_t)N_NODES_MAX * HIDDEN];   // 102.4 MB
__device__ float g_z   [(size_t)N_NODES_MAX * HIDDEN];   // 102.4 MB
__device__ float g_deg [N_NODES_MAX];
__device__ float g_invdeg[N_NODES_MAX];
__device__ int   g_src[N_EDGES_MAX];
__device__ int   g_dst[N_EDGES_MAX];
__device__ int   g_ea [N_EDGES_MAX];
__device__ int   g_eb [N_EDGES_MAX];
__device__ int   g_is64;

// ---------------- dtype detection (int64 vs int32 edge indices) ----------------
__global__ void detect_kernel(const int* __restrict__ ei32) {
    __shared__ int bad;
    if (threadIdx.x == 0) bad = 0;
    __syncthreads();
    // If the data is really int64 (values < 2^31, nonneg), every odd int32 word is 0.
    for (int i = threadIdx.x; i < 2048; i += blockDim.x)
        if (ei32[2 * i + 1] != 0) bad = 1;
    __syncthreads();
    if (threadIdx.x == 0) g_is64 = bad ? 0 : 1;
}

__global__ void convert_kernel(const void* __restrict__ ei,
                               const void* __restrict__ edges,
                               int E, int E2) {
    int is64 = g_is64;
    int n = E > E2 ? E : E2;
    for (int e = blockIdx.x * blockDim.x + threadIdx.x; e < n;
         e += gridDim.x * blockDim.x) {
        if (e < E) {
            if (is64) {
                const long long* p = (const long long*)ei;
                g_src[e] = (int)p[e];
                g_dst[e] = (int)p[(size_t)e + E];
            } else {
                const int* p = (const int*)ei;
                g_src[e] = p[e];
                g_dst[e] = p[e + E];
            }
        }
        if (e < E2) {
            if (is64) {
                const long long* q = (const long long*)edges;
                g_ea[e] = (int)q[2 * (size_t)e];
                g_eb[e] = (int)q[2 * (size_t)e + 1];
            } else {
                const int* q = (const int*)edges;
                g_ea[e] = q[2 * e];
                g_eb[e] = q[2 * e + 1];
            }
        }
    }
}

// ---------------- zero scratch accumulators ----------------
__global__ void zero_all_kernel() {
    size_t tid = (size_t)blockIdx.x * blockDim.x + threadIdx.x;
    size_t stride = (size_t)gridDim.x * blockDim.x;
    float4 z4 = make_float4(0.f, 0.f, 0.f, 0.f);
    float4* a1 = (float4*)g_agg1;
    float4* a2 = (float4*)g_agg2;
    size_t n1 = (size_t)N_NODES_MAX * IN_CH / 4;
    size_t n2 = (size_t)N_NODES_MAX * HIDDEN / 4;
    for (size_t i = tid; i < n1; i += stride) a1[i] = z4;
    for (size_t i = tid; i < n2; i += stride) a2[i] = z4;
    for (size_t i = tid; i < N_NODES_MAX; i += stride) g_deg[i] = 0.f;
}

// ---------------- degree ----------------
__global__ void deg_kernel(int E) {
    for (int e = blockIdx.x * blockDim.x + threadIdx.x; e < E;
         e += gridDim.x * blockDim.x)
        atomicAdd(&g_deg[g_dst[e]], 1.0f);
}

__global__ void invdeg_kernel(int M) {
    int i = blockIdx.x * blockDim.x + threadIdx.x;
    if (i < M) g_invdeg[i] = 1.0f / fmaxf(g_deg[i], 1.0f);
}

// ---------------- vector reduction helper ----------------
__device__ __forceinline__ void red_add_v4(float* p, float4 v) {
    unsigned long long ga = (unsigned long long)__cvta_generic_to_global(p);
    asm volatile("red.global.add.v4.f32 [%0], {%1,%2,%3,%4};"
                 :: "l"(ga), "f"(v.x), "f"(v.y), "f"(v.z), "f"(v.w)
                 : "memory");
}

// ---------------- scatter-add: one warp per edge ----------------
__global__ void scatter1_kernel(const float* __restrict__ in, int E) {
    int w = (blockIdx.x * blockDim.x + threadIdx.x) >> 5;
    if (w >= E) return;
    int lane = threadIdx.x & 31;
    int s = g_src[w], d = g_dst[w];
    const float4* src = (const float4*)(in + (size_t)s * IN_CH);
    float* dstp = g_agg1 + (size_t)d * IN_CH;
    float4 v = src[lane];                 // 32 * float4 = 128 floats
    red_add_v4(dstp + lane * 4, v);
}

__global__ void scatter2_kernel(int E) {
    int w = (blockIdx.x * blockDim.x + threadIdx.x) >> 5;
    if (w >= E) return;
    int lane = threadIdx.x & 31;
    int s = g_src[w], d = g_dst[w];
    const float4* src = (const float4*)(g_h + (size_t)s * HIDDEN);
    float* dstp = g_agg2 + (size_t)d * HIDDEN;
#pragma unroll
    for (int i = lane; i < HIDDEN / 4; i += 32) {
        float4 v = src[i];
        red_add_v4(dstp + i * 4, v);
    }
}

// ---------------- fused SAGE layer GEMM ----------------
// Out[m, 0:256] = (Aagg[m,:] * invdeg[m]) @ Wl + Ax[m,:] @ Wr + b  (optional ReLU)
// BM=64, BN=64, BK=32, 256 threads, 4x4 register tile per thread.
#define BM 64
#define BN 64
#define BK 32

template <int LAYER>
__global__ void __launch_bounds__(256)
sage_gemm_kernel(const float* __restrict__ Ax_ext,
                 const float* __restrict__ Wl,
                 const float* __restrict__ Wr,
                 const float* __restrict__ bias,
                 int M) {
    constexpr int K = (LAYER == 1) ? IN_CH : HIDDEN;
    constexpr bool RELU = (LAYER == 1);
    const float* Aagg = (LAYER == 1) ? g_agg1 : g_agg2;
    const float* Ax   = (LAYER == 1) ? Ax_ext : g_h;
    float* Out        = (LAYER == 1) ? g_h    : g_z;

    __shared__ float As[BK][BM];
    __shared__ float Ws[BK][BN];

    int tid = threadIdx.x;
    int m0 = blockIdx.x * BM;
    int n0 = blockIdx.y * BN;
    int tx = tid & 15, ty = tid >> 4;

    float acc[4][4] = {};

#pragma unroll
    for (int part = 0; part < 2; part++) {
        const float* A = part ? Ax : Aagg;
        const float* W = part ? Wr : Wl;
        for (int k0 = 0; k0 < K; k0 += BK) {
            // ---- load A tile (transposed into As[k][m]) ----
            {
                int r = tid & 63;
                int grow = m0 + r;
                float s = 1.0f;
                if (!part) s = (grow < M) ? g_invdeg[grow] : 0.f;
#pragma unroll
                for (int it = 0; it < 2; it++) {
                    int kq = ((tid >> 6) << 2) + it * 16;  // 0,4,...,28
                    float4 v = make_float4(0.f, 0.f, 0.f, 0.f);
                    if (grow < M)
                        v = *(const float4*)(A + (size_t)grow * K + k0 + kq);
                    As[kq + 0][r] = v.x * s;
                    As[kq + 1][r] = v.y * s;
                    As[kq + 2][r] = v.z * s;
                    As[kq + 3][r] = v.w * s;
                }
            }
            // ---- load W tile ----
            {
                int n4 = (tid & 15) * 4;
#pragma unroll
                for (int it = 0; it < 2; it++) {
                    int kk = (tid >> 4) + it * 16;
                    float4 v = *(const float4*)(W + (size_t)(k0 + kk) * HIDDEN + n0 + n4);
                    *(float4*)&Ws[kk][n4] = v;
                }
            }
            __syncthreads();
#pragma unroll
            for (int kk = 0; kk < BK; kk++) {
                float4 a = *(const float4*)&As[kk][ty * 4];
                float4 w = *(const float4*)&Ws[kk][tx * 4];
                float av[4] = {a.x, a.y, a.z, a.w};
                float wv[4] = {w.x, w.y, w.z, w.w};
#pragma unroll
                for (int i = 0; i < 4; i++)
#pragma unroll
                    for (int j = 0; j < 4; j++)
                        acc[i][j] = fmaf(av[i], wv[j], acc[i][j]);
            }
            __syncthreads();
        }
    }

    // ---- epilogue ----
    float4 bv = *(const float4*)(bias + n0 + tx * 4);
#pragma unroll
    for (int i = 0; i < 4; i++) {
        int grow = m0 + ty * 4 + i;
        if (grow >= M) continue;
        float4 o;
        o.x = acc[i][0] + bv.x;
        o.y = acc[i][1] + bv.y;
        o.z = acc[i][2] + bv.z;
        o.w = acc[i][3] + bv.w;
        if (RELU) {
            o.x = fmaxf(o.x, 0.f); o.y = fmaxf(o.y, 0.f);
            o.z = fmaxf(o.z, 0.f); o.w = fmaxf(o.w, 0.f);
        }
        *(float4*)(Out + (size_t)grow * HIDDEN + n0 + tx * 4) = o;
    }
}

// ---------------- decoder: out[e] = dot(z[ea], z[eb]) ----------------
__global__ void decode_kernel(float* __restrict__ out, int E2) {
    int w = (blockIdx.x * blockDim.x + threadIdx.x) >> 5;
    if (w >= E2) return;
    int lane = threadIdx.x & 31;
    int a = g_ea[w], b = g_eb[w];
    const float4* za = (const float4*)(g_z + (size_t)a * HIDDEN);
    const float4* zb = (const float4*)(g_z + (size_t)b * HIDDEN);
    float acc = 0.f;
#pragma unroll
    for (int i = 0; i < 2; i++) {
        float4 va = za[lane + i * 32];
        float4 vb = zb[lane + i * 32];
        acc = fmaf(va.x, vb.x, acc);
        acc = fmaf(va.y, vb.y, acc);
        acc = fmaf(va.z, vb.z, acc);
        acc = fmaf(va.w, vb.w, acc);
    }
#pragma unroll
    for (int o = 16; o > 0; o >>= 1) acc += __shfl_xor_sync(0xffffffffu, acc, o);
    if (lane == 0) out[w] = acc;
}

// ---------------- launch ----------------
extern "C" void kernel_launch(void* const* d_in, const int* in_sizes, int n_in,
                              void* d_out, int out_size) {
    const float* x   = (const float*)d_in[0];
    const void*  ei  = d_in[1];
    const void*  edg = d_in[2];
    const float* W1l = (const float*)d_in[3];
    const float* b1  = (const float*)d_in[4];
    const float* W1r = (const float*)d_in[5];
    const float* W2l = (const float*)d_in[6];
    const float* b2  = (const float*)d_in[7];
    const float* W2r = (const float*)d_in[8];
    float* out = (float*)d_out;

    int M  = in_sizes[0] / IN_CH;   // 100000
    int E  = in_sizes[1] / 2;       // 1.6M graph edges
    int E2 = out_size;              // 1.6M candidate pairs

    detect_kernel<<<1, 256>>>((const int*)ei);
    convert_kernel<<<4096, 256>>>(ei, edg, E, E2);
    zero_all_kernel<<<2048, 256>>>();
    deg_kernel<<<2048, 256>>>(E);
    invdeg_kernel<<<(M + 255) / 256, 256>>>(M);

    // layer 1
    scatter1_kernel<<<(E * 32 + 255) / 256, 256>>>(x, E);
    {
        dim3 grid((M + BM - 1) / BM, HIDDEN / BN);
        sage_gemm_kernel<1><<<grid, 256>>>(x, W1l, W1r, b1, M);
    }
    // layer 2
    scatter2_kernel<<<(E * 32 + 255) / 256, 256>>>(E);
    {
        dim3 grid((M + BM - 1) / BM, HIDDEN / BN);
        sage_gemm_kernel<2><<<grid, 256>>>(nullptr, W2l, W2r, b2, M);
    }
    // decode
    decode_kernel<<<(E2 * 32 + 255) / 256, 256>>>(out, E2);
}

// round 3
// speedup vs baseline: 1.6856x; 1.6856x over previous
#include <cuda_runtime.h>
#include <cuda_bf16.h>
#include <cstdint>

#define N_NODES_MAX 100000
#define IN_CH 128
#define HIDDEN 256
#define N_EDGES_MAX 1600000

// ---------------- scratch (static device globals; no allocation) ----------------
__device__ float g_agg1[(size_t)N_NODES_MAX * IN_CH];    // 51.2 MB
__device__ float g_h   [(size_t)N_NODES_MAX * HIDDEN];   // 102.4 MB
__device__ float g_agg2[(size_t)N_NODES_MAX * HIDDEN];   // 102.4 MB
__device__ float g_z   [(size_t)N_NODES_MAX * HIDDEN];   // 102.4 MB
__device__ float g_deg [N_NODES_MAX];
__device__ float g_invdeg[N_NODES_MAX];
__device__ int   g_src[N_EDGES_MAX];
__device__ int   g_dst[N_EDGES_MAX];
__device__ int   g_ea [N_EDGES_MAX];
__device__ int   g_eb [N_EDGES_MAX];
__device__ int   g_is64;
// pre-transposed, tf32-rounded weights: Bt[n][k_cat]  (k_cat = [Wl rows ; Wr rows])
__device__ float g_Bt1[256 * 256];   // layer1: Kcat=256
__device__ float g_Bt2[256 * 512];   // layer2: Kcat=512

// ---------------- small PTX helpers (sm_80-level features only!) ----------------
__device__ __forceinline__ uint32_t smem_u32(const void* p) {
    uint32_t a;
    asm("{ .reg .u64 t; cvta.to.shared.u64 t, %1; cvt.u32.u64 %0, t; }" : "=r"(a) : "l"(p));
    return a;
}
__device__ __forceinline__ uint32_t rna_tf32(float f) {
    uint32_t r; asm("cvt.rna.tf32.f32 %0, %1;" : "=r"(r) : "f"(f)); return r;
}
__device__ __forceinline__ void sts128(uint32_t addr, uint4 v) {
    asm volatile("st.shared.v4.b32 [%0], {%1,%2,%3,%4};"
                 :: "r"(addr), "r"(v.x), "r"(v.y), "r"(v.z), "r"(v.w) : "memory");
}
__device__ __forceinline__ void cp_async16(uint32_t dst, const void* src) {
    asm volatile("cp.async.cg.shared.global [%0], [%1], 16;"
                 :: "r"(dst), "l"(src) : "memory");
}
__device__ __forceinline__ void cp_commit() {
    asm volatile("cp.async.commit_group;" ::: "memory");
}
template <int N>
__device__ __forceinline__ void cp_wait() {
    asm volatile("cp.async.wait_group %0;" :: "n"(N) : "memory");
}
__device__ __forceinline__ void ldsm4(uint32_t* r, uint32_t addr) {
    asm volatile("ldmatrix.sync.aligned.m8n8.x4.shared.b16 {%0,%1,%2,%3}, [%4];"
                 : "=r"(r[0]), "=r"(r[1]), "=r"(r[2]), "=r"(r[3]) : "r"(addr));
}
__device__ __forceinline__ void mma_tf32(float* c, const uint32_t* a,
                                         uint32_t b0, uint32_t b1) {
    asm volatile(
        "mma.sync.aligned.m16n8k8.row.col.f32.tf32.tf32.f32 "
        "{%0,%1,%2,%3}, {%4,%5,%6,%7}, {%8,%9}, {%0,%1,%2,%3};"
        : "+f"(c[0]), "+f"(c[1]), "+f"(c[2]), "+f"(c[3])
        : "r"(a[0]), "r"(a[1]), "r"(a[2]), "r"(a[3]), "r"(b0), "r"(b1));
}

// ---------------- dtype detection (int64 vs int32 edge indices) ----------------
__global__ void detect_kernel(const int* __restrict__ ei32) {
    __shared__ int bad;
    if (threadIdx.x == 0) bad = 0;
    __syncthreads();
    for (int i = threadIdx.x; i < 2048; i += blockDim.x)
        if (ei32[2 * i + 1] != 0) bad = 1;
    __syncthreads();
    if (threadIdx.x == 0) g_is64 = bad ? 0 : 1;
}

__global__ void convert_kernel(const void* __restrict__ ei,
                               const void* __restrict__ edges,
                               int E, int E2) {
    int is64 = g_is64;
    int n = E > E2 ? E : E2;
    for (int e = blockIdx.x * blockDim.x + threadIdx.x; e < n;
         e += gridDim.x * blockDim.x) {
        if (e < E) {
            if (is64) {
                const long long* p = (const long long*)ei;
                g_src[e] = (int)p[e];
                g_dst[e] = (int)p[(size_t)e + E];
            } else {
                const int* p = (const int*)ei;
                g_src[e] = p[e];
                g_dst[e] = p[e + E];
            }
        }
        if (e < E2) {
            if (is64) {
                const long long* q = (const long long*)edges;
                g_ea[e] = (int)q[2 * (size_t)e];
                g_eb[e] = (int)q[2 * (size_t)e + 1];
            } else {
                const int* q = (const int*)edges;
                g_ea[e] = q[2 * e];
                g_eb[e] = q[2 * e + 1];
            }
        }
    }
}

__global__ void zero_all_kernel() {
    size_t tid = (size_t)blockIdx.x * blockDim.x + threadIdx.x;
    size_t stride = (size_t)gridDim.x * blockDim.x;
    float4 z4 = make_float4(0.f, 0.f, 0.f, 0.f);
    float4* a1 = (float4*)g_agg1;
    float4* a2 = (float4*)g_agg2;
    size_t n1 = (size_t)N_NODES_MAX * IN_CH / 4;
    size_t n2 = (size_t)N_NODES_MAX * HIDDEN / 4;
    for (size_t i = tid; i < n1; i += stride) a1[i] = z4;
    for (size_t i = tid; i < n2; i += stride) a2[i] = z4;
    for (size_t i = tid; i < N_NODES_MAX; i += stride) g_deg[i] = 0.f;
}

__global__ void deg_kernel(int E) {
    for (int e = blockIdx.x * blockDim.x + threadIdx.x; e < E;
         e += gridDim.x * blockDim.x)
        atomicAdd(&g_deg[g_dst[e]], 1.0f);
}

__global__ void invdeg_kernel(int M) {
    int i = blockIdx.x * blockDim.x + threadIdx.x;
    if (i < M) g_invdeg[i] = 1.0f / fmaxf(g_deg[i], 1.0f);
}

// weights -> transposed, concatenated, tf32-rounded: Bt[n][kcat]
__global__ void prep_weights(const float* __restrict__ W1l, const float* __restrict__ W1r,
                             const float* __restrict__ W2l, const float* __restrict__ W2r) {
    int i = blockIdx.x * blockDim.x + threadIdx.x;
    if (i < 256 * 256) {
        int n = i >> 8, k = i & 255;
        float v = (k < 128) ? W1l[k * HIDDEN + n] : W1r[(k - 128) * HIDDEN + n];
        g_Bt1[n * 256 + k] = __uint_as_float(rna_tf32(v));
    }
    if (i < 256 * 512) {
        int n = i >> 9, k = i & 511;
        float v = (k < 256) ? W2l[k * HIDDEN + n] : W2r[(k - 256) * HIDDEN + n];
        g_Bt2[n * 512 + k] = __uint_as_float(rna_tf32(v));
    }
}

// ---------------- scatter-add ----------------
__device__ __forceinline__ void red_add_v4(float* p, float4 v) {
    unsigned long long ga = (unsigned long long)__cvta_generic_to_global(p);
    asm volatile("red.global.add.v4.f32 [%0], {%1,%2,%3,%4};"
                 :: "l"(ga), "f"(v.x), "f"(v.y), "f"(v.z), "f"(v.w)
                 : "memory");
}

__global__ void scatter1_kernel(const float* __restrict__ in, int E) {
    int w = (blockIdx.x * blockDim.x + threadIdx.x) >> 5;
    if (w >= E) return;
    int lane = threadIdx.x & 31;
    int s = g_src[w], d = g_dst[w];
    const float4* src = (const float4*)(in + (size_t)s * IN_CH);
    float* dstp = g_agg1 + (size_t)d * IN_CH;
    float4 v = src[lane];
    red_add_v4(dstp + lane * 4, v);
}

__global__ void scatter2_kernel(int E) {
    int w = (blockIdx.x * blockDim.x + threadIdx.x) >> 5;
    if (w >= E) return;
    int lane = threadIdx.x & 31;
    int s = g_src[w], d = g_dst[w];
    const float4* src = (const float4*)(g_h + (size_t)s * HIDDEN);
    float* dstp = g_agg2 + (size_t)d * HIDDEN;
#pragma unroll
    for (int i = lane; i < HIDDEN / 4; i += 32) {
        float4 v = src[i];
        red_add_v4(dstp + i * 4, v);
    }
}

// ---------------- mma.sync tf32 fused SAGE GEMM ----------------
// Out[m,0:256] = (A0[m,:]*invdeg[m]) @ Wl + A1[m,:] @ Wr + b  (opt ReLU)
// CTA: 128 rows x 256 cols, 8 warps (2x4), warp tile 64x64, BK=32.
// A smem: [128][36] floats (row pad 144B), B smem: [256][36] floats.
#define A_STAGE 18432u
#define B_STAGE 36864u
#define GEMM_DSMEM (2 * (A_STAGE + B_STAGE))

template <int KPART, bool RELU>
__global__ void __launch_bounds__(256, 1)
sage_gemm_mma(const float* __restrict__ A0, const float* __restrict__ A1,
              const float* __restrict__ Bt, const float* __restrict__ bias,
              float* __restrict__ Out, int M)
{
    constexpr int KCAT = 2 * KPART;
    constexpr int NC = KCAT / 32;
    extern __shared__ char sm[];
    const uint32_t smbase = smem_u32(sm);
    const uint32_t Aoff[2] = {0u, A_STAGE};
    const uint32_t Boff[2] = {2 * A_STAGE, 2 * A_STAGE + B_STAGE};

    int tid = threadIdx.x, lane = tid & 31, wid = tid >> 5;
    int m0 = blockIdx.x * 128;
    int warp_m = (wid >> 2) * 64, warp_n = (wid & 3) * 64;

    // A global->reg mapping: thread handles row tid>>1, 16 floats at col (tid&1)*16
    int arow = tid >> 1;
    int acol = (tid & 1) * 16;
    int grow = m0 + arow;
    bool avalid = grow < M;
    float sdeg = avalid ? g_invdeg[grow] : 0.f;

    float acc[4][8][4] = {};

    auto ldgA = [&](int ci, float4* r) {
        bool p1 = (ci * 32) >= KPART;
        const float* A = p1 ? A1 : A0;
        int kof = p1 ? ci * 32 - KPART : ci * 32;
        if (avalid) {
            const float4* src = (const float4*)(A + (size_t)grow * KPART + kof + acol);
            r[0] = src[0]; r[1] = src[1]; r[2] = src[2]; r[3] = src[3];
            if (!p1) {
#pragma unroll
                for (int i = 0; i < 4; i++) {
                    r[i].x *= sdeg; r[i].y *= sdeg; r[i].z *= sdeg; r[i].w *= sdeg;
                }
            }
        } else {
#pragma unroll
            for (int i = 0; i < 4; i++) r[i] = make_float4(0.f, 0.f, 0.f, 0.f);
        }
    };
    auto stsA = [&](int buf, const float4* r) {
        uint32_t a = smbase + Aoff[buf] + arow * 144 + acol * 4;
#pragma unroll
        for (int i = 0; i < 4; i++) {
            uint4 u;
            u.x = rna_tf32(r[i].x); u.y = rna_tf32(r[i].y);
            u.z = rna_tf32(r[i].z); u.w = rna_tf32(r[i].w);
            sts128(a + i * 16, u);
        }
    };
    auto cpB = [&](int ci, int buf) {
#pragma unroll
        for (int rr = 0; rr < 8; rr++) {
            int i = tid + 256 * rr;
            int n = i >> 3, kq = i & 7;
            uint32_t dst = smbase + Boff[buf] + n * 144 + kq * 16;
            const float* src = Bt + (size_t)n * KCAT + ci * 32 + kq * 4;
            cp_async16(dst, src);
        }
        cp_commit();
    };
    auto compute = [&](int buf) {
        uint32_t Ab = smbase + Aoff[buf] +
                      (warp_m + (lane & 15)) * 144 + ((lane & 16) ? 16 : 0);
        uint32_t Bb = smbase + Boff[buf] +
                      (warp_n + (lane & 7) + ((lane & 16) >> 1)) * 144 +
                      ((lane & 8) ? 16 : 0);
#pragma unroll
        for (int kk = 0; kk < 4; kk++) {
            uint32_t af[4][4];
#pragma unroll
            for (int ti = 0; ti < 4; ti++) ldsm4(af[ti], Ab + ti * 16 * 144 + kk * 32);
            uint32_t bf[4][4];
#pragma unroll
            for (int tjp = 0; tjp < 4; tjp++) ldsm4(bf[tjp], Bb + tjp * 16 * 144 + kk * 32);
#pragma unroll
            for (int ti = 0; ti < 4; ti++)
#pragma unroll
                for (int tjp = 0; tjp < 4; tjp++) {
                    mma_tf32(acc[ti][2 * tjp],     af[ti], bf[tjp][0], bf[tjp][1]);
                    mma_tf32(acc[ti][2 * tjp + 1], af[ti], bf[tjp][2], bf[tjp][3]);
                }
        }
    };

    float4 areg[4];
    ldgA(0, areg);
    cpB(0, 0);
    stsA(0, areg);

    for (int ci = 0; ci < NC; ci++) {
        int cb = ci & 1;
        float4 areg2[4];
        if (ci + 1 < NC) {
            ldgA(ci + 1, areg2);
            cpB(ci + 1, cb ^ 1);
            cp_wait<1>();
        } else {
            cp_wait<0>();
        }
        __syncthreads();
        compute(cb);
        __syncthreads();
        if (ci + 1 < NC) stsA(cb ^ 1, areg2);
    }

    // epilogue: acc -> global with bias (+relu)
    int r0base = m0 + warp_m + (lane >> 2);
    int colb = warp_n + (lane & 3) * 2;
#pragma unroll
    for (int tj = 0; tj < 8; tj++) {
        int col = colb + tj * 8;
        float2 b2 = *(const float2*)(bias + col);
#pragma unroll
        for (int ti = 0; ti < 4; ti++) {
            int r0 = r0base + ti * 16;
            int r1 = r0 + 8;
            if (r0 < M) {
                float2 v;
                v.x = acc[ti][tj][0] + b2.x;
                v.y = acc[ti][tj][1] + b2.y;
                if (RELU) { v.x = fmaxf(v.x, 0.f); v.y = fmaxf(v.y, 0.f); }
                *(float2*)(Out + (size_t)r0 * HIDDEN + col) = v;
            }
            if (r1 < M) {
                float2 v;
                v.x = acc[ti][tj][2] + b2.x;
                v.y = acc[ti][tj][3] + b2.y;
                if (RELU) { v.x = fmaxf(v.x, 0.f); v.y = fmaxf(v.y, 0.f); }
                *(float2*)(Out + (size_t)r1 * HIDDEN + col) = v;
            }
        }
    }
}

// ---------------- decoder ----------------
__global__ void decode_kernel(float* __restrict__ out, int E2) {
    int w = (blockIdx.x * blockDim.x + threadIdx.x) >> 5;
    if (w >= E2) return;
    int lane = threadIdx.x & 31;
    int a = g_ea[w], b = g_eb[w];
    const float4* za = (const float4*)(g_z + (size_t)a * HIDDEN);
    const float4* zb = (const float4*)(g_z + (size_t)b * HIDDEN);
    float acc = 0.f;
#pragma unroll
    for (int i = 0; i < 2; i++) {
        float4 va = za[lane + i * 32];
        float4 vb = zb[lane + i * 32];
        acc = fmaf(va.x, vb.x, acc);
        acc = fmaf(va.y, vb.y, acc);
        acc = fmaf(va.z, vb.z, acc);
        acc = fmaf(va.w, vb.w, acc);
    }
#pragma unroll
    for (int o = 16; o > 0; o >>= 1) acc += __shfl_xor_sync(0xffffffffu, acc, o);
    if (lane == 0) out[w] = acc;
}

// ---------------- launch ----------------
extern "C" void kernel_launch(void* const* d_in, const int* in_sizes, int n_in,
                              void* d_out, int out_size) {
    const float* x   = (const float*)d_in[0];
    const void*  ei  = d_in[1];
    const void*  edg = d_in[2];
    const float* W1l = (const float*)d_in[3];
    const float* b1  = (const float*)d_in[4];
    const float* W1r = (const float*)d_in[5];
    const float* W2l = (const float*)d_in[6];
    const float* b2  = (const float*)d_in[7];
    const float* W2r = (const float*)d_in[8];
    float* out = (float*)d_out;

    int M  = in_sizes[0] / IN_CH;   // 100000
    int E  = in_sizes[1] / 2;       // 1.6M graph edges
    int E2 = out_size;              // 1.6M candidate pairs

    cudaFuncSetAttribute(sage_gemm_mma<128, true>,
                         cudaFuncAttributeMaxDynamicSharedMemorySize, GEMM_DSMEM);
    cudaFuncSetAttribute(sage_gemm_mma<256, false>,
                         cudaFuncAttributeMaxDynamicSharedMemorySize, GEMM_DSMEM);

    float* agg1p; cudaGetSymbolAddress((void**)&agg1p, g_agg1);
    float* agg2p; cudaGetSymbolAddress((void**)&agg2p, g_agg2);
    float* hp;    cudaGetSymbolAddress((void**)&hp,    g_h);
    float* zp;    cudaGetSymbolAddress((void**)&zp,    g_z);
    float* bt1p;  cudaGetSymbolAddress((void**)&bt1p,  g_Bt1);
    float* bt2p;  cudaGetSymbolAddress((void**)&bt2p,  g_Bt2);

    detect_kernel<<<1, 256>>>((const int*)ei);
    convert_kernel<<<4096, 256>>>(ei, edg, E, E2);
    zero_all_kernel<<<2048, 256>>>();
    deg_kernel<<<2048, 256>>>(E);
    invdeg_kernel<<<(M + 255) / 256, 256>>>(M);
    prep_weights<<<512, 256>>>(W1l, W1r, W2l, W2r);

    int gtiles = (M + 127) / 128;

    // layer 1
    scatter1_kernel<<<(E * 32 + 255) / 256, 256>>>(x, E);
    sage_gemm_mma<128, true><<<gtiles, 256, GEMM_DSMEM>>>(agg1p, x, bt1p, b1, hp, M);
    // layer 2
    scatter2_kernel<<<(E * 32 + 255) / 256, 256>>>(E);
    sage_gemm_mma<256, false><<<gtiles, 256, GEMM_DSMEM>>>(agg2p, hp, bt2p, b2, zp, M);
    // decode
    decode_kernel<<<(E2 * 32 + 255) / 256, 256>>>(out, E2);
}

// round 4
// speedup vs baseline: 2.5344x; 1.5035x over previous
#include <cuda_runtime.h>
#include <cuda_bf16.h>
#include <cstdint>

#define N_NODES_MAX 100000
#define IN_CH 128
#define HIDDEN 256
#define N_EDGES_MAX 1600000

// ---------------- scratch (static device globals; no allocation) ----------------
__device__ float g_agg1[(size_t)N_NODES_MAX * IN_CH];    // 51.2 MB
__device__ float g_h   [(size_t)N_NODES_MAX * HIDDEN];   // 102.4 MB
__device__ float g_agg2[(size_t)N_NODES_MAX * HIDDEN];   // 102.4 MB
__device__ float g_z   [(size_t)N_NODES_MAX * HIDDEN];   // 102.4 MB
__device__ float g_invdeg[N_NODES_MAX];
__device__ int   g_src[N_EDGES_MAX];
__device__ int   g_dst[N_EDGES_MAX];
__device__ int   g_ea [N_EDGES_MAX];
__device__ int   g_eb [N_EDGES_MAX];
__device__ int   g_is64;
// CSR
__device__ int   g_cnt[N_NODES_MAX];
__device__ int   g_rowstart[N_NODES_MAX];
__device__ int   g_cursor[N_NODES_MAX];
__device__ int   g_csrc[N_EDGES_MAX];
__device__ int   g_partial[512];
// pre-transposed, tf32-rounded weights: Bt[n][k_cat]  (k_cat = [Wl rows ; Wr rows])
__device__ float g_Bt1[256 * 256];   // layer1: Kcat=256
__device__ float g_Bt2[256 * 512];   // layer2: Kcat=512

// ---------------- small PTX helpers (sm_80-level features only) ----------------
__device__ __forceinline__ uint32_t smem_u32(const void* p) {
    uint32_t a;
    asm("{ .reg .u64 t; cvta.to.shared.u64 t, %1; cvt.u32.u64 %0, t; }" : "=r"(a) : "l"(p));
    return a;
}
__device__ __forceinline__ uint32_t rna_tf32(float f) {
    uint32_t r; asm("cvt.rna.tf32.f32 %0, %1;" : "=r"(r) : "f"(f)); return r;
}
__device__ __forceinline__ void sts128(uint32_t addr, uint4 v) {
    asm volatile("st.shared.v4.b32 [%0], {%1,%2,%3,%4};"
                 :: "r"(addr), "r"(v.x), "r"(v.y), "r"(v.z), "r"(v.w) : "memory");
}
__device__ __forceinline__ void cp_async16(uint32_t dst, const void* src) {
    asm volatile("cp.async.cg.shared.global [%0], [%1], 16;"
                 :: "r"(dst), "l"(src) : "memory");
}
__device__ __forceinline__ void cp_commit() {
    asm volatile("cp.async.commit_group;" ::: "memory");
}
template <int N>
__device__ __forceinline__ void cp_wait() {
    asm volatile("cp.async.wait_group %0;" :: "n"(N) : "memory");
}
__device__ __forceinline__ void ldsm4(uint32_t* r, uint32_t addr) {
    asm volatile("ldmatrix.sync.aligned.m8n8.x4.shared.b16 {%0,%1,%2,%3}, [%4];"
                 : "=r"(r[0]), "=r"(r[1]), "=r"(r[2]), "=r"(r[3]) : "r"(addr));
}
__device__ __forceinline__ void mma_tf32(float* c, const uint32_t* a,
                                         uint32_t b0, uint32_t b1) {
    asm volatile(
        "mma.sync.aligned.m16n8k8.row.col.f32.tf32.tf32.f32 "
        "{%0,%1,%2,%3}, {%4,%5,%6,%7}, {%8,%9}, {%0,%1,%2,%3};"
        : "+f"(c[0]), "+f"(c[1]), "+f"(c[2]), "+f"(c[3])
        : "r"(a[0]), "r"(a[1]), "r"(a[2]), "r"(a[3]), "r"(b0), "r"(b1));
}

// ---------------- dtype detection (int64 vs int32 edge indices) ----------------
__global__ void detect_kernel(const int* __restrict__ ei32) {
    __shared__ int bad;
    if (threadIdx.x == 0) bad = 0;
    __syncthreads();
    for (int i = threadIdx.x; i < 2048; i += blockDim.x)
        if (ei32[2 * i + 1] != 0) bad = 1;
    __syncthreads();
    if (threadIdx.x == 0) g_is64 = bad ? 0 : 1;
}

__global__ void zero_cnt_kernel(int M) {
    int i = blockIdx.x * blockDim.x + threadIdx.x;
    if (i < M) g_cnt[i] = 0;
}

// convert + histogram fused
__global__ void convert_kernel(const void* __restrict__ ei,
                               const void* __restrict__ edges,
                               int E, int E2) {
    int is64 = g_is64;
    int n = E > E2 ? E : E2;
    for (int e = blockIdx.x * blockDim.x + threadIdx.x; e < n;
         e += gridDim.x * blockDim.x) {
        if (e < E) {
            int s, d;
            if (is64) {
                const long long* p = (const long long*)ei;
                s = (int)p[e];
                d = (int)p[(size_t)e + E];
            } else {
                const int* p = (const int*)ei;
                s = p[e];
                d = p[e + E];
            }
            g_src[e] = s;
            g_dst[e] = d;
            atomicAdd(&g_cnt[d], 1);
        }
        if (e < E2) {
            if (is64) {
                const long long* q = (const long long*)edges;
                g_ea[e] = (int)q[2 * (size_t)e];
                g_eb[e] = (int)q[2 * (size_t)e + 1];
            } else {
                const int* q = (const int*)edges;
                g_ea[e] = q[2 * e];
                g_eb[e] = q[2 * e + 1];
            }
        }
    }
}

// ---------------- CSR build: 2-level exclusive scan + cursor scatter ----------------
#define SCAN_BLK 256

__global__ void scan1_kernel(int M) {
    __shared__ int sd[SCAN_BLK];
    int i = blockIdx.x * SCAN_BLK + threadIdx.x;
    sd[threadIdx.x] = (i < M) ? g_cnt[i] : 0;
    __syncthreads();
#pragma unroll
    for (int s = SCAN_BLK / 2; s > 0; s >>= 1) {
        if (threadIdx.x < s) sd[threadIdx.x] += sd[threadIdx.x + s];
        __syncthreads();
    }
    if (threadIdx.x == 0) g_partial[blockIdx.x] = sd[0];
}

__global__ void scan2_kernel(int nb) {
    __shared__ int sd[512];
    int t = threadIdx.x;
    sd[t] = (t < nb) ? g_partial[t] : 0;
    __syncthreads();
#pragma unroll
    for (int off = 1; off < 512; off <<= 1) {
        int v = (t >= off) ? sd[t - off] : 0;
        __syncthreads();
        sd[t] += v;
        __syncthreads();
    }
    if (t < nb) g_partial[t] = (t == 0) ? 0 : sd[t - 1];
}

__global__ void scan3_kernel(int M) {
    __shared__ int sd[SCAN_BLK];
    int i = blockIdx.x * SCAN_BLK + threadIdx.x;
    int cnt = (i < M) ? g_cnt[i] : 0;
    sd[threadIdx.x] = cnt;
    __syncthreads();
#pragma unroll
    for (int off = 1; off < SCAN_BLK; off <<= 1) {
        int v = (threadIdx.x >= off) ? sd[threadIdx.x - off] : 0;
        __syncthreads();
        sd[threadIdx.x] += v;
        __syncthreads();
    }
    if (i < M) {
        int start = g_partial[blockIdx.x] + sd[threadIdx.x] - cnt;
        g_rowstart[i] = start;
        g_cursor[i] = start;
        g_invdeg[i] = 1.0f / fmaxf((float)cnt, 1.0f);
    }
}

__global__ void fill_kernel(int E) {
    for (int e = blockIdx.x * blockDim.x + threadIdx.x; e < E;
         e += gridDim.x * blockDim.x) {
        int d = g_dst[e];
        int pos = atomicAdd(&g_cursor[d], 1);
        g_csrc[pos] = g_src[e];
    }
}
// after fill_kernel: g_cursor[n] == row end

// weights -> transposed, concatenated, tf32-rounded: Bt[n][kcat]
__global__ void prep_weights(const float* __restrict__ W1l, const float* __restrict__ W1r,
                             const float* __restrict__ W2l, const float* __restrict__ W2r) {
    int i = blockIdx.x * blockDim.x + threadIdx.x;
    if (i < 256 * 256) {
        int n = i >> 8, k = i & 255;
        float v = (k < 128) ? W1l[k * HIDDEN + n] : W1r[(k - 128) * HIDDEN + n];
        g_Bt1[n * 256 + k] = __uint_as_float(rna_tf32(v));
    }
    if (i < 256 * 512) {
        int n = i >> 9, k = i & 511;
        float v = (k < 256) ? W2l[k * HIDDEN + n] : W2r[(k - 256) * HIDDEN + n];
        g_Bt2[n * 512 + k] = __uint_as_float(rna_tf32(v));
    }
}

// ---------------- gather aggregation (warp per node) ----------------
__global__ void gather1_kernel(const float* __restrict__ x, int M) {
    int w = (blockIdx.x * blockDim.x + threadIdx.x) >> 5;
    if (w >= M) return;
    int lane = threadIdx.x & 31;
    int e0 = g_rowstart[w], e1 = g_cursor[w];
    float4 acc = make_float4(0.f, 0.f, 0.f, 0.f);
    for (int e = e0; e < e1; e++) {
        int s = g_csrc[e];
        float4 v = *(const float4*)(x + (size_t)s * IN_CH + lane * 4);
        acc.x += v.x; acc.y += v.y; acc.z += v.z; acc.w += v.w;
    }
    *(float4*)(g_agg1 + (size_t)w * IN_CH + lane * 4) = acc;
}

__global__ void gather2_kernel(int M) {
    int w = (blockIdx.x * blockDim.x + threadIdx.x) >> 5;
    if (w >= M) return;
    int lane = threadIdx.x & 31;
    int e0 = g_rowstart[w], e1 = g_cursor[w];
    float4 a0 = make_float4(0.f, 0.f, 0.f, 0.f);
    float4 a1 = a0;
    const float* base = g_h + lane * 4;
    for (int e = e0; e < e1; e++) {
        int s = g_csrc[e];
        const float* row = base + (size_t)s * HIDDEN;
        float4 v0 = *(const float4*)(row);
        float4 v1 = *(const float4*)(row + 128);
        a0.x += v0.x; a0.y += v0.y; a0.z += v0.z; a0.w += v0.w;
        a1.x += v1.x; a1.y += v1.y; a1.z += v1.z; a1.w += v1.w;
    }
    float* outp = g_agg2 + (size_t)w * HIDDEN + lane * 4;
    *(float4*)(outp) = a0;
    *(float4*)(outp + 128) = a1;
}

// ---------------- mma.sync tf32 fused SAGE GEMM ----------------
// Out[m,0:256] = (A0[m,:]*invdeg[m]) @ Wl + A1[m,:] @ Wr + b  (opt ReLU)
#define A_STAGE 18432u
#define B_STAGE 36864u
#define GEMM_DSMEM (2 * (A_STAGE + B_STAGE))

template <int KPART, bool RELU>
__global__ void __launch_bounds__(256, 1)
sage_gemm_mma(const float* __restrict__ A0, const float* __restrict__ A1,
              const float* __restrict__ Bt, const float* __restrict__ bias,
              float* __restrict__ Out, int M)
{
    constexpr int KCAT = 2 * KPART;
    constexpr int NC = KCAT / 32;
    extern __shared__ char sm[];
    const uint32_t smbase = smem_u32(sm);
    const uint32_t Aoff[2] = {0u, A_STAGE};
    const uint32_t Boff[2] = {2 * A_STAGE, 2 * A_STAGE + B_STAGE};

    int tid = threadIdx.x, lane = tid & 31, wid = tid >> 5;
    int m0 = blockIdx.x * 128;
    int warp_m = (wid >> 2) * 64, warp_n = (wid & 3) * 64;

    int arow = tid >> 1;
    int acol = (tid & 1) * 16;
    int grow = m0 + arow;
    bool avalid = grow < M;
    float sdeg = avalid ? g_invdeg[grow] : 0.f;

    float acc[4][8][4] = {};

    auto ldgA = [&](int ci, float4* r) {
        bool p1 = (ci * 32) >= KPART;
        const float* A = p1 ? A1 : A0;
        int kof = p1 ? ci * 32 - KPART : ci * 32;
        if (avalid) {
            const float4* src = (const float4*)(A + (size_t)grow * KPART + kof + acol);
            r[0] = src[0]; r[1] = src[1]; r[2] = src[2]; r[3] = src[3];
            if (!p1) {
#pragma unroll
                for (int i = 0; i < 4; i++) {
                    r[i].x *= sdeg; r[i].y *= sdeg; r[i].z *= sdeg; r[i].w *= sdeg;
                }
            }
        } else {
#pragma unroll
            for (int i = 0; i < 4; i++) r[i] = make_float4(0.f, 0.f, 0.f, 0.f);
        }
    };
    auto stsA = [&](int buf, const float4* r) {
        uint32_t a = smbase + Aoff[buf] + arow * 144 + acol * 4;
#pragma unroll
        for (int i = 0; i < 4; i++) {
            uint4 u;
            u.x = rna_tf32(r[i].x); u.y = rna_tf32(r[i].y);
            u.z = rna_tf32(r[i].z); u.w = rna_tf32(r[i].w);
            sts128(a + i * 16, u);
        }
    };
    auto cpB = [&](int ci, int buf) {
#pragma unroll
        for (int rr = 0; rr < 8; rr++) {
            int i = tid + 256 * rr;
            int n = i >> 3, kq = i & 7;
            uint32_t dst = smbase + Boff[buf] + n * 144 + kq * 16;
            const float* src = Bt + (size_t)n * KCAT + ci * 32 + kq * 4;
            cp_async16(dst, src);
        }
        cp_commit();
    };
    auto compute = [&](int buf) {
        uint32_t Ab = smbase + Aoff[buf] +
                      (warp_m + (lane & 15)) * 144 + ((lane & 16) ? 16 : 0);
        uint32_t Bb = smbase + Boff[buf] +
                      (warp_n + (lane & 7) + ((lane & 16) >> 1)) * 144 +
                      ((lane & 8) ? 16 : 0);
#pragma unroll
        for (int kk = 0; kk < 4; kk++) {
            uint32_t af[4][4];
#pragma unroll
            for (int ti = 0; ti < 4; ti++) ldsm4(af[ti], Ab + ti * 16 * 144 + kk * 32);
            uint32_t bf[4][4];
#pragma unroll
            for (int tjp = 0; tjp < 4; tjp++) ldsm4(bf[tjp], Bb + tjp * 16 * 144 + kk * 32);
#pragma unroll
            for (int ti = 0; ti < 4; ti++)
#pragma unroll
                for (int tjp = 0; tjp < 4; tjp++) {
                    mma_tf32(acc[ti][2 * tjp],     af[ti], bf[tjp][0], bf[tjp][1]);
                    mma_tf32(acc[ti][2 * tjp + 1], af[ti], bf[tjp][2], bf[tjp][3]);
                }
        }
    };

    float4 areg[4];
    ldgA(0, areg);
    cpB(0, 0);
    stsA(0, areg);

    for (int ci = 0; ci < NC; ci++) {
        int cb = ci & 1;
        float4 areg2[4];
        if (ci + 1 < NC) {
            ldgA(ci + 1, areg2);
            cpB(ci + 1, cb ^ 1);
            cp_wait<1>();
        } else {
            cp_wait<0>();
        }
        __syncthreads();
        compute(cb);
        __syncthreads();
        if (ci + 1 < NC) stsA(cb ^ 1, areg2);
    }

    int r0base = m0 + warp_m + (lane >> 2);
    int colb = warp_n + (lane & 3) * 2;
#pragma unroll
    for (int tj = 0; tj < 8; tj++) {
        int col = colb + tj * 8;
        float2 b2 = *(const float2*)(bias + col);
#pragma unroll
        for (int ti = 0; ti < 4; ti++) {
            int r0 = r0base + ti * 16;
            int r1 = r0 + 8;
            if (r0 < M) {
                float2 v;
                v.x = acc[ti][tj][0] + b2.x;
                v.y = acc[ti][tj][1] + b2.y;
                if (RELU) { v.x = fmaxf(v.x, 0.f); v.y = fmaxf(v.y, 0.f); }
                *(float2*)(Out + (size_t)r0 * HIDDEN + col) = v;
            }
            if (r1 < M) {
                float2 v;
                v.x = acc[ti][tj][2] + b2.x;
                v.y = acc[ti][tj][3] + b2.y;
                if (RELU) { v.x = fmaxf(v.x, 0.f); v.y = fmaxf(v.y, 0.f); }
                *(float2*)(Out + (size_t)r1 * HIDDEN + col) = v;
            }
        }
    }
}

// ---------------- decoder ----------------
__global__ void decode_kernel(float* __restrict__ out, int E2) {
    int w = (blockIdx.x * blockDim.x + threadIdx.x) >> 5;
    if (w >= E2) return;
    int lane = threadIdx.x & 31;
    int a = g_ea[w], b = g_eb[w];
    const float4* za = (const float4*)(g_z + (size_t)a * HIDDEN);
    const float4* zb = (const float4*)(g_z + (size_t)b * HIDDEN);
    float acc = 0.f;
#pragma unroll
    for (int i = 0; i < 2; i++) {
        float4 va = za[lane + i * 32];
        float4 vb = zb[lane + i * 32];
        acc = fmaf(va.x, vb.x, acc);
        acc = fmaf(va.y, vb.y, acc);
        acc = fmaf(va.z, vb.z, acc);
        acc = fmaf(va.w, vb.w, acc);
    }
#pragma unroll
    for (int o = 16; o > 0; o >>= 1) acc += __shfl_xor_sync(0xffffffffu, acc, o);
    if (lane == 0) out[w] = acc;
}

// ---------------- launch ----------------
extern "C" void kernel_launch(void* const* d_in, const int* in_sizes, int n_in,
                              void* d_out, int out_size) {
    const float* x   = (const float*)d_in[0];
    const void*  ei  = d_in[1];
    const void*  edg = d_in[2];
    const float* W1l = (const float*)d_in[3];
    const float* b1  = (const float*)d_in[4];
    const float* W1r = (const float*)d_in[5];
    const float* W2l = (const float*)d_in[6];
    const float* b2  = (const float*)d_in[7];
    const float* W2r = (const float*)d_in[8];
    float* out = (float*)d_out;

    int M  = in_sizes[0] / IN_CH;   // 100000
    int E  = in_sizes[1] / 2;       // 1.6M graph edges
    int E2 = out_size;              // 1.6M candidate pairs

    cudaFuncSetAttribute(sage_gemm_mma<128, true>,
                         cudaFuncAttributeMaxDynamicSharedMemorySize, GEMM_DSMEM);
    cudaFuncSetAttribute(sage_gemm_mma<256, false>,
                         cudaFuncAttributeMaxDynamicSharedMemorySize, GEMM_DSMEM);

    float* agg1p; cudaGetSymbolAddress((void**)&agg1p, g_agg1);
    float* agg2p; cudaGetSymbolAddress((void**)&agg2p, g_agg2);
    float* hp;    cudaGetSymbolAddress((void**)&hp,    g_h);
    float* zp;    cudaGetSymbolAddress((void**)&zp,    g_z);
    float* bt1p;  cudaGetSymbolAddress((void**)&bt1p,  g_Bt1);
    float* bt2p;  cudaGetSymbolAddress((void**)&bt2p,  g_Bt2);

    int nb = (M + SCAN_BLK - 1) / SCAN_BLK;   // 391 <= 512

    detect_kernel<<<1, 256>>>((const int*)ei);
    zero_cnt_kernel<<<(M + 1023) / 1024, 1024>>>(M);
    convert_kernel<<<4096, 256>>>(ei, edg, E, E2);
    prep_weights<<<512, 256>>>(W1l, W1r, W2l, W2r);
    scan1_kernel<<<nb, SCAN_BLK>>>(M);
    scan2_kernel<<<1, 512>>>(nb);
    scan3_kernel<<<nb, SCAN_BLK>>>(M);
    fill_kernel<<<2048, 256>>>(E);

    int gtiles = (M + 127) / 128;

    // layer 1
    gather1_kernel<<<(M * 32 + 255) / 256, 256>>>(x, M);
    sage_gemm_mma<128, true><<<gtiles, 256, GEMM_DSMEM>>>(agg1p, x, bt1p, b1, hp, M);
    // layer 2
    gather2_kernel<<<(M * 32 + 255) / 256, 256>>>(M);
    sage_gemm_mma<256, false><<<gtiles, 256, GEMM_DSMEM>>>(agg2p, hp, bt2p, b2, zp, M);
    // decode
    decode_kernel<<<(E2 * 32 + 255) / 256, 256>>>(out, E2);
}

// round 6
// speedup vs baseline: 2.7020x; 1.0661x over previous
#include <cuda_runtime.h>
#include <cuda_bf16.h>
#include <cstdint>

#define N_NODES_MAX 100000
#define IN_CH 128
#define HIDDEN 256
#define N_EDGES_MAX 1600000

// ---------------- scratch (static device globals; no allocation) ----------------
__device__ float g_agg1[(size_t)N_NODES_MAX * IN_CH];    // 51.2 MB
__device__ float g_h   [(size_t)N_NODES_MAX * HIDDEN];   // 102.4 MB
__device__ float g_agg2[(size_t)N_NODES_MAX * HIDDEN];   // 102.4 MB
__device__ __nv_bfloat16 g_z[(size_t)N_NODES_MAX * HIDDEN]; // 51.2 MB (decode-only)
__device__ float g_invdeg[N_NODES_MAX];
__device__ int   g_src[N_EDGES_MAX];
__device__ int   g_dst[N_EDGES_MAX];
__device__ int   g_ea [N_EDGES_MAX];
__device__ int   g_eb [N_EDGES_MAX];
__device__ int   g_is64;
// CSR
__device__ int   g_cnt[N_NODES_MAX];
__device__ int   g_rowstart[N_NODES_MAX];
__device__ int   g_cursor[N_NODES_MAX];
__device__ int   g_csrc[N_EDGES_MAX];
__device__ int   g_partial[512];
// pre-transposed, tf32-rounded weights: Bt[n][k_cat]  (k_cat = [Wl rows ; Wr rows])
__device__ float g_Bt1[256 * 256];   // layer1: Kcat=256
__device__ float g_Bt2[256 * 512];   // layer2: Kcat=512

// ---------------- small PTX helpers (sm_80-level features only) ----------------
__device__ __forceinline__ uint32_t smem_u32(const void* p) {
    uint32_t a;
    asm("{ .reg .u64 t; cvta.to.shared.u64 t, %1; cvt.u32.u64 %0, t; }" : "=r"(a) : "l"(p));
    return a;
}
__device__ __forceinline__ uint32_t rna_tf32(float f) {
    uint32_t r; asm("cvt.rna.tf32.f32 %0, %1;" : "=r"(r) : "f"(f)); return r;
}
__device__ __forceinline__ void sts128(uint32_t addr, uint4 v) {
    asm volatile("st.shared.v4.b32 [%0], {%1,%2,%3,%4};"
                 :: "r"(addr), "r"(v.x), "r"(v.y), "r"(v.z), "r"(v.w) : "memory");
}
__device__ __forceinline__ void cp_async16(uint32_t dst, const void* src) {
    asm volatile("cp.async.cg.shared.global [%0], [%1], 16;"
                 :: "r"(dst), "l"(src) : "memory");
}
__device__ __forceinline__ void cp_commit() {
    asm volatile("cp.async.commit_group;" ::: "memory");
}
template <int N>
__device__ __forceinline__ void cp_wait() {
    asm volatile("cp.async.wait_group %0;" :: "n"(N) : "memory");
}
__device__ __forceinline__ void ldsm4(uint32_t* r, uint32_t addr) {
    asm volatile("ldmatrix.sync.aligned.m8n8.x4.shared.b16 {%0,%1,%2,%3}, [%4];"
                 : "=r"(r[0]), "=r"(r[1]), "=r"(r[2]), "=r"(r[3]) : "r"(addr));
}
__device__ __forceinline__ void mma_tf32(float* c, const uint32_t* a,
                                         uint32_t b0, uint32_t b1) {
    asm volatile(
        "mma.sync.aligned.m16n8k8.row.col.f32.tf32.tf32.f32 "
        "{%0,%1,%2,%3}, {%4,%5,%6,%7}, {%8,%9}, {%0,%1,%2,%3};"
        : "+f"(c[0]), "+f"(c[1]), "+f"(c[2]), "+f"(c[3])
        : "r"(a[0]), "r"(a[1]), "r"(a[2]), "r"(a[3]), "r"(b0), "r"(b1));
}

// ---------------- dtype detection (int64 vs int32 edge indices) ----------------
__global__ void detect_kernel(const int* __restrict__ ei32) {
    __shared__ int bad;
    if (threadIdx.x == 0) bad = 0;
    __syncthreads();
    for (int i = threadIdx.x; i < 2048; i += blockDim.x)
        if (ei32[2 * i + 1] != 0) bad = 1;
    __syncthreads();
    if (threadIdx.x == 0) g_is64 = bad ? 0 : 1;
}

__global__ void zero_cnt_kernel(int M) {
    int i = blockIdx.x * blockDim.x + threadIdx.x;
    if (i < M) g_cnt[i] = 0;
}

// convert + histogram fused
__global__ void convert_kernel(const void* __restrict__ ei,
                               const void* __restrict__ edges,
                               int E, int E2) {
    int is64 = g_is64;
    int n = E > E2 ? E : E2;
    for (int e = blockIdx.x * blockDim.x + threadIdx.x; e < n;
         e += gridDim.x * blockDim.x) {
        if (e < E) {
            int s, d;
            if (is64) {
                const long long* p = (const long long*)ei;
                s = (int)p[e];
                d = (int)p[(size_t)e + E];
            } else {
                const int* p = (const int*)ei;
                s = p[e];
                d = p[e + E];
            }
            g_src[e] = s;
            g_dst[e] = d;
            atomicAdd(&g_cnt[d], 1);
        }
        if (e < E2) {
            if (is64) {
                const long long* q = (const long long*)edges;
                g_ea[e] = (int)q[2 * (size_t)e];
                g_eb[e] = (int)q[2 * (size_t)e + 1];
            } else {
                const int* q = (const int*)edges;
                g_ea[e] = q[2 * e];
                g_eb[e] = q[2 * e + 1];
            }
        }
    }
}

// ---------------- CSR build: 2-level exclusive scan + cursor scatter ----------------
#define SCAN_BLK 256

__global__ void scan1_kernel(int M) {
    __shared__ int sd[SCAN_BLK];
    int i = blockIdx.x * SCAN_BLK + threadIdx.x;
    sd[threadIdx.x] = (i < M) ? g_cnt[i] : 0;
    __syncthreads();
#pragma unroll
    for (int s = SCAN_BLK / 2; s > 0; s >>= 1) {
        if (threadIdx.x < s) sd[threadIdx.x] += sd[threadIdx.x + s];
        __syncthreads();
    }
    if (threadIdx.x == 0) g_partial[blockIdx.x] = sd[0];
}

__global__ void scan2_kernel(int nb) {
    __shared__ int sd[512];
    int t = threadIdx.x;
    sd[t] = (t < nb) ? g_partial[t] : 0;
    __syncthreads();
#pragma unroll
    for (int off = 1; off < 512; off <<= 1) {
        int v = (t >= off) ? sd[t - off] : 0;
        __syncthreads();
        sd[t] += v;
        __syncthreads();
    }
    if (t < nb) g_partial[t] = (t == 0) ? 0 : sd[t - 1];
}

__global__ void scan3_kernel(int M) {
    __shared__ int sd[SCAN_BLK];
    int i = blockIdx.x * SCAN_BLK + threadIdx.x;
    int cnt = (i < M) ? g_cnt[i] : 0;
    sd[threadIdx.x] = cnt;
    __syncthreads();
#pragma unroll
    for (int off = 1; off < SCAN_BLK; off <<= 1) {
        int v = (threadIdx.x >= off) ? sd[threadIdx.x - off] : 0;
        __syncthreads();
        sd[threadIdx.x] += v;
        __syncthreads();
    }
    if (i < M) {
        int start = g_partial[blockIdx.x] + sd[threadIdx.x] - cnt;
        g_rowstart[i] = start;
        g_cursor[i] = start;
        g_invdeg[i] = 1.0f / fmaxf((float)cnt, 1.0f);
    }
}

__global__ void fill_kernel(int E) {
    for (int e = blockIdx.x * blockDim.x + threadIdx.x; e < E;
         e += gridDim.x * blockDim.x) {
        int d = g_dst[e];
        int pos = atomicAdd(&g_cursor[d], 1);
        g_csrc[pos] = g_src[e];
    }
}
// after fill_kernel: g_cursor[n] == row end

// weights -> transposed, concatenated, tf32-rounded: Bt[n][kcat]
__global__ void prep_weights(const float* __restrict__ W1l, const float* __restrict__ W1r,
                             const float* __restrict__ W2l, const float* __restrict__ W2r) {
    int i = blockIdx.x * blockDim.x + threadIdx.x;
    if (i < 256 * 256) {
        int n = i >> 8, k = i & 255;
        float v = (k < 128) ? W1l[k * HIDDEN + n] : W1r[(k - 128) * HIDDEN + n];
        g_Bt1[n * 256 + k] = __uint_as_float(rna_tf32(v));
    }
    if (i < 256 * 512) {
        int n = i >> 9, k = i & 511;
        float v = (k < 256) ? W2l[k * HIDDEN + n] : W2r[(k - 256) * HIDDEN + n];
        g_Bt2[n * 512 + k] = __uint_as_float(rna_tf32(v));
    }
}

// ---------------- gather aggregation (warp per node) ----------------
__global__ void gather1_kernel(const float* __restrict__ x, int M) {
    int w = (blockIdx.x * blockDim.x + threadIdx.x) >> 5;
    if (w >= M) return;
    int lane = threadIdx.x & 31;
    int e0 = g_rowstart[w], e1 = g_cursor[w];
    float4 acc = make_float4(0.f, 0.f, 0.f, 0.f);
    for (int e = e0; e < e1; e++) {
        int s = g_csrc[e];
        float4 v = *(const float4*)(x + (size_t)s * IN_CH + lane * 4);
        acc.x += v.x; acc.y += v.y; acc.z += v.z; acc.w += v.w;
    }
    *(float4*)(g_agg1 + (size_t)w * IN_CH + lane * 4) = acc;
}

__global__ void gather2_kernel(int M) {
    int w = (blockIdx.x * blockDim.x + threadIdx.x) >> 5;
    if (w >= M) return;
    int lane = threadIdx.x & 31;
    int e0 = g_rowstart[w], e1 = g_cursor[w];
    float4 a0 = make_float4(0.f, 0.f, 0.f, 0.f);
    float4 a1 = a0;
    const float* base = g_h + lane * 4;
    for (int e = e0; e < e1; e++) {
        int s = g_csrc[e];
        const float* row = base + (size_t)s * HIDDEN;
        float4 v0 = *(const float4*)(row);
        float4 v1 = *(const float4*)(row + 128);
        a0.x += v0.x; a0.y += v0.y; a0.z += v0.z; a0.w += v0.w;
        a1.x += v1.x; a1.y += v1.y; a1.z += v1.z; a1.w += v1.w;
    }
    float* outp = g_agg2 + (size_t)w * HIDDEN + lane * 4;
    *(float4*)(outp) = a0;
    *(float4*)(outp + 128) = a1;
}

// ---------------- mma.sync tf32 fused SAGE GEMM ----------------
// Out[m,0:256] = (A0[m,:]*invdeg[m]) @ Wl + A1[m,:] @ Wr + b  (opt ReLU)
// OUTBF16: write __nv_bfloat16 output (decode path) instead of fp32.
#define A_STAGE 18432u
#define B_STAGE 36864u
#define GEMM_DSMEM (2 * (A_STAGE + B_STAGE))

template <int KPART, bool RELU, bool OUTBF16>
__global__ void __launch_bounds__(256, 1)
sage_gemm_mma(const float* __restrict__ A0, const float* __restrict__ A1,
              const float* __restrict__ Bt, const float* __restrict__ bias,
              void* __restrict__ OutV, int M)
{
    constexpr int KCAT = 2 * KPART;
    constexpr int NC = KCAT / 32;
    extern __shared__ char sm[];
    const uint32_t smbase = smem_u32(sm);
    const uint32_t Aoff[2] = {0u, A_STAGE};
    const uint32_t Boff[2] = {2 * A_STAGE, 2 * A_STAGE + B_STAGE};

    int tid = threadIdx.x, lane = tid & 31, wid = tid >> 5;
    int m0 = blockIdx.x * 128;
    int warp_m = (wid >> 2) * 64, warp_n = (wid & 3) * 64;

    int arow = tid >> 1;
    int acol = (tid & 1) * 16;
    int grow = m0 + arow;
    bool avalid = grow < M;
    float sdeg = avalid ? g_invdeg[grow] : 0.f;

    float acc[4][8][4] = {};

    auto ldgA = [&](int ci, float4* r) {
        bool p1 = (ci * 32) >= KPART;
        const float* A = p1 ? A1 : A0;
        int kof = p1 ? ci * 32 - KPART : ci * 32;
        if (avalid) {
            const float4* src = (const float4*)(A + (size_t)grow * KPART + kof + acol);
            r[0] = src[0]; r[1] = src[1]; r[2] = src[2]; r[3] = src[3];
            if (!p1) {
#pragma unroll
                for (int i = 0; i < 4; i++) {
                    r[i].x *= sdeg; r[i].y *= sdeg; r[i].z *= sdeg; r[i].w *= sdeg;
                }
            }
        } else {
#pragma unroll
            for (int i = 0; i < 4; i++) r[i] = make_float4(0.f, 0.f, 0.f, 0.f);
        }
    };
    auto stsA = [&](int buf, const float4* r) {
        uint32_t a = smbase + Aoff[buf] + arow * 144 + acol * 4;
#pragma unroll
        for (int i = 0; i < 4; i++) {
            uint4 u;
            u.x = rna_tf32(r[i].x); u.y = rna_tf32(r[i].y);
            u.z = rna_tf32(r[i].z); u.w = rna_tf32(r[i].w);
            sts128(a + i * 16, u);
        }
    };
    auto cpB = [&](int ci, int buf) {
#pragma unroll
        for (int rr = 0; rr < 8; rr++) {
            int i = tid + 256 * rr;
            int n = i >> 3, kq = i & 7;
            uint32_t dst = smbase + Boff[buf] + n * 144 + kq * 16;
            const float* src = Bt + (size_t)n * KCAT + ci * 32 + kq * 4;
            cp_async16(dst, src);
        }
        cp_commit();
    };
    auto compute = [&](int buf) {
        uint32_t Ab = smbase + Aoff[buf] +
                      (warp_m + (lane & 15)) * 144 + ((lane & 16) ? 16 : 0);
        uint32_t Bb = smbase + Boff[buf] +
                      (warp_n + (lane & 7) + ((lane & 16) >> 1)) * 144 +
                      ((lane & 8) ? 16 : 0);
#pragma unroll
        for (int kk = 0; kk < 4; kk++) {
            uint32_t af[4][4];
#pragma unroll
            for (int ti = 0; ti < 4; ti++) ldsm4(af[ti], Ab + ti * 16 * 144 + kk * 32);
            uint32_t bf[4][4];
#pragma unroll
            for (int tjp = 0; tjp < 4; tjp++) ldsm4(bf[tjp], Bb + tjp * 16 * 144 + kk * 32);
#pragma unroll
            for (int ti = 0; ti < 4; ti++)
#pragma unroll
                for (int tjp = 0; tjp < 4; tjp++) {
                    mma_tf32(acc[ti][2 * tjp],     af[ti], bf[tjp][0], bf[tjp][1]);
                    mma_tf32(acc[ti][2 * tjp + 1], af[ti], bf[tjp][2], bf[tjp][3]);
                }
        }
    };

    float4 areg[4];
    ldgA(0, areg);
    cpB(0, 0);
    stsA(0, areg);

    for (int ci = 0; ci < NC; ci++) {
        int cb = ci & 1;
        float4 areg2[4];
        if (ci + 1 < NC) {
            ldgA(ci + 1, areg2);
            cpB(ci + 1, cb ^ 1);
            cp_wait<1>();
        } else {
            cp_wait<0>();
        }
        __syncthreads();
        compute(cb);
        __syncthreads();
        if (ci + 1 < NC) stsA(cb ^ 1, areg2);
    }

    int r0base = m0 + warp_m + (lane >> 2);
    int colb = warp_n + (lane & 3) * 2;
#pragma unroll
    for (int tj = 0; tj < 8; tj++) {
        int col = colb + tj * 8;
        float2 b2 = *(const float2*)(bias + col);
#pragma unroll
        for (int ti = 0; ti < 4; ti++) {
            int rr[2] = {r0base + ti * 16, r0base + ti * 16 + 8};
#pragma unroll
            for (int hh = 0; hh < 2; hh++) {
                int r = rr[hh];
                if (r >= M) continue;
                float2 v;
                v.x = acc[ti][tj][2 * hh]     + b2.x;
                v.y = acc[ti][tj][2 * hh + 1] + b2.y;
                if (RELU) { v.x = fmaxf(v.x, 0.f); v.y = fmaxf(v.y, 0.f); }
                if (OUTBF16) {
                    __nv_bfloat162 o2 = __float22bfloat162_rn(v);
                    *(__nv_bfloat162*)((__nv_bfloat16*)OutV + (size_t)r * HIDDEN + col) = o2;
                } else {
                    *(float2*)((float*)OutV + (size_t)r * HIDDEN + col) = v;
                }
            }
        }
    }
}

// ---------------- decoder (bf16 z, warp per pair, fp32 accum) ----------------
__global__ void decode_kernel(float* __restrict__ out, int E2) {
    int w = (blockIdx.x * blockDim.x + threadIdx.x) >> 5;
    if (w >= E2) return;
    int lane = threadIdx.x & 31;
    int a = g_ea[w], b = g_eb[w];
    // one uint4 per lane per row: 32 lanes * 16B = 512B = 256 bf16
    const uint4* za = (const uint4*)((const char*)(g_z + (size_t)a * HIDDEN)) + lane;
    const uint4* zb = (const uint4*)((const char*)(g_z + (size_t)b * HIDDEN)) + lane;
    uint4 va = *za;
    uint4 vb = *zb;
    float acc = 0.f;
    const uint32_t* pa = (const uint32_t*)&va;
    const uint32_t* pb = (const uint32_t*)&vb;
#pragma unroll
    for (int j = 0; j < 4; j++) {
        float2 fa = __bfloat1622float2(*(const __nv_bfloat162*)&pa[j]);
        float2 fb = __bfloat1622float2(*(const __nv_bfloat162*)&pb[j]);
        acc = fmaf(fa.x, fb.x, acc);
        acc = fmaf(fa.y, fb.y, acc);
    }
#pragma unroll
    for (int o = 16; o > 0; o >>= 1) acc += __shfl_xor_sync(0xffffffffu, acc, o);
    if (lane == 0) out[w] = acc;
}

// ---------------- launch ----------------
extern "C" void kernel_launch(void* const* d_in, const int* in_sizes, int n_in,
                              void* d_out, int out_size) {
    const float* x   = (const float*)d_in[0];
    const void*  ei  = d_in[1];
    const void*  edg = d_in[2];
    const float* W1l = (const float*)d_in[3];
    const float* b1  = (const float*)d_in[4];
    const float* W1r = (const float*)d_in[5];
    const float* W2l = (const float*)d_in[6];
    const float* b2  = (const float*)d_in[7];
    const float* W2r = (const float*)d_in[8];
    float* out = (float*)d_out;

    int M  = in_sizes[0] / IN_CH;   // 100000
    int E  = in_sizes[1] / 2;       // 1.6M graph edges
    int E2 = out_size;              // 1.6M candidate pairs

    cudaFuncSetAttribute(sage_gemm_mma<128, true, false>,
                         cudaFuncAttributeMaxDynamicSharedMemorySize, GEMM_DSMEM);
    cudaFuncSetAttribute(sage_gemm_mma<256, false, true>,
                         cudaFuncAttributeMaxDynamicSharedMemorySize, GEMM_DSMEM);

    float* agg1p; cudaGetSymbolAddress((void**)&agg1p, g_agg1);
    float* agg2p; cudaGetSymbolAddress((void**)&agg2p, g_agg2);
    float* hp;    cudaGetSymbolAddress((void**)&hp,    g_h);
    void*  zp;    cudaGetSymbolAddress(&zp,            g_z);
    float* bt1p;  cudaGetSymbolAddress((void**)&bt1p,  g_Bt1);
    float* bt2p;  cudaGetSymbolAddress((void**)&bt2p,  g_Bt2);

    int nb = (M + SCAN_BLK - 1) / SCAN_BLK;   // 391 <= 512

    detect_kernel<<<1, 256>>>((const int*)ei);
    zero_cnt_kernel<<<(M + 1023) / 1024, 1024>>>(M);
    convert_kernel<<<4096, 256>>>(ei, edg, E, E2);
    prep_weights<<<512, 256>>>(W1l, W1r, W2l, W2r);
    scan1_kernel<<<nb, SCAN_BLK>>>(M);
    scan2_kernel<<<1, 512>>>(nb);
    scan3_kernel<<<nb, SCAN_BLK>>>(M);
    fill_kernel<<<2048, 256>>>(E);

    int gtiles = (M + 127) / 128;

    // layer 1
    gather1_kernel<<<(M * 32 + 255) / 256, 256>>>(x, M);
    sage_gemm_mma<128, true, false><<<gtiles, 256, GEMM_DSMEM>>>(agg1p, x, bt1p, b1, hp, M);
    // layer 2
    gather2_kernel<<<(M * 32 + 255) / 256, 256>>>(M);
    sage_gemm_mma<256, false, true><<<gtiles, 256, GEMM_DSMEM>>>(agg2p, hp, bt2p, b2, zp, M);
    // decode
    decode_kernel<<<(E2 * 32 + 255) / 256, 256>>>(out, E2);
}

// round 7
// speedup vs baseline: 3.0319x; 1.1221x over previous
#include <cuda_runtime.h>
#include <cuda_bf16.h>
#include <cstdint>

#define N_NODES_MAX 100000
#define IN_CH 128
#define HIDDEN 256
#define N_EDGES_MAX 1600000

// ---------------- scratch (static device globals; no allocation) ----------------
__device__ float g_agg1[(size_t)N_NODES_MAX * IN_CH];       // 51.2 MB
__device__ __nv_bfloat16 g_h[(size_t)N_NODES_MAX * HIDDEN]; // 51.2 MB (bf16)
__device__ float g_agg2[(size_t)N_NODES_MAX * HIDDEN];      // 102.4 MB
__device__ __nv_bfloat16 g_z[(size_t)N_NODES_MAX * HIDDEN]; // 51.2 MB (decode-only)
__device__ float g_invdeg[N_NODES_MAX];
__device__ int   g_src[N_EDGES_MAX];
__device__ int   g_dst[N_EDGES_MAX];
__device__ int   g_ea [N_EDGES_MAX];
__device__ int   g_eb [N_EDGES_MAX];
__device__ int   g_is64;
// CSR
__device__ int   g_cnt[N_NODES_MAX];
__device__ int   g_rowstart[N_NODES_MAX];
__device__ int   g_cursor[N_NODES_MAX];
__device__ int   g_csrc[N_EDGES_MAX];
__device__ int   g_partial[512];
// pre-transposed, tf32-rounded weights: Bt[n][k_cat]  (k_cat = [Wl rows ; Wr rows])
__device__ float g_Bt1[256 * 256];   // layer1: Kcat=256
__device__ float g_Bt2[256 * 512];   // layer2: Kcat=512

// ---------------- small PTX helpers (sm_80-level features only) ----------------
__device__ __forceinline__ uint32_t smem_u32(const void* p) {
    uint32_t a;
    asm("{ .reg .u64 t; cvta.to.shared.u64 t, %1; cvt.u32.u64 %0, t; }" : "=r"(a) : "l"(p));
    return a;
}
__device__ __forceinline__ uint32_t rna_tf32(float f) {
    uint32_t r; asm("cvt.rna.tf32.f32 %0, %1;" : "=r"(r) : "f"(f)); return r;
}
__device__ __forceinline__ void sts128(uint32_t addr, uint4 v) {
    asm volatile("st.shared.v4.b32 [%0], {%1,%2,%3,%4};"
                 :: "r"(addr), "r"(v.x), "r"(v.y), "r"(v.z), "r"(v.w) : "memory");
}
__device__ __forceinline__ void cp_async16(uint32_t dst, const void* src) {
    asm volatile("cp.async.cg.shared.global [%0], [%1], 16;"
                 :: "r"(dst), "l"(src) : "memory");
}
__device__ __forceinline__ void cp_commit() {
    asm volatile("cp.async.commit_group;" ::: "memory");
}
template <int N>
__device__ __forceinline__ void cp_wait() {
    asm volatile("cp.async.wait_group %0;" :: "n"(N) : "memory");
}
__device__ __forceinline__ void ldsm4(uint32_t* r, uint32_t addr) {
    asm volatile("ldmatrix.sync.aligned.m8n8.x4.shared.b16 {%0,%1,%2,%3}, [%4];"
                 : "=r"(r[0]), "=r"(r[1]), "=r"(r[2]), "=r"(r[3]) : "r"(addr));
}
__device__ __forceinline__ void mma_tf32(float* c, const uint32_t* a,
                                         uint32_t b0, uint32_t b1) {
    asm volatile(
        "mma.sync.aligned.m16n8k8.row.col.f32.tf32.tf32.f32 "
        "{%0,%1,%2,%3}, {%4,%5,%6,%7}, {%8,%9}, {%0,%1,%2,%3};"
        : "+f"(c[0]), "+f"(c[1]), "+f"(c[2]), "+f"(c[3])
        : "r"(a[0]), "r"(a[1]), "r"(a[2]), "r"(a[3]), "r"(b0), "r"(b1));
}

// ---------------- dtype detection (int64 vs int32 edge indices) ----------------
__global__ void detect_kernel(const int* __restrict__ ei32) {
    __shared__ int bad;
    if (threadIdx.x == 0) bad = 0;
    __syncthreads();
    for (int i = threadIdx.x; i < 2048; i += blockDim.x)
        if (ei32[2 * i + 1] != 0) bad = 1;
    __syncthreads();
    if (threadIdx.x == 0) g_is64 = bad ? 0 : 1;
}

__global__ void zero_cnt_kernel(int M) {
    int i = blockIdx.x * blockDim.x + threadIdx.x;
    if (i < M) g_cnt[i] = 0;
}

// convert + histogram fused
__global__ void convert_kernel(const void* __restrict__ ei,
                               const void* __restrict__ edges,
                               int E, int E2) {
    int is64 = g_is64;
    int n = E > E2 ? E : E2;
    for (int e = blockIdx.x * blockDim.x + threadIdx.x; e < n;
         e += gridDim.x * blockDim.x) {
        if (e < E) {
            int s, d;
            if (is64) {
                const long long* p = (const long long*)ei;
                s = (int)p[e];
                d = (int)p[(size_t)e + E];
            } else {
                const int* p = (const int*)ei;
                s = p[e];
                d = p[e + E];
            }
            g_src[e] = s;
            g_dst[e] = d;
            atomicAdd(&g_cnt[d], 1);
        }
        if (e < E2) {
            if (is64) {
                const long long* q = (const long long*)edges;
                g_ea[e] = (int)q[2 * (size_t)e];
                g_eb[e] = (int)q[2 * (size_t)e + 1];
            } else {
                const int* q = (const int*)edges;
                g_ea[e] = q[2 * e];
                g_eb[e] = q[2 * e + 1];
            }
        }
    }
}

// ---------------- CSR build: 2-level exclusive scan + cursor scatter ----------------
#define SCAN_BLK 256

__global__ void scan1_kernel(int M) {
    __shared__ int sd[SCAN_BLK];
    int i = blockIdx.x * SCAN_BLK + threadIdx.x;
    sd[threadIdx.x] = (i < M) ? g_cnt[i] : 0;
    __syncthreads();
#pragma unroll
    for (int s = SCAN_BLK / 2; s > 0; s >>= 1) {
        if (threadIdx.x < s) sd[threadIdx.x] += sd[threadIdx.x + s];
        __syncthreads();
    }
    if (threadIdx.x == 0) g_partial[blockIdx.x] = sd[0];
}

__global__ void scan2_kernel(int nb) {
    __shared__ int sd[512];
    int t = threadIdx.x;
    sd[t] = (t < nb) ? g_partial[t] : 0;
    __syncthreads();
#pragma unroll
    for (int off = 1; off < 512; off <<= 1) {
        int v = (t >= off) ? sd[t - off] : 0;
        __syncthreads();
        sd[t] += v;
        __syncthreads();
    }
    if (t < nb) g_partial[t] = (t == 0) ? 0 : sd[t - 1];
}

__global__ void scan3_kernel(int M) {
    __shared__ int sd[SCAN_BLK];
    int i = blockIdx.x * SCAN_BLK + threadIdx.x;
    int cnt = (i < M) ? g_cnt[i] : 0;
    sd[threadIdx.x] = cnt;
    __syncthreads();
#pragma unroll
    for (int off = 1; off < SCAN_BLK; off <<= 1) {
        int v = (threadIdx.x >= off) ? sd[threadIdx.x - off] : 0;
        __syncthreads();
        sd[threadIdx.x] += v;
        __syncthreads();
    }
    if (i < M) {
        int start = g_partial[blockIdx.x] + sd[threadIdx.x] - cnt;
        g_rowstart[i] = start;
        g_cursor[i] = start;
        g_invdeg[i] = 1.0f / fmaxf((float)cnt, 1.0f);
    }
}

__global__ void fill_kernel(int E) {
    for (int e = blockIdx.x * blockDim.x + threadIdx.x; e < E;
         e += gridDim.x * blockDim.x) {
        int d = g_dst[e];
        int pos = atomicAdd(&g_cursor[d], 1);
        g_csrc[pos] = g_src[e];
    }
}
// after fill_kernel: g_cursor[n] == row end

// weights -> transposed, concatenated, tf32-rounded: Bt[n][kcat]
__global__ void prep_weights(const float* __restrict__ W1l, const float* __restrict__ W1r,
                             const float* __restrict__ W2l, const float* __restrict__ W2r) {
    int i = blockIdx.x * blockDim.x + threadIdx.x;
    if (i < 256 * 256) {
        int n = i >> 8, k = i & 255;
        float v = (k < 128) ? W1l[k * HIDDEN + n] : W1r[(k - 128) * HIDDEN + n];
        g_Bt1[n * 256 + k] = __uint_as_float(rna_tf32(v));
    }
    if (i < 256 * 512) {
        int n = i >> 9, k = i & 511;
        float v = (k < 256) ? W2l[k * HIDDEN + n] : W2r[(k - 256) * HIDDEN + n];
        g_Bt2[n * 512 + k] = __uint_as_float(rna_tf32(v));
    }
}

// ---------------- gather aggregation (warp per node) ----------------
__global__ void gather1_kernel(const float* __restrict__ x, int M) {
    int w = (blockIdx.x * blockDim.x + threadIdx.x) >> 5;
    if (w >= M) return;
    int lane = threadIdx.x & 31;
    int e0 = g_rowstart[w], e1 = g_cursor[w];
    float4 acc = make_float4(0.f, 0.f, 0.f, 0.f);
    for (int e = e0; e < e1; e++) {
        int s = g_csrc[e];
        float4 v = *(const float4*)(x + (size_t)s * IN_CH + lane * 4);
        acc.x += v.x; acc.y += v.y; acc.z += v.z; acc.w += v.w;
    }
    *(float4*)(g_agg1 + (size_t)w * IN_CH + lane * 4) = acc;
}

// bf16 h: one uint4 (8 bf16) per lane per neighbor row; fp32 accumulate
__global__ void gather2_kernel(int M) {
    int w = (blockIdx.x * blockDim.x + threadIdx.x) >> 5;
    if (w >= M) return;
    int lane = threadIdx.x & 31;
    int e0 = g_rowstart[w], e1 = g_cursor[w];
    float acc[8] = {};
    const __nv_bfloat16* base = g_h + lane * 8;
    for (int e = e0; e < e1; e++) {
        int s = g_csrc[e];
        uint4 u = *(const uint4*)(base + (size_t)s * HIDDEN);
        const uint32_t* p = (const uint32_t*)&u;
#pragma unroll
        for (int j = 0; j < 4; j++) {
            float2 f = __bfloat1622float2(*(const __nv_bfloat162*)&p[j]);
            acc[2 * j]     += f.x;
            acc[2 * j + 1] += f.y;
        }
    }
    float* outp = g_agg2 + (size_t)w * HIDDEN + lane * 8;
    *(float4*)(outp)     = make_float4(acc[0], acc[1], acc[2], acc[3]);
    *(float4*)(outp + 4) = make_float4(acc[4], acc[5], acc[6], acc[7]);
}

// ---------------- mma.sync tf32 fused SAGE GEMM ----------------
// Out[m,0:256] = (A0[m,:]*invdeg[m]) @ Wl + A1[m,:] @ Wr + b  (opt ReLU)
// A1BF16: A1 operand stored as bf16 (exact convert to fp32 before tf32 round).
// OUTBF16: write __nv_bfloat16 output instead of fp32.
#define A_STAGE 18432u
#define B_STAGE 36864u
#define GEMM_DSMEM (2 * (A_STAGE + B_STAGE))

template <int KPART, bool RELU, bool A1BF16, bool OUTBF16>
__global__ void __launch_bounds__(256, 1)
sage_gemm_mma(const float* __restrict__ A0, const void* __restrict__ A1v,
              const float* __restrict__ Bt, const float* __restrict__ bias,
              void* __restrict__ OutV, int M)
{
    constexpr int KCAT = 2 * KPART;
    constexpr int NC = KCAT / 32;
    extern __shared__ char sm[];
    const uint32_t smbase = smem_u32(sm);
    const uint32_t Aoff[2] = {0u, A_STAGE};
    const uint32_t Boff[2] = {2 * A_STAGE, 2 * A_STAGE + B_STAGE};

    int tid = threadIdx.x, lane = tid & 31, wid = tid >> 5;
    int m0 = blockIdx.x * 128;
    int warp_m = (wid >> 2) * 64, warp_n = (wid & 3) * 64;

    int arow = tid >> 1;
    int acol = (tid & 1) * 16;
    int grow = m0 + arow;
    bool avalid = grow < M;
    float sdeg = avalid ? g_invdeg[grow] : 0.f;

    float acc[4][8][4] = {};

    auto ldgA = [&](int ci, float4* r) {
        bool p1 = (ci * 32) >= KPART;
        if (!avalid) {
#pragma unroll
            for (int i = 0; i < 4; i++) r[i] = make_float4(0.f, 0.f, 0.f, 0.f);
            return;
        }
        if (!p1) {
            const float4* src = (const float4*)(A0 + (size_t)grow * KPART + ci * 32 + acol);
#pragma unroll
            for (int i = 0; i < 4; i++) {
                r[i] = src[i];
                r[i].x *= sdeg; r[i].y *= sdeg; r[i].z *= sdeg; r[i].w *= sdeg;
            }
        } else {
            int kof = ci * 32 - KPART;
            if (A1BF16) {
                const __nv_bfloat16* rowp =
                    (const __nv_bfloat16*)A1v + (size_t)grow * KPART + kof + acol;
                uint4 u0 = *(const uint4*)rowp;
                uint4 u1 = *(const uint4*)(rowp + 8);
                const uint32_t* p0 = (const uint32_t*)&u0;
                const uint32_t* p1p = (const uint32_t*)&u1;
#pragma unroll
                for (int j = 0; j < 4; j++) {
                    float2 f = __bfloat1622float2(*(const __nv_bfloat162*)&p0[j]);
                    ((float*)&r[j >> 1])[(j & 1) * 2]     = f.x;
                    ((float*)&r[j >> 1])[(j & 1) * 2 + 1] = f.y;
                }
#pragma unroll
                for (int j = 0; j < 4; j++) {
                    float2 f = __bfloat1622float2(*(const __nv_bfloat162*)&p1p[j]);
                    ((float*)&r[2 + (j >> 1)])[(j & 1) * 2]     = f.x;
                    ((float*)&r[2 + (j >> 1)])[(j & 1) * 2 + 1] = f.y;
                }
            } else {
                const float4* src =
                    (const float4*)((const float*)A1v + (size_t)grow * KPART + kof + acol);
#pragma unroll
                for (int i = 0; i < 4; i++) r[i] = src[i];
            }
        }
    };
    auto stsA = [&](int buf, const float4* r) {
        uint32_t a = smbase + Aoff[buf] + arow * 144 + acol * 4;
#pragma unroll
        for (int i = 0; i < 4; i++) {
            uint4 u;
            u.x = rna_tf32(r[i].x); u.y = rna_tf32(r[i].y);
            u.z = rna_tf32(r[i].z); u.w = rna_tf32(r[i].w);
            sts128(a + i * 16, u);
        }
    };
    auto cpB = [&](int ci, int buf) {
#pragma unroll
        for (int rr = 0; rr < 8; rr++) {
            int i = tid + 256 * rr;
            int n = i >> 3, kq = i & 7;
            uint32_t dst = smbase + Boff[buf] + n * 144 + kq * 16;
            const float* src = Bt + (size_t)n * KCAT + ci * 32 + kq * 4;
            cp_async16(dst, src);
        }
        cp_commit();
    };
    auto compute = [&](int buf) {
        uint32_t Ab = smbase + Aoff[buf] +
                      (warp_m + (lane & 15)) * 144 + ((lane & 16) ? 16 : 0);
        uint32_t Bb = smbase + Boff[buf] +
                      (warp_n + (lane & 7) + ((lane & 16) >> 1)) * 144 +
                      ((lane & 8) ? 16 : 0);
#pragma unroll
        for (int kk = 0; kk < 4; kk++) {
            uint32_t af[4][4];
#pragma unroll
            for (int ti = 0; ti < 4; ti++) ldsm4(af[ti], Ab + ti * 16 * 144 + kk * 32);
            uint32_t bf[4][4];
#pragma unroll
            for (int tjp = 0; tjp < 4; tjp++) ldsm4(bf[tjp], Bb + tjp * 16 * 144 + kk * 32);
#pragma unroll
            for (int ti = 0; ti < 4; ti++)
#pragma unroll
                for (int tjp = 0; tjp < 4; tjp++) {
                    mma_tf32(acc[ti][2 * tjp],     af[ti], bf[tjp][0], bf[tjp][1]);
                    mma_tf32(acc[ti][2 * tjp + 1], af[ti], bf[tjp][2], bf[tjp][3]);
                }
        }
    };

    float4 areg[4];
    ldgA(0, areg);
    cpB(0, 0);
    stsA(0, areg);

    for (int ci = 0; ci < NC; ci++) {
        int cb = ci & 1;
        float4 areg2[4];
        if (ci + 1 < NC) {
            ldgA(ci + 1, areg2);
            cpB(ci + 1, cb ^ 1);
            cp_wait<1>();
        } else {
            cp_wait<0>();
        }
        __syncthreads();
        compute(cb);
        __syncthreads();
        if (ci + 1 < NC) stsA(cb ^ 1, areg2);
    }

    int r0base = m0 + warp_m + (lane >> 2);
    int colb = warp_n + (lane & 3) * 2;
#pragma unroll
    for (int tj = 0; tj < 8; tj++) {
        int col = colb + tj * 8;
        float2 b2 = *(const float2*)(bias + col);
#pragma unroll
        for (int ti = 0; ti < 4; ti++) {
            int rr[2] = {r0base + ti * 16, r0base + ti * 16 + 8};
#pragma unroll
            for (int hh = 0; hh < 2; hh++) {
                int r = rr[hh];
                if (r >= M) continue;
                float2 v;
                v.x = acc[ti][tj][2 * hh]     + b2.x;
                v.y = acc[ti][tj][2 * hh + 1] + b2.y;
                if (RELU) { v.x = fmaxf(v.x, 0.f); v.y = fmaxf(v.y, 0.f); }
                if (OUTBF16) {
                    __nv_bfloat162 o2 = __float22bfloat162_rn(v);
                    *(__nv_bfloat162*)((__nv_bfloat16*)OutV + (size_t)r * HIDDEN + col) = o2;
                } else {
                    *(float2*)((float*)OutV + (size_t)r * HIDDEN + col) = v;
                }
            }
        }
    }
}

// ---------------- decoder (bf16 z, warp per pair, fp32 accum) ----------------
__global__ void decode_kernel(float* __restrict__ out, int E2) {
    int w = (blockIdx.x * blockDim.x + threadIdx.x) >> 5;
    if (w >= E2) return;
    int lane = threadIdx.x & 31;
    int a = g_ea[w], b = g_eb[w];
    const uint4* za = (const uint4*)((const char*)(g_z + (size_t)a * HIDDEN)) + lane;
    const uint4* zb = (const uint4*)((const char*)(g_z + (size_t)b * HIDDEN)) + lane;
    uint4 va = *za;
    uint4 vb = *zb;
    float acc = 0.f;
    const uint32_t* pa = (const uint32_t*)&va;
    const uint32_t* pb = (const uint32_t*)&vb;
#pragma unroll
    for (int j = 0; j < 4; j++) {
        float2 fa = __bfloat1622float2(*(const __nv_bfloat162*)&pa[j]);
        float2 fb = __bfloat1622float2(*(const __nv_bfloat162*)&pb[j]);
        acc = fmaf(fa.x, fb.x, acc);
        acc = fmaf(fa.y, fb.y, acc);
    }
#pragma unroll
    for (int o = 16; o > 0; o >>= 1) acc += __shfl_xor_sync(0xffffffffu, acc, o);
    if (lane == 0) out[w] = acc;
}

// ---------------- launch ----------------
extern "C" void kernel_launch(void* const* d_in, const int* in_sizes, int n_in,
                              void* d_out, int out_size) {
    const float* x   = (const float*)d_in[0];
    const void*  ei  = d_in[1];
    const void*  edg = d_in[2];
    const float* W1l = (const float*)d_in[3];
    const float* b1  = (const float*)d_in[4];
    const float* W1r = (const float*)d_in[5];
    const float* W2l = (const float*)d_in[6];
    const float* b2  = (const float*)d_in[7];
    const float* W2r = (const float*)d_in[8];
    float* out = (float*)d_out;

    int M  = in_sizes[0] / IN_CH;   // 100000
    int E  = in_sizes[1] / 2;       // 1.6M graph edges
    int E2 = out_size;              // 1.6M candidate pairs

    cudaFuncSetAttribute(sage_gemm_mma<128, true, false, true>,
                         cudaFuncAttributeMaxDynamicSharedMemorySize, GEMM_DSMEM);
    cudaFuncSetAttribute(sage_gemm_mma<256, false, true, true>,
                         cudaFuncAttributeMaxDynamicSharedMemorySize, GEMM_DSMEM);

    float* agg1p; cudaGetSymbolAddress((void**)&agg1p, g_agg1);
    float* agg2p; cudaGetSymbolAddress((void**)&agg2p, g_agg2);
    void*  hp;    cudaGetSymbolAddress(&hp,            g_h);
    void*  zp;    cudaGetSymbolAddress(&zp,            g_z);
    float* bt1p;  cudaGetSymbolAddress((void**)&bt1p,  g_Bt1);
    float* bt2p;  cudaGetSymbolAddress((void**)&bt2p,  g_Bt2);

    int nb = (M + SCAN_BLK - 1) / SCAN_BLK;   // 391 <= 512

    detect_kernel<<<1, 256>>>((const int*)ei);
    zero_cnt_kernel<<<(M + 1023) / 1024, 1024>>>(M);
    convert_kernel<<<4096, 256>>>(ei, edg, E, E2);
    prep_weights<<<512, 256>>>(W1l, W1r, W2l, W2r);
    scan1_kernel<<<nb, SCAN_BLK>>>(M);
    scan2_kernel<<<1, 512>>>(nb);
    scan3_kernel<<<nb, SCAN_BLK>>>(M);
    fill_kernel<<<2048, 256>>>(E);

    int gtiles = (M + 127) / 128;

    // layer 1  (h written as bf16)
    gather1_kernel<<<(M * 32 + 255) / 256, 256>>>(x, M);
    sage_gemm_mma<128, true, false, true><<<gtiles, 256, GEMM_DSMEM>>>(
        agg1p, x, bt1p, b1, hp, M);
    // layer 2  (A1 = h bf16, z written as bf16)
    gather2_kernel<<<(M * 32 + 255) / 256, 256>>>(M);
    sage_gemm_mma<256, false, true, true><<<gtiles, 256, GEMM_DSMEM>>>(
        agg2p, hp, bt2p, b2, zp, M);
    // decode
    decode_kernel<<<(E2 * 32 + 255) / 256, 256>>>(out, E2);
}

// round 9
// speedup vs baseline: 3.0864x; 1.0180x over previous
#include <cuda_runtime.h>
#include <cuda_bf16.h>
#include <cstdint>

#define N_NODES_MAX 100000
#define IN_CH 128
#define HIDDEN 256
#define N_EDGES_MAX 1600000

// ---------------- scratch (static device globals; no allocation) ----------------
__device__ float g_agg1[(size_t)N_NODES_MAX * IN_CH];          // 51.2 MB (fp32)
__device__ __nv_bfloat16 g_xb[(size_t)N_NODES_MAX * IN_CH];    // 25.6 MB (bf16 x)
__device__ __nv_bfloat16 g_h[(size_t)N_NODES_MAX * HIDDEN];    // 51.2 MB (bf16)
__device__ __nv_bfloat16 g_agg2[(size_t)N_NODES_MAX * HIDDEN]; // 51.2 MB (bf16)
__device__ __nv_bfloat16 g_z[(size_t)N_NODES_MAX * HIDDEN];    // 51.2 MB (decode-only)
__device__ float g_invdeg[N_NODES_MAX];
__device__ int   g_src[N_EDGES_MAX];
__device__ int   g_dst[N_EDGES_MAX];
__device__ int   g_ea [N_EDGES_MAX];
__device__ int   g_eb [N_EDGES_MAX];
__device__ int   g_is64;
// CSR
__device__ int   g_cnt[N_NODES_MAX];
__device__ int   g_rowstart[N_NODES_MAX];
__device__ int   g_cursor[N_NODES_MAX];
__device__ int   g_csrc[N_EDGES_MAX];
__device__ int   g_partial[512];
// pre-transposed, tf32-rounded weights: Bt[n][k_cat]  (k_cat = [Wl rows ; Wr rows])
__device__ float g_Bt1[256 * 256];   // layer1: Kcat=256
__device__ float g_Bt2[256 * 512];   // layer2: Kcat=512

// ---------------- small PTX helpers (sm_80-level features only) ----------------
__device__ __forceinline__ uint32_t smem_u32(const void* p) {
    uint32_t a;
    asm("{ .reg .u64 t; cvta.to.shared.u64 t, %1; cvt.u32.u64 %0, t; }" : "=r"(a) : "l"(p));
    return a;
}
__device__ __forceinline__ uint32_t rna_tf32(float f) {
    uint32_t r; asm("cvt.rna.tf32.f32 %0, %1;" : "=r"(r) : "f"(f)); return r;
}
__device__ __forceinline__ void sts128(uint32_t addr, uint4 v) {
    asm volatile("st.shared.v4.b32 [%0], {%1,%2,%3,%4};"
                 :: "r"(addr), "r"(v.x), "r"(v.y), "r"(v.z), "r"(v.w) : "memory");
}
__device__ __forceinline__ void cp_async16(uint32_t dst, const void* src) {
    asm volatile("cp.async.cg.shared.global [%0], [%1], 16;"
                 :: "r"(dst), "l"(src) : "memory");
}
__device__ __forceinline__ void cp_commit() {
    asm volatile("cp.async.commit_group;" ::: "memory");
}
template <int N>
__device__ __forceinline__ void cp_wait() {
    asm volatile("cp.async.wait_group %0;" :: "n"(N) : "memory");
}
__device__ __forceinline__ void ldsm4(uint32_t* r, uint32_t addr) {
    asm volatile("ldmatrix.sync.aligned.m8n8.x4.shared.b16 {%0,%1,%2,%3}, [%4];"
                 : "=r"(r[0]), "=r"(r[1]), "=r"(r[2]), "=r"(r[3]) : "r"(addr));
}
__device__ __forceinline__ void mma_tf32(float* c, const uint32_t* a,
                                         uint32_t b0, uint32_t b1) {
    asm volatile(
        "mma.sync.aligned.m16n8k8.row.col.f32.tf32.tf32.f32 "
        "{%0,%1,%2,%3}, {%4,%5,%6,%7}, {%8,%9}, {%0,%1,%2,%3};"
        : "+f"(c[0]), "+f"(c[1]), "+f"(c[2]), "+f"(c[3])
        : "r"(a[0]), "r"(a[1]), "r"(a[2]), "r"(a[3]), "r"(b0), "r"(b1));
}
// load 16 consecutive bf16 -> 4x float4
__device__ __forceinline__ void ld16bf(const __nv_bfloat16* p, float4* r) {
    uint4 u0 = *(const uint4*)p;
    uint4 u1 = *(const uint4*)(p + 8);
    const uint32_t* a = (const uint32_t*)&u0;
    const uint32_t* b = (const uint32_t*)&u1;
#pragma unroll
    for (int j = 0; j < 4; j++) {
        float2 f = __bfloat1622float2(*(const __nv_bfloat162*)&a[j]);
        ((float*)&r[j >> 1])[(j & 1) * 2]     = f.x;
        ((float*)&r[j >> 1])[(j & 1) * 2 + 1] = f.y;
    }
#pragma unroll
    for (int j = 0; j < 4; j++) {
        float2 f = __bfloat1622float2(*(const __nv_bfloat162*)&b[j]);
        ((float*)&r[2 + (j >> 1)])[(j & 1) * 2]     = f.x;
        ((float*)&r[2 + (j >> 1)])[(j & 1) * 2 + 1] = f.y;
    }
}

// ---------------- dtype detection (int64 vs int32 edge indices) ----------------
__global__ void detect_kernel(const int* __restrict__ ei32) {
    __shared__ int bad;
    if (threadIdx.x == 0) bad = 0;
    __syncthreads();
    for (int i = threadIdx.x; i < 2048; i += blockDim.x)
        if (ei32[2 * i + 1] != 0) bad = 1;
    __syncthreads();
    if (threadIdx.x == 0) g_is64 = bad ? 0 : 1;
}

// convert + histogram fused
__global__ void convert_kernel(const void* __restrict__ ei,
                               const void* __restrict__ edges,
                               int E, int E2) {
    int is64 = g_is64;
    int n = E > E2 ? E : E2;
    for (int e = blockIdx.x * blockDim.x + threadIdx.x; e < n;
         e += gridDim.x * blockDim.x) {
        if (e < E) {
            int s, d;
            if (is64) {
                const long long* p = (const long long*)ei;
                s = (int)p[e];
                d = (int)p[(size_t)e + E];
            } else {
                const int* p = (const int*)ei;
                s = p[e];
                d = p[e + E];
            }
            g_src[e] = s;
            g_dst[e] = d;
            atomicAdd(&g_cnt[d], 1);
        }
        if (e < E2) {
            if (is64) {
                const long long* q = (const long long*)edges;
                g_ea[e] = (int)q[2 * (size_t)e];
                g_eb[e] = (int)q[2 * (size_t)e + 1];
            } else {
                const int* q = (const int*)edges;
                g_ea[e] = q[2 * e];
                g_eb[e] = q[2 * e + 1];
            }
        }
    }
}

// x fp32 -> bf16 staging
__global__ void prep_x_kernel(const float* __restrict__ x, int n8) {
    int i = blockIdx.x * blockDim.x + threadIdx.x;
    if (i >= n8) return;
    const float4* src = (const float4*)x + 2 * (size_t)i;
    float4 v0 = src[0], v1 = src[1];
    __nv_bfloat162* dst = (__nv_bfloat162*)(g_xb + (size_t)i * 8);
    dst[0] = __float22bfloat162_rn(make_float2(v0.x, v0.y));
    dst[1] = __float22bfloat162_rn(make_float2(v0.z, v0.w));
    dst[2] = __float22bfloat162_rn(make_float2(v1.x, v1.y));
    dst[3] = __float22bfloat162_rn(make_float2(v1.z, v1.w));
}

// ---------------- CSR build: 2-level exclusive scan + cursor scatter ----------------
#define SCAN_BLK 256

__global__ void scan1_kernel(int M) {
    __shared__ int sd[SCAN_BLK];
    int i = blockIdx.x * SCAN_BLK + threadIdx.x;
    sd[threadIdx.x] = (i < M) ? g_cnt[i] : 0;
    __syncthreads();
#pragma unroll
    for (int s = SCAN_BLK / 2; s > 0; s >>= 1) {
        if (threadIdx.x < s) sd[threadIdx.x] += sd[threadIdx.x + s];
        __syncthreads();
    }
    if (threadIdx.x == 0) g_partial[blockIdx.x] = sd[0];
}

__global__ void scan2_kernel(int nb) {
    __shared__ int sd[512];
    int t = threadIdx.x;
    sd[t] = (t < nb) ? g_partial[t] : 0;
    __syncthreads();
#pragma unroll
    for (int off = 1; off < 512; off <<= 1) {
        int v = (t >= off) ? sd[t - off] : 0;
        __syncthreads();
        sd[t] += v;
        __syncthreads();
    }
    if (t < nb) g_partial[t] = (t == 0) ? 0 : sd[t - 1];
}

__global__ void scan3_kernel(int M) {
    __shared__ int sd[SCAN_BLK];
    int i = blockIdx.x * SCAN_BLK + threadIdx.x;
    int cnt = (i < M) ? g_cnt[i] : 0;
    sd[threadIdx.x] = cnt;
    __syncthreads();
#pragma unroll
    for (int off = 1; off < SCAN_BLK; off <<= 1) {
        int v = (threadIdx.x >= off) ? sd[threadIdx.x - off] : 0;
        __syncthreads();
        sd[threadIdx.x] += v;
        __syncthreads();
    }
    if (i < M) {
        int start = g_partial[blockIdx.x] + sd[threadIdx.x] - cnt;
        g_rowstart[i] = start;
        g_cursor[i] = start;
        g_invdeg[i] = 1.0f / fmaxf((float)cnt, 1.0f);
    }
}

__global__ void fill_kernel(int E) {
    for (int e = blockIdx.x * blockDim.x + threadIdx.x; e < E;
         e += gridDim.x * blockDim.x) {
        int d = g_dst[e];
        int pos = atomicAdd(&g_cursor[d], 1);
        g_csrc[pos] = g_src[e];
    }
}
// after fill_kernel: g_cursor[n] == row end

// weights -> transposed, concatenated, tf32-rounded: Bt[n][kcat]
__global__ void prep_weights(const float* __restrict__ W1l, const float* __restrict__ W1r,
                             const float* __restrict__ W2l, const float* __restrict__ W2r) {
    int i = blockIdx.x * blockDim.x + threadIdx.x;
    if (i < 256 * 256) {
        int n = i >> 8, k = i & 255;
        float v = (k < 128) ? W1l[k * HIDDEN + n] : W1r[(k - 128) * HIDDEN + n];
        g_Bt1[n * 256 + k] = __uint_as_float(rna_tf32(v));
    }
    if (i < 256 * 512) {
        int n = i >> 9, k = i & 511;
        float v = (k < 256) ? W2l[k * HIDDEN + n] : W2r[(k - 256) * HIDDEN + n];
        g_Bt2[n * 512 + k] = __uint_as_float(rna_tf32(v));
    }
}

// ---------------- gather aggregation (warp per node) ----------------
// bf16 x: lane loads uint2 (4 bf16) per neighbor row; fp32 accumulate; fp32 out
__global__ void gather1_kernel(int M) {
    int w = (blockIdx.x * blockDim.x + threadIdx.x) >> 5;
    if (w >= M) return;
    int lane = threadIdx.x & 31;
    int e0 = g_rowstart[w], e1 = g_cursor[w];
    float acc[4] = {};
    const __nv_bfloat16* base = g_xb + lane * 4;
    for (int e = e0; e < e1; e++) {
        int s = g_csrc[e];
        uint2 u = *(const uint2*)(base + (size_t)s * IN_CH);
        float2 f0 = __bfloat1622float2(*(const __nv_bfloat162*)&u.x);
        float2 f1 = __bfloat1622float2(*(const __nv_bfloat162*)&u.y);
        acc[0] += f0.x; acc[1] += f0.y; acc[2] += f1.x; acc[3] += f1.y;
    }
    *(float4*)(g_agg1 + (size_t)w * IN_CH + lane * 4) =
        make_float4(acc[0], acc[1], acc[2], acc[3]);
}

// bf16 h: one uint4 (8 bf16) per lane per neighbor row; fp32 accumulate; bf16 out
__global__ void gather2_kernel(int M) {
    int w = (blockIdx.x * blockDim.x + threadIdx.x) >> 5;
    if (w >= M) return;
    int lane = threadIdx.x & 31;
    int e0 = g_rowstart[w], e1 = g_cursor[w];
    float acc[8] = {};
    const __nv_bfloat16* base = g_h + lane * 8;
    for (int e = e0; e < e1; e++) {
        int s = g_csrc[e];
        uint4 u = *(const uint4*)(base + (size_t)s * HIDDEN);
        const uint32_t* p = (const uint32_t*)&u;
#pragma unroll
        for (int j = 0; j < 4; j++) {
            float2 f = __bfloat1622float2(*(const __nv_bfloat162*)&p[j]);
            acc[2 * j]     += f.x;
            acc[2 * j + 1] += f.y;
        }
    }
    uint4 o;
    uint32_t* po = (uint32_t*)&o;
#pragma unroll
    for (int j = 0; j < 4; j++) {
        __nv_bfloat162 b2 = __float22bfloat162_rn(make_float2(acc[2 * j], acc[2 * j + 1]));
        po[j] = *(const uint32_t*)&b2;
    }
    *(uint4*)(g_agg2 + (size_t)w * HIDDEN + lane * 8) = o;
}

// ---------------- mma.sync tf32 fused SAGE GEMM ----------------
// Out[m,0:256] = (A0[m,:]*invdeg[m]) @ Wl + A1[m,:] @ Wr + b  (opt ReLU)
// A0BF16/A1BF16: operand stored as bf16. OUTBF16: bf16 output.
#define A_STAGE 18432u
#define B_STAGE 36864u
#define GEMM_DSMEM (2 * (A_STAGE + B_STAGE))

template <int KPART, bool RELU, bool A0BF16, bool A1BF16, bool OUTBF16>
__global__ void __launch_bounds__(256, 1)
sage_gemm_mma(const void* __restrict__ A0v, const void* __restrict__ A1v,
              const float* __restrict__ Bt, const float* __restrict__ bias,
              void* __restrict__ OutV, int M)
{
    constexpr int KCAT = 2 * KPART;
    constexpr int NC = KCAT / 32;
    extern __shared__ char sm[];
    const uint32_t smbase = smem_u32(sm);
    const uint32_t Aoff[2] = {0u, A_STAGE};
    const uint32_t Boff[2] = {2 * A_STAGE, 2 * A_STAGE + B_STAGE};

    int tid = threadIdx.x, lane = tid & 31, wid = tid >> 5;
    int m0 = blockIdx.x * 128;
    int warp_m = (wid >> 2) * 64, warp_n = (wid & 3) * 64;

    int arow = tid >> 1;
    int acol = (tid & 1) * 16;
    int grow = m0 + arow;
    bool avalid = grow < M;
    float sdeg = avalid ? g_invdeg[grow] : 0.f;

    float acc[4][8][4] = {};

    auto ldgA = [&](int ci, float4* r) {
        bool p1 = (ci * 32) >= KPART;
        if (!avalid) {
#pragma unroll
            for (int i = 0; i < 4; i++) r[i] = make_float4(0.f, 0.f, 0.f, 0.f);
            return;
        }
        if (!p1) {
            if (A0BF16) {
                ld16bf((const __nv_bfloat16*)A0v + (size_t)grow * KPART + ci * 32 + acol, r);
            } else {
                const float4* src =
                    (const float4*)((const float*)A0v + (size_t)grow * KPART + ci * 32 + acol);
#pragma unroll
                for (int i = 0; i < 4; i++) r[i] = src[i];
            }
#pragma unroll
            for (int i = 0; i < 4; i++) {
                r[i].x *= sdeg; r[i].y *= sdeg; r[i].z *= sdeg; r[i].w *= sdeg;
            }
        } else {
            int kof = ci * 32 - KPART;
            if (A1BF16) {
                ld16bf((const __nv_bfloat16*)A1v + (size_t)grow * KPART + kof + acol, r);
            } else {
                const float4* src =
                    (const float4*)((const float*)A1v + (size_t)grow * KPART + kof + acol);
#pragma unroll
                for (int i = 0; i < 4; i++) r[i] = src[i];
            }
        }
    };
    auto stsA = [&](int buf, const float4* r) {
        uint32_t a = smbase + Aoff[buf] + arow * 144 + acol * 4;
#pragma unroll
        for (int i = 0; i < 4; i++) {
            uint4 u;
            u.x = rna_tf32(r[i].x); u.y = rna_tf32(r[i].y);
            u.z = rna_tf32(r[i].z); u.w = rna_tf32(r[i].w);
            sts128(a + i * 16, u);
        }
    };
    auto cpB = [&](int ci, int buf) {
#pragma unroll
        for (int rr = 0; rr < 8; rr++) {
            int i = tid + 256 * rr;
            int n = i >> 3, kq = i & 7;
            uint32_t dst = smbase + Boff[buf] + n * 144 + kq * 16;
            const float* src = Bt + (size_t)n * KCAT + ci * 32 + kq * 4;
            cp_async16(dst, src);
        }
        cp_commit();
    };
    auto compute = [&](int buf) {
        uint32_t Ab = smbase + Aoff[buf] +
                      (warp_m + (lane & 15)) * 144 + ((lane & 16) ? 16 : 0);
        uint32_t Bb = smbase + Boff[buf] +
                      (warp_n + (lane & 7) + ((lane & 16) >> 1)) * 144 +
                      ((lane & 8) ? 16 : 0);
#pragma unroll
        for (int kk = 0; kk < 4; kk++) {
            uint32_t af[4][4];
#pragma unroll
            for (int ti = 0; ti < 4; ti++) ldsm4(af[ti], Ab + ti * 16 * 144 + kk * 32);
            uint32_t bf[4][4];
#pragma unroll
            for (int tjp = 0; tjp < 4; tjp++) ldsm4(bf[tjp], Bb + tjp * 16 * 144 + kk * 32);
#pragma unroll
            for (int ti = 0; ti < 4; ti++)
#pragma unroll
                for (int tjp = 0; tjp < 4; tjp++) {
                    mma_tf32(acc[ti][2 * tjp],     af[ti], bf[tjp][0], bf[tjp][1]);
                    mma_tf32(acc[ti][2 * tjp + 1], af[ti], bf[tjp][2], bf[tjp][3]);
                }
        }
    };

    float4 areg[4];
    ldgA(0, areg);
    cpB(0, 0);
    stsA(0, areg);

    for (int ci = 0; ci < NC; ci++) {
        int cb = ci & 1;
        float4 areg2[4];
        if (ci + 1 < NC) {
            ldgA(ci + 1, areg2);
            cpB(ci + 1, cb ^ 1);
            cp_wait<1>();
        } else {
            cp_wait<0>();
        }
        __syncthreads();
        compute(cb);
        __syncthreads();
        if (ci + 1 < NC) stsA(cb ^ 1, areg2);
    }

    int r0base = m0 + warp_m + (lane >> 2);
    int colb = warp_n + (lane & 3) * 2;
#pragma unroll
    for (int tj = 0; tj < 8; tj++) {
        int col = colb + tj * 8;
        float2 b2 = *(const float2*)(bias + col);
#pragma unroll
        for (int ti = 0; ti < 4; ti++) {
            int rr[2] = {r0base + ti * 16, r0base + ti * 16 + 8};
#pragma unroll
            for (int hh = 0; hh < 2; hh++) {
                int r = rr[hh];
                if (r >= M) continue;
                float2 v;
                v.x = acc[ti][tj][2 * hh]     + b2.x;
                v.y = acc[ti][tj][2 * hh + 1] + b2.y;
                if (RELU) { v.x = fmaxf(v.x, 0.f); v.y = fmaxf(v.y, 0.f); }
                if (OUTBF16) {
                    __nv_bfloat162 o2 = __float22bfloat162_rn(v);
                    *(__nv_bfloat162*)((__nv_bfloat16*)OutV + (size_t)r * HIDDEN + col) = o2;
                } else {
                    *(float2*)((float*)OutV + (size_t)r * HIDDEN + col) = v;
                }
            }
        }
    }
}

// ---------------- decoder (bf16 z, warp per pair, fp32 accum) ----------------
__global__ void decode_kernel(float* __restrict__ out, int E2) {
    int w = (blockIdx.x * blockDim.x + threadIdx.x) >> 5;
    if (w >= E2) return;
    int lane = threadIdx.x & 31;
    int a = g_ea[w], b = g_eb[w];
    const uint4* za = (const uint4*)((const char*)(g_z + (size_t)a * HIDDEN)) + lane;
    const uint4* zb = (const uint4*)((const char*)(g_z + (size_t)b * HIDDEN)) + lane;
    uint4 va = *za;
    uint4 vb = *zb;
    float acc = 0.f;
    const uint32_t* pa = (const uint32_t*)&va;
    const uint32_t* pb = (const uint32_t*)&vb;
#pragma unroll
    for (int j = 0; j < 4; j++) {
        float2 fa = __bfloat1622float2(*(const __nv_bfloat162*)&pa[j]);
        float2 fb = __bfloat1622float2(*(const __nv_bfloat162*)&pb[j]);
        acc = fmaf(fa.x, fb.x, acc);
        acc = fmaf(fa.y, fb.y, acc);
    }
#pragma unroll
    for (int o = 16; o > 0; o >>= 1) acc += __shfl_xor_sync(0xffffffffu, acc, o);
    if (lane == 0) out[w] = acc;
}

// ---------------- launch ----------------
extern "C" void kernel_launch(void* const* d_in, const int* in_sizes, int n_in,
                              void* d_out, int out_size) {
    const float* x   = (const float*)d_in[0];
    const void*  ei  = d_in[1];
    const void*  edg = d_in[2];
    const float* W1l = (const float*)d_in[3];
    const float* b1  = (const float*)d_in[4];
    const float* W1r = (const float*)d_in[5];
    const float* W2l = (const float*)d_in[6];
    const float* b2  = (const float*)d_in[7];
    const float* W2r = (const float*)d_in[8];
    float* out = (float*)d_out;

    int M  = in_sizes[0] / IN_CH;   // 100000
    int E  = in_sizes[1] / 2;       // 1.6M graph edges
    int E2 = out_size;              // 1.6M candidate pairs

    cudaFuncSetAttribute(sage_gemm_mma<128, true, false, true, true>,
                         cudaFuncAttributeMaxDynamicSharedMemorySize, GEMM_DSMEM);
    cudaFuncSetAttribute(sage_gemm_mma<256, false, true, true, true>,
                         cudaFuncAttributeMaxDynamicSharedMemorySize, GEMM_DSMEM);

    void* agg1p; cudaGetSymbolAddress(&agg1p, g_agg1);
    void* agg2p; cudaGetSymbolAddress(&agg2p, g_agg2);
    void* xbp;   cudaGetSymbolAddress(&xbp,   g_xb);
    void* hp;    cudaGetSymbolAddress(&hp,    g_h);
    void* zp;    cudaGetSymbolAddress(&zp,    g_z);
    float* bt1p; cudaGetSymbolAddress((void**)&bt1p, g_Bt1);
    float* bt2p; cudaGetSymbolAddress((void**)&bt2p, g_Bt2);
    void* cntp;  cudaGetSymbolAddress(&cntp,  g_cnt);

    int nb = (M + SCAN_BLK - 1) / SCAN_BLK;   // 391 <= 512

    detect_kernel<<<1, 256>>>((const int*)ei);
    cudaMemsetAsync(cntp, 0, (size_t)M * sizeof(int));
    convert_kernel<<<4096, 256>>>(ei, edg, E, E2);
    prep_x_kernel<<<(M * IN_CH / 8 + 255) / 256, 256>>>(x, M * IN_CH / 8);
    prep_weights<<<512, 256>>>(W1l, W1r, W2l, W2r);
    scan1_kernel<<<nb, SCAN_BLK>>>(M);
    scan2_kernel<<<1, 512>>>(nb);
    scan3_kernel<<<nb, SCAN_BLK>>>(M);
    fill_kernel<<<2048, 256>>>(E);

    int gtiles = (M + 127) / 128;

    // layer 1  (A0 = agg1 fp32, A1 = x bf16, h written bf16)
    gather1_kernel<<<(M * 32 + 255) / 256, 256>>>(M);
    sage_gemm_mma<128, true, false, true, true><<<gtiles, 256, GEMM_DSMEM>>>(
        agg1p, xbp, bt1p, b1, hp, M);
    // layer 2  (A0 = agg2 bf16, A1 = h bf16, z written bf16)
    gather2_kernel<<<(M * 32 + 255) / 256, 256>>>(M);
    sage_gemm_mma<256, false, true, true, true><<<gtiles, 256, GEMM_DSMEM>>>(
        agg2p, hp, bt2p, b2, zp, M);
    // decode
    decode_kernel<<<(E2 * 32 + 255) / 256, 256>>>(out, E2);
}

// round 10
// speedup vs baseline: 3.1231x; 1.0119x over previous
#include <cuda_runtime.h>
#include <cuda_bf16.h>
#include <cstdint>

#define N_NODES_MAX 100000
#define IN_CH 128
#define HIDDEN 256
#define N_EDGES_MAX 1600000

// ---------------- scratch (static device globals; no allocation) ----------------
__device__ float g_agg1[(size_t)N_NODES_MAX * IN_CH];          // 51.2 MB (fp32)
__device__ __nv_bfloat16 g_xb[(size_t)N_NODES_MAX * IN_CH];    // 25.6 MB (bf16 x)
__device__ __nv_bfloat16 g_h[(size_t)N_NODES_MAX * HIDDEN];    // 51.2 MB (bf16)
__device__ __nv_bfloat16 g_agg2[(size_t)N_NODES_MAX * HIDDEN]; // 51.2 MB (bf16)
__device__ __nv_bfloat16 g_z[(size_t)N_NODES_MAX * HIDDEN];    // 51.2 MB (decode-only)
__device__ float g_invdeg[N_NODES_MAX];
__device__ int   g_src[N_EDGES_MAX];
__device__ int   g_dst[N_EDGES_MAX];
__device__ int   g_ea [N_EDGES_MAX];
__device__ int   g_eb [N_EDGES_MAX];
__device__ int   g_is64;
// CSR
__device__ int   g_cnt[N_NODES_MAX];
__device__ int   g_rowstart[N_NODES_MAX];
__device__ int   g_cursor[N_NODES_MAX];
__device__ int   g_csrc[N_EDGES_MAX];
__device__ int   g_partial[512];
// pre-transposed, tf32-rounded weights: Bt[n][k_cat]  (k_cat = [Wl rows ; Wr rows])
__device__ float g_Bt1[256 * 256];   // layer1: Kcat=256
__device__ float g_Bt2[256 * 512];   // layer2: Kcat=512

// ---------------- small PTX helpers (sm_80-level features only) ----------------
__device__ __forceinline__ uint32_t smem_u32(const void* p) {
    uint32_t a;
    asm("{ .reg .u64 t; cvta.to.shared.u64 t, %1; cvt.u32.u64 %0, t; }" : "=r"(a) : "l"(p));
    return a;
}
__device__ __forceinline__ uint32_t rna_tf32(float f) {
    uint32_t r; asm("cvt.rna.tf32.f32 %0, %1;" : "=r"(r) : "f"(f)); return r;
}
__device__ __forceinline__ void sts128(uint32_t addr, uint4 v) {
    asm volatile("st.shared.v4.b32 [%0], {%1,%2,%3,%4};"
                 :: "r"(addr), "r"(v.x), "r"(v.y), "r"(v.z), "r"(v.w) : "memory");
}
__device__ __forceinline__ void cp_async16(uint32_t dst, const void* src) {
    asm volatile("cp.async.cg.shared.global [%0], [%1], 16;"
                 :: "r"(dst), "l"(src) : "memory");
}
__device__ __forceinline__ void cp_commit() {
    asm volatile("cp.async.commit_group;" ::: "memory");
}
template <int N>
__device__ __forceinline__ void cp_wait() {
    asm volatile("cp.async.wait_group %0;" :: "n"(N) : "memory");
}
__device__ __forceinline__ void ldsm4(uint32_t* r, uint32_t addr) {
    asm volatile("ldmatrix.sync.aligned.m8n8.x4.shared.b16 {%0,%1,%2,%3}, [%4];"
                 : "=r"(r[0]), "=r"(r[1]), "=r"(r[2]), "=r"(r[3]) : "r"(addr));
}
__device__ __forceinline__ void mma_tf32(float* c, const uint32_t* a,
                                         uint32_t b0, uint32_t b1) {
    asm volatile(
        "mma.sync.aligned.m16n8k8.row.col.f32.tf32.tf32.f32 "
        "{%0,%1,%2,%3}, {%4,%5,%6,%7}, {%8,%9}, {%0,%1,%2,%3};"
        : "+f"(c[0]), "+f"(c[1]), "+f"(c[2]), "+f"(c[3])
        : "r"(a[0]), "r"(a[1]), "r"(a[2]), "r"(a[3]), "r"(b0), "r"(b1));
}
// load 16 consecutive bf16 -> 4x float4
__device__ __forceinline__ void ld16bf(const __nv_bfloat16* p, float4* r) {
    uint4 u0 = *(const uint4*)p;
    uint4 u1 = *(const uint4*)(p + 8);
    const uint32_t* a = (const uint32_t*)&u0;
    const uint32_t* b = (const uint32_t*)&u1;
#pragma unroll
    for (int j = 0; j < 4; j++) {
        float2 f = __bfloat1622float2(*(const __nv_bfloat162*)&a[j]);
        ((float*)&r[j >> 1])[(j & 1) * 2]     = f.x;
        ((float*)&r[j >> 1])[(j & 1) * 2 + 1] = f.y;
    }
#pragma unroll
    for (int j = 0; j < 4; j++) {
        float2 f = __bfloat1622float2(*(const __nv_bfloat162*)&b[j]);
        ((float*)&r[2 + (j >> 1)])[(j & 1) * 2]     = f.x;
        ((float*)&r[2 + (j >> 1)])[(j & 1) * 2 + 1] = f.y;
    }
}
// accumulate 4 bf16 (uint2) into 4 floats
__device__ __forceinline__ void accbf4(float* acc, uint2 u) {
    float2 f0 = __bfloat1622float2(*(const __nv_bfloat162*)&u.x);
    float2 f1 = __bfloat1622float2(*(const __nv_bfloat162*)&u.y);
    acc[0] += f0.x; acc[1] += f0.y; acc[2] += f1.x; acc[3] += f1.y;
}
// accumulate 8 bf16 (uint4) into 8 floats
__device__ __forceinline__ void accbf8(float* acc, uint4 u) {
    const uint32_t* p = (const uint32_t*)&u;
#pragma unroll
    for (int j = 0; j < 4; j++) {
        float2 f = __bfloat1622float2(*(const __nv_bfloat162*)&p[j]);
        acc[2 * j]     += f.x;
        acc[2 * j + 1] += f.y;
    }
}

// ---------------- dtype detection (int64 vs int32 edge indices) ----------------
__global__ void detect_kernel(const int* __restrict__ ei32) {
    __shared__ int bad;
    if (threadIdx.x == 0) bad = 0;
    __syncthreads();
    for (int i = threadIdx.x; i < 2048; i += blockDim.x)
        if (ei32[2 * i + 1] != 0) bad = 1;
    __syncthreads();
    if (threadIdx.x == 0) g_is64 = bad ? 0 : 1;
}

// convert + histogram fused
__global__ void convert_kernel(const void* __restrict__ ei,
                               const void* __restrict__ edges,
                               int E, int E2) {
    int is64 = g_is64;
    int n = E > E2 ? E : E2;
    for (int e = blockIdx.x * blockDim.x + threadIdx.x; e < n;
         e += gridDim.x * blockDim.x) {
        if (e < E) {
            int s, d;
            if (is64) {
                const long long* p = (const long long*)ei;
                s = (int)p[e];
                d = (int)p[(size_t)e + E];
            } else {
                const int* p = (const int*)ei;
                s = p[e];
                d = p[e + E];
            }
            g_src[e] = s;
            g_dst[e] = d;
            atomicAdd(&g_cnt[d], 1);
        }
        if (e < E2) {
            if (is64) {
                const long long* q = (const long long*)edges;
                g_ea[e] = (int)q[2 * (size_t)e];
                g_eb[e] = (int)q[2 * (size_t)e + 1];
            } else {
                const int* q = (const int*)edges;
                g_ea[e] = q[2 * e];
                g_eb[e] = q[2 * e + 1];
            }
        }
    }
}

// fused: x fp32 -> bf16 staging  +  weights transpose/round
__global__ void prep_xw_kernel(const float* __restrict__ x, int n8,
                               const float* __restrict__ W1l, const float* __restrict__ W1r,
                               const float* __restrict__ W2l, const float* __restrict__ W2r) {
    int i = blockIdx.x * blockDim.x + threadIdx.x;
    if (i < n8) {
        const float4* src = (const float4*)x + 2 * (size_t)i;
        float4 v0 = src[0], v1 = src[1];
        __nv_bfloat162* dst = (__nv_bfloat162*)(g_xb + (size_t)i * 8);
        dst[0] = __float22bfloat162_rn(make_float2(v0.x, v0.y));
        dst[1] = __float22bfloat162_rn(make_float2(v0.z, v0.w));
        dst[2] = __float22bfloat162_rn(make_float2(v1.x, v1.y));
        dst[3] = __float22bfloat162_rn(make_float2(v1.z, v1.w));
    }
    if (i < 256 * 256) {
        int n = i >> 8, k = i & 255;
        float v = (k < 128) ? W1l[k * HIDDEN + n] : W1r[(k - 128) * HIDDEN + n];
        g_Bt1[n * 256 + k] = __uint_as_float(rna_tf32(v));
    }
    if (i < 256 * 512) {
        int n = i >> 9, k = i & 511;
        float v = (k < 256) ? W2l[k * HIDDEN + n] : W2r[(k - 256) * HIDDEN + n];
        g_Bt2[n * 512 + k] = __uint_as_float(rna_tf32(v));
    }
}

// ---------------- CSR build: 2-level exclusive scan + cursor scatter ----------------
#define SCAN_BLK 256

__global__ void scan1_kernel(int M) {
    __shared__ int sd[SCAN_BLK];
    int i = blockIdx.x * SCAN_BLK + threadIdx.x;
    sd[threadIdx.x] = (i < M) ? g_cnt[i] : 0;
    __syncthreads();
#pragma unroll
    for (int s = SCAN_BLK / 2; s > 0; s >>= 1) {
        if (threadIdx.x < s) sd[threadIdx.x] += sd[threadIdx.x + s];
        __syncthreads();
    }
    if (threadIdx.x == 0) g_partial[blockIdx.x] = sd[0];
}

__global__ void scan2_kernel(int nb) {
    __shared__ int sd[512];
    int t = threadIdx.x;
    sd[t] = (t < nb) ? g_partial[t] : 0;
    __syncthreads();
#pragma unroll
    for (int off = 1; off < 512; off <<= 1) {
        int v = (t >= off) ? sd[t - off] : 0;
        __syncthreads();
        sd[t] += v;
        __syncthreads();
    }
    if (t < nb) g_partial[t] = (t == 0) ? 0 : sd[t - 1];
}

__global__ void scan3_kernel(int M) {
    __shared__ int sd[SCAN_BLK];
    int i = blockIdx.x * SCAN_BLK + threadIdx.x;
    int cnt = (i < M) ? g_cnt[i] : 0;
    sd[threadIdx.x] = cnt;
    __syncthreads();
#pragma unroll
    for (int off = 1; off < SCAN_BLK; off <<= 1) {
        int v = (threadIdx.x >= off) ? sd[threadIdx.x - off] : 0;
        __syncthreads();
        sd[threadIdx.x] += v;
        __syncthreads();
    }
    if (i < M) {
        int start = g_partial[blockIdx.x] + sd[threadIdx.x] - cnt;
        g_rowstart[i] = start;
        g_cursor[i] = start;
        g_invdeg[i] = 1.0f / fmaxf((float)cnt, 1.0f);
    }
}

__global__ void fill_kernel(int E) {
    for (int e = blockIdx.x * blockDim.x + threadIdx.x; e < E;
         e += gridDim.x * blockDim.x) {
        int d = g_dst[e];
        int pos = atomicAdd(&g_cursor[d], 1);
        g_csrc[pos] = g_src[e];
    }
}
// after fill_kernel: g_cursor[n] == row end

// ---------------- gather aggregation (warp per node, 4x MLP unroll) ----------------
__global__ void gather1_kernel(int M) {
    int w = (blockIdx.x * blockDim.x + threadIdx.x) >> 5;
    if (w >= M) return;
    int lane = threadIdx.x & 31;
    int e0 = g_rowstart[w], e1 = g_cursor[w];
    float acc[4] = {};
    const __nv_bfloat16* base = g_xb + lane * 4;
    int e = e0;
    for (; e + 4 <= e1; e += 4) {
        int s0 = g_csrc[e], s1 = g_csrc[e + 1], s2 = g_csrc[e + 2], s3 = g_csrc[e + 3];
        uint2 u0 = *(const uint2*)(base + (size_t)s0 * IN_CH);
        uint2 u1 = *(const uint2*)(base + (size_t)s1 * IN_CH);
        uint2 u2 = *(const uint2*)(base + (size_t)s2 * IN_CH);
        uint2 u3 = *(const uint2*)(base + (size_t)s3 * IN_CH);
        accbf4(acc, u0); accbf4(acc, u1); accbf4(acc, u2); accbf4(acc, u3);
    }
    for (; e < e1; e++) {
        int s = g_csrc[e];
        uint2 u = *(const uint2*)(base + (size_t)s * IN_CH);
        accbf4(acc, u);
    }
    *(float4*)(g_agg1 + (size_t)w * IN_CH + lane * 4) =
        make_float4(acc[0], acc[1], acc[2], acc[3]);
}

__global__ void gather2_kernel(int M) {
    int w = (blockIdx.x * blockDim.x + threadIdx.x) >> 5;
    if (w >= M) return;
    int lane = threadIdx.x & 31;
    int e0 = g_rowstart[w], e1 = g_cursor[w];
    float acc[8] = {};
    const __nv_bfloat16* base = g_h + lane * 8;
    int e = e0;
    for (; e + 4 <= e1; e += 4) {
        int s0 = g_csrc[e], s1 = g_csrc[e + 1], s2 = g_csrc[e + 2], s3 = g_csrc[e + 3];
        uint4 u0 = *(const uint4*)(base + (size_t)s0 * HIDDEN);
        uint4 u1 = *(const uint4*)(base + (size_t)s1 * HIDDEN);
        uint4 u2 = *(const uint4*)(base + (size_t)s2 * HIDDEN);
        uint4 u3 = *(const uint4*)(base + (size_t)s3 * HIDDEN);
        accbf8(acc, u0); accbf8(acc, u1); accbf8(acc, u2); accbf8(acc, u3);
    }
    for (; e < e1; e++) {
        int s = g_csrc[e];
        uint4 u = *(const uint4*)(base + (size_t)s * HIDDEN);
        accbf8(acc, u);
    }
    uint4 o;
    uint32_t* po = (uint32_t*)&o;
#pragma unroll
    for (int j = 0; j < 4; j++) {
        __nv_bfloat162 b2 = __float22bfloat162_rn(make_float2(acc[2 * j], acc[2 * j + 1]));
        po[j] = *(const uint32_t*)&b2;
    }
    *(uint4*)(g_agg2 + (size_t)w * HIDDEN + lane * 8) = o;
}

// ---------------- mma.sync tf32 fused SAGE GEMM ----------------
// Out[m,0:256] = (A0[m,:]*invdeg[m]) @ Wl + A1[m,:] @ Wr + b  (opt ReLU)
// A0BF16/A1BF16: operand stored as bf16. OUTBF16: bf16 output.
#define A_STAGE 18432u
#define B_STAGE 36864u
#define GEMM_DSMEM (2 * (A_STAGE + B_STAGE))

template <int KPART, bool RELU, bool A0BF16, bool A1BF16, bool OUTBF16>
__global__ void __launch_bounds__(256, 1)
sage_gemm_mma(const void* __restrict__ A0v, const void* __restrict__ A1v,
              const float* __restrict__ Bt, const float* __restrict__ bias,
              void* __restrict__ OutV, int M)
{
    constexpr int KCAT = 2 * KPART;
    constexpr int NC = KCAT / 32;
    extern __shared__ char sm[];
    const uint32_t smbase = smem_u32(sm);
    const uint32_t Aoff[2] = {0u, A_STAGE};
    const uint32_t Boff[2] = {2 * A_STAGE, 2 * A_STAGE + B_STAGE};

    int tid = threadIdx.x, lane = tid & 31, wid = tid >> 5;
    int m0 = blockIdx.x * 128;
    int warp_m = (wid >> 2) * 64, warp_n = (wid & 3) * 64;

    int arow = tid >> 1;
    int acol = (tid & 1) * 16;
    int grow = m0 + arow;
    bool avalid = grow < M;
    float sdeg = avalid ? g_invdeg[grow] : 0.f;

    float acc[4][8][4] = {};

    auto ldgA = [&](int ci, float4* r) {
        bool p1 = (ci * 32) >= KPART;
        if (!avalid) {
#pragma unroll
            for (int i = 0; i < 4; i++) r[i] = make_float4(0.f, 0.f, 0.f, 0.f);
            return;
        }
        if (!p1) {
            if (A0BF16) {
                ld16bf((const __nv_bfloat16*)A0v + (size_t)grow * KPART + ci * 32 + acol, r);
            } else {
                const float4* src =
                    (const float4*)((const float*)A0v + (size_t)grow * KPART + ci * 32 + acol);
#pragma unroll
                for (int i = 0; i < 4; i++) r[i] = src[i];
            }
#pragma unroll
            for (int i = 0; i < 4; i++) {
                r[i].x *= sdeg; r[i].y *= sdeg; r[i].z *= sdeg; r[i].w *= sdeg;
            }
        } else {
            int kof = ci * 32 - KPART;
            if (A1BF16) {
                ld16bf((const __nv_bfloat16*)A1v + (size_t)grow * KPART + kof + acol, r);
            } else {
                const float4* src =
                    (const float4*)((const float*)A1v + (size_t)grow * KPART + kof + acol);
#pragma unroll
                for (int i = 0; i < 4; i++) r[i] = src[i];
            }
        }
    };
    auto stsA = [&](int buf, const float4* r) {
        uint32_t a = smbase + Aoff[buf] + arow * 144 + acol * 4;
#pragma unroll
        for (int i = 0; i < 4; i++) {
            uint4 u;
            u.x = rna_tf32(r[i].x); u.y = rna_tf32(r[i].y);
            u.z = rna_tf32(r[i].z); u.w = rna_tf32(r[i].w);
            sts128(a + i * 16, u);
        }
    };
    auto cpB = [&](int ci, int buf) {
#pragma unroll
        for (int rr = 0; rr < 8; rr++) {
            int i = tid + 256 * rr;
            int n = i >> 3, kq = i & 7;
            uint32_t dst = smbase + Boff[buf] + n * 144 + kq * 16;
            const float* src = Bt + (size_t)n * KCAT + ci * 32 + kq * 4;
            cp_async16(dst, src);
        }
        cp_commit();
    };
    auto compute = [&](int buf) {
        uint32_t Ab = smbase + Aoff[buf] +
                      (warp_m + (lane & 15)) * 144 + ((lane & 16) ? 16 : 0);
        uint32_t Bb = smbase + Boff[buf] +
                      (warp_n + (lane & 7) + ((lane & 16) >> 1)) * 144 +
                      ((lane & 8) ? 16 : 0);
#pragma unroll
        for (int kk = 0; kk < 4; kk++) {
            uint32_t af[4][4];
#pragma unroll
            for (int ti = 0; ti < 4; ti++) ldsm4(af[ti], Ab + ti * 16 * 144 + kk * 32);
            uint32_t bf[4][4];
#pragma unroll
            for (int tjp = 0; tjp < 4; tjp++) ldsm4(bf[tjp], Bb + tjp * 16 * 144 + kk * 32);
#pragma unroll
            for (int ti = 0; ti < 4; ti++)
#pragma unroll
                for (int tjp = 0; tjp < 4; tjp++) {
                    mma_tf32(acc[ti][2 * tjp],     af[ti], bf[tjp][0], bf[tjp][1]);
                    mma_tf32(acc[ti][2 * tjp + 1], af[ti], bf[tjp][2], bf[tjp][3]);
                }
        }
    };

    float4 areg[4];
    ldgA(0, areg);
    cpB(0, 0);
    stsA(0, areg);

    for (int ci = 0; ci < NC; ci++) {
        int cb = ci & 1;
        float4 areg2[4];
        if (ci + 1 < NC) {
            ldgA(ci + 1, areg2);
            cpB(ci + 1, cb ^ 1);
            cp_wait<1>();
        } else {
            cp_wait<0>();
        }
        __syncthreads();
        compute(cb);
        __syncthreads();
        if (ci + 1 < NC) stsA(cb ^ 1, areg2);
    }

    int r0base = m0 + warp_m + (lane >> 2);
    int colb = warp_n + (lane & 3) * 2;
#pragma unroll
    for (int tj = 0; tj < 8; tj++) {
        int col = colb + tj * 8;
        float2 b2 = *(const float2*)(bias + col);
#pragma unroll
        for (int ti = 0; ti < 4; ti++) {
            int rr[2] = {r0base + ti * 16, r0base + ti * 16 + 8};
#pragma unroll
            for (int hh = 0; hh < 2; hh++) {
                int r = rr[hh];
                if (r >= M) continue;
                float2 v;
                v.x = acc[ti][tj][2 * hh]     + b2.x;
                v.y = acc[ti][tj][2 * hh + 1] + b2.y;
                if (RELU) { v.x = fmaxf(v.x, 0.f); v.y = fmaxf(v.y, 0.f); }
                if (OUTBF16) {
                    __nv_bfloat162 o2 = __float22bfloat162_rn(v);
                    *(__nv_bfloat162*)((__nv_bfloat16*)OutV + (size_t)r * HIDDEN + col) = o2;
                } else {
                    *(float2*)((float*)OutV + (size_t)r * HIDDEN + col) = v;
                }
            }
        }
    }
}

// ---------------- decoder (bf16 z, warp per pair, fp32 accum) ----------------
__global__ void decode_kernel(float* __restrict__ out, int E2) {
    int w = (blockIdx.x * blockDim.x + threadIdx.x) >> 5;
    if (w >= E2) return;
    int lane = threadIdx.x & 31;
    int a = g_ea[w], b = g_eb[w];
    const uint4* za = (const uint4*)((const char*)(g_z + (size_t)a * HIDDEN)) + lane;
    const uint4* zb = (const uint4*)((const char*)(g_z + (size_t)b * HIDDEN)) + lane;
    uint4 va = *za;
    uint4 vb = *zb;
    float acc = 0.f;
    const uint32_t* pa = (const uint32_t*)&va;
    const uint32_t* pb = (const uint32_t*)&vb;
#pragma unroll
    for (int j = 0; j < 4; j++) {
        float2 fa = __bfloat1622float2(*(const __nv_bfloat162*)&pa[j]);
        float2 fb = __bfloat1622float2(*(const __nv_bfloat162*)&pb[j]);
        acc = fmaf(fa.x, fb.x, acc);
        acc = fmaf(fa.y, fb.y, acc);
    }
#pragma unroll
    for (int o = 16; o > 0; o >>= 1) acc += __shfl_xor_sync(0xffffffffu, acc, o);
    if (lane == 0) out[w] = acc;
}

// ---------------- launch ----------------
extern "C" void kernel_launch(void* const* d_in, const int* in_sizes, int n_in,
                              void* d_out, int out_size) {
    const float* x   = (const float*)d_in[0];
    const void*  ei  = d_in[1];
    const void*  edg = d_in[2];
    const float* W1l = (const float*)d_in[3];
    const float* b1  = (const float*)d_in[4];
    const float* W1r = (const float*)d_in[5];
    const float* W2l = (const float*)d_in[6];
    const float* b2  = (const float*)d_in[7];
    const float* W2r = (const float*)d_in[8];
    float* out = (float*)d_out;

    int M  = in_sizes[0] / IN_CH;   // 100000
    int E  = in_sizes[1] / 2;       // 1.6M graph edges
    int E2 = out_size;              // 1.6M candidate pairs

    cudaFuncSetAttribute(sage_gemm_mma<128, true, false, true, true>,
                         cudaFuncAttributeMaxDynamicSharedMemorySize, GEMM_DSMEM);
    cudaFuncSetAttribute(sage_gemm_mma<256, false, true, true, true>,
                         cudaFuncAttributeMaxDynamicSharedMemorySize, GEMM_DSMEM);

    void* agg1p; cudaGetSymbolAddress(&agg1p, g_agg1);
    void* agg2p; cudaGetSymbolAddress(&agg2p, g_agg2);
    void* xbp;   cudaGetSymbolAddress(&xbp,   g_xb);
    void* hp;    cudaGetSymbolAddress(&hp,    g_h);
    void* zp;    cudaGetSymbolAddress(&zp,    g_z);
    float* bt1p; cudaGetSymbolAddress((void**)&bt1p, g_Bt1);
    float* bt2p; cudaGetSymbolAddress((void**)&bt2p, g_Bt2);
    void* cntp;  cudaGetSymbolAddress(&cntp,  g_cnt);

    int nb = (M + SCAN_BLK - 1) / SCAN_BLK;   // 391 <= 512
    int n8 = M * IN_CH / 8;                   // 1.6M x-chunks

    detect_kernel<<<1, 256>>>((const int*)ei);
    cudaMemsetAsync(cntp, 0, (size_t)M * sizeof(int));
    convert_kernel<<<4096, 256>>>(ei, edg, E, E2);
    prep_xw_kernel<<<(n8 + 255) / 256, 256>>>(x, n8, W1l, W1r, W2l, W2r);
    scan1_kernel<<<nb, SCAN_BLK>>>(M);
    scan2_kernel<<<1, 512>>>(nb);
    scan3_kernel<<<nb, SCAN_BLK>>>(M);
    fill_kernel<<<2048, 256>>>(E);

    int gtiles = (M + 127) / 128;

    // layer 1  (A0 = agg1 fp32, A1 = x bf16, h written bf16)
    gather1_kernel<<<(M * 32 + 255) / 256, 256>>>(M);
    sage_gemm_mma<128, true, false, true, true><<<gtiles, 256, GEMM_DSMEM>>>(
        agg1p, xbp, bt1p, b1, hp, M);
    // layer 2  (A0 = agg2 bf16, A1 = h bf16, z written bf16)
    gather2_kernel<<<(M * 32 + 255) / 256, 256>>>(M);
    sage_gemm_mma<256, false, true, true, true><<<gtiles, 256, GEMM_DSMEM>>>(
        agg2p, hp, bt2p, b2, zp, M);
    // decode
    decode_kernel<<<(E2 * 32 + 255) / 256, 256>>>(out, E2);
}

// round 11
// speedup vs baseline: 3.4781x; 1.1137x over previous
#include <cuda_runtime.h>
#include <cuda_bf16.h>
#include <cstdint>

#define N_NODES_MAX 100000
#define IN_CH 128
#define HIDDEN 256
#define N_EDGES_MAX 1600000

// ---------------- scratch (static device globals; no allocation) ----------------
__device__ __nv_bfloat16 g_agg1[(size_t)N_NODES_MAX * IN_CH];  // 25.6 MB (bf16)
__device__ __nv_bfloat16 g_xb[(size_t)N_NODES_MAX * IN_CH];    // 25.6 MB (bf16 x)
__device__ __nv_bfloat16 g_h[(size_t)N_NODES_MAX * HIDDEN];    // 51.2 MB (bf16)
__device__ __nv_bfloat16 g_agg2[(size_t)N_NODES_MAX * HIDDEN]; // 51.2 MB (bf16)
__device__ __nv_bfloat16 g_z[(size_t)N_NODES_MAX * HIDDEN];    // 51.2 MB (decode-only)
__device__ float g_invdeg[N_NODES_MAX];
__device__ int   g_src[N_EDGES_MAX];
__device__ int   g_dst[N_EDGES_MAX];
__device__ int   g_ea [N_EDGES_MAX];
__device__ int   g_eb [N_EDGES_MAX];
__device__ int   g_is64;
// CSR
__device__ int   g_cnt[N_NODES_MAX];
__device__ int   g_rowstart[N_NODES_MAX];
__device__ int   g_cursor[N_NODES_MAX];
__device__ int   g_csrc[N_EDGES_MAX];
__device__ int   g_partial[512];
// pre-transposed, tf32-rounded weights: Bt[n][k_cat]  (k_cat = [Wl rows ; Wr rows])
__device__ float g_Bt1[256 * 256];   // layer1: Kcat=256
__device__ float g_Bt2[256 * 512];   // layer2: Kcat=512

// ---------------- small PTX helpers (sm_80-level features only) ----------------
__device__ __forceinline__ uint32_t smem_u32(const void* p) {
    uint32_t a;
    asm("{ .reg .u64 t; cvta.to.shared.u64 t, %1; cvt.u32.u64 %0, t; }" : "=r"(a) : "l"(p));
    return a;
}
__device__ __forceinline__ uint32_t rna_tf32(float f) {
    uint32_t r; asm("cvt.rna.tf32.f32 %0, %1;" : "=r"(r) : "f"(f)); return r;
}
__device__ __forceinline__ void sts128(uint32_t addr, uint4 v) {
    asm volatile("st.shared.v4.b32 [%0], {%1,%2,%3,%4};"
                 :: "r"(addr), "r"(v.x), "r"(v.y), "r"(v.z), "r"(v.w) : "memory");
}
__device__ __forceinline__ void cp_async16(uint32_t dst, const void* src) {
    asm volatile("cp.async.cg.shared.global [%0], [%1], 16;"
                 :: "r"(dst), "l"(src) : "memory");
}
__device__ __forceinline__ void cp_commit() {
    asm volatile("cp.async.commit_group;" ::: "memory");
}
template <int N>
__device__ __forceinline__ void cp_wait() {
    asm volatile("cp.async.wait_group %0;" :: "n"(N) : "memory");
}
__device__ __forceinline__ void ldsm4(uint32_t* r, uint32_t addr) {
    asm volatile("ldmatrix.sync.aligned.m8n8.x4.shared.b16 {%0,%1,%2,%3}, [%4];"
                 : "=r"(r[0]), "=r"(r[1]), "=r"(r[2]), "=r"(r[3]) : "r"(addr));
}
__device__ __forceinline__ void mma_tf32(float* c, const uint32_t* a,
                                         uint32_t b0, uint32_t b1) {
    asm volatile(
        "mma.sync.aligned.m16n8k8.row.col.f32.tf32.tf32.f32 "
        "{%0,%1,%2,%3}, {%4,%5,%6,%7}, {%8,%9}, {%0,%1,%2,%3};"
        : "+f"(c[0]), "+f"(c[1]), "+f"(c[2]), "+f"(c[3])
        : "r"(a[0]), "r"(a[1]), "r"(a[2]), "r"(a[3]), "r"(b0), "r"(b1));
}
// load 16 consecutive bf16 -> 4x float4
__device__ __forceinline__ void ld16bf(const __nv_bfloat16* p, float4* r) {
    uint4 u0 = *(const uint4*)p;
    uint4 u1 = *(const uint4*)(p + 8);
    const uint32_t* a = (const uint32_t*)&u0;
    const uint32_t* b = (const uint32_t*)&u1;
#pragma unroll
    for (int j = 0; j < 4; j++) {
        float2 f = __bfloat1622float2(*(const __nv_bfloat162*)&a[j]);
        ((float*)&r[j >> 1])[(j & 1) * 2]     = f.x;
        ((float*)&r[j >> 1])[(j & 1) * 2 + 1] = f.y;
    }
#pragma unroll
    for (int j = 0; j < 4; j++) {
        float2 f = __bfloat1622float2(*(const __nv_bfloat162*)&b[j]);
        ((float*)&r[2 + (j >> 1)])[(j & 1) * 2]     = f.x;
        ((float*)&r[2 + (j >> 1)])[(j & 1) * 2 + 1] = f.y;
    }
}
// accumulate 4 bf16 (uint2) into 4 floats
__device__ __forceinline__ void accbf4(float* acc, uint2 u) {
    float2 f0 = __bfloat1622float2(*(const __nv_bfloat162*)&u.x);
    float2 f1 = __bfloat1622float2(*(const __nv_bfloat162*)&u.y);
    acc[0] += f0.x; acc[1] += f0.y; acc[2] += f1.x; acc[3] += f1.y;
}
// accumulate 8 bf16 (uint4) into 8 floats
__device__ __forceinline__ void accbf8(float* acc, uint4 u) {
    const uint32_t* p = (const uint32_t*)&u;
#pragma unroll
    for (int j = 0; j < 4; j++) {
        float2 f = __bfloat1622float2(*(const __nv_bfloat162*)&p[j]);
        acc[2 * j]     += f.x;
        acc[2 * j + 1] += f.y;
    }
}
// dot-accumulate two uint4 bf16 vectors into fp32 scalar
__device__ __forceinline__ void dotbf8(float& acc, uint4 ua, uint4 ub) {
    const uint32_t* pa = (const uint32_t*)&ua;
    const uint32_t* pb = (const uint32_t*)&ub;
#pragma unroll
    for (int j = 0; j < 4; j++) {
        float2 fa = __bfloat1622float2(*(const __nv_bfloat162*)&pa[j]);
        float2 fb = __bfloat1622float2(*(const __nv_bfloat162*)&pb[j]);
        acc = fmaf(fa.x, fb.x, acc);
        acc = fmaf(fa.y, fb.y, acc);
    }
}

// ---------------- dtype detection (int64 vs int32 edge indices) ----------------
__global__ void detect_kernel(const int* __restrict__ ei32) {
    __shared__ int bad;
    if (threadIdx.x == 0) bad = 0;
    __syncthreads();
    for (int i = threadIdx.x; i < 2048; i += blockDim.x)
        if (ei32[2 * i + 1] != 0) bad = 1;
    __syncthreads();
    if (threadIdx.x == 0) g_is64 = bad ? 0 : 1;
}

// convert + histogram fused
__global__ void convert_kernel(const void* __restrict__ ei,
                               const void* __restrict__ edges,
                               int E, int E2) {
    int is64 = g_is64;
    int n = E > E2 ? E : E2;
    for (int e = blockIdx.x * blockDim.x + threadIdx.x; e < n;
         e += gridDim.x * blockDim.x) {
        if (e < E) {
            int s, d;
            if (is64) {
                const long long* p = (const long long*)ei;
                s = (int)p[e];
                d = (int)p[(size_t)e + E];
            } else {
                const int* p = (const int*)ei;
                s = p[e];
                d = p[e + E];
            }
            g_src[e] = s;
            g_dst[e] = d;
            atomicAdd(&g_cnt[d], 1);
        }
        if (e < E2) {
            if (is64) {
                const long long* q = (const long long*)edges;
                g_ea[e] = (int)q[2 * (size_t)e];
                g_eb[e] = (int)q[2 * (size_t)e + 1];
            } else {
                const int* q = (const int*)edges;
                g_ea[e] = q[2 * e];
                g_eb[e] = q[2 * e + 1];
            }
        }
    }
}

// fused: x fp32 -> bf16 staging  +  weights transpose/round
__global__ void prep_xw_kernel(const float* __restrict__ x, int n8,
                               const float* __restrict__ W1l, const float* __restrict__ W1r,
                               const float* __restrict__ W2l, const float* __restrict__ W2r) {
    int i = blockIdx.x * blockDim.x + threadIdx.x;
    if (i < n8) {
        const float4* src = (const float4*)x + 2 * (size_t)i;
        float4 v0 = src[0], v1 = src[1];
        __nv_bfloat162* dst = (__nv_bfloat162*)(g_xb + (size_t)i * 8);
        dst[0] = __float22bfloat162_rn(make_float2(v0.x, v0.y));
        dst[1] = __float22bfloat162_rn(make_float2(v0.z, v0.w));
        dst[2] = __float22bfloat162_rn(make_float2(v1.x, v1.y));
        dst[3] = __float22bfloat162_rn(make_float2(v1.z, v1.w));
    }
    if (i < 256 * 256) {
        int n = i >> 8, k = i & 255;
        float v = (k < 128) ? W1l[k * HIDDEN + n] : W1r[(k - 128) * HIDDEN + n];
        g_Bt1[n * 256 + k] = __uint_as_float(rna_tf32(v));
    }
    if (i < 256 * 512) {
        int n = i >> 9, k = i & 511;
        float v = (k < 256) ? W2l[k * HIDDEN + n] : W2r[(k - 256) * HIDDEN + n];
        g_Bt2[n * 512 + k] = __uint_as_float(rna_tf32(v));
    }
}

// ---------------- CSR build: 2-level exclusive scan + cursor scatter ----------------
#define SCAN_BLK 256

__global__ void scan1_kernel(int M) {
    __shared__ int sd[SCAN_BLK];
    int i = blockIdx.x * SCAN_BLK + threadIdx.x;
    sd[threadIdx.x] = (i < M) ? g_cnt[i] : 0;
    __syncthreads();
#pragma unroll
    for (int s = SCAN_BLK / 2; s > 0; s >>= 1) {
        if (threadIdx.x < s) sd[threadIdx.x] += sd[threadIdx.x + s];
        __syncthreads();
    }
    if (threadIdx.x == 0) g_partial[blockIdx.x] = sd[0];
}

__global__ void scan2_kernel(int nb) {
    __shared__ int sd[512];
    int t = threadIdx.x;
    sd[t] = (t < nb) ? g_partial[t] : 0;
    __syncthreads();
#pragma unroll
    for (int off = 1; off < 512; off <<= 1) {
        int v = (t >= off) ? sd[t - off] : 0;
        __syncthreads();
        sd[t] += v;
        __syncthreads();
    }
    if (t < nb) g_partial[t] = (t == 0) ? 0 : sd[t - 1];
}

__global__ void scan3_kernel(int M) {
    __shared__ int sd[SCAN_BLK];
    int i = blockIdx.x * SCAN_BLK + threadIdx.x;
    int cnt = (i < M) ? g_cnt[i] : 0;
    sd[threadIdx.x] = cnt;
    __syncthreads();
#pragma unroll
    for (int off = 1; off < SCAN_BLK; off <<= 1) {
        int v = (threadIdx.x >= off) ? sd[threadIdx.x - off] : 0;
        __syncthreads();
        sd[threadIdx.x] += v;
        __syncthreads();
    }
    if (i < M) {
        int start = g_partial[blockIdx.x] + sd[threadIdx.x] - cnt;
        g_rowstart[i] = start;
        g_cursor[i] = start;
        g_invdeg[i] = 1.0f / fmaxf((float)cnt, 1.0f);
    }
}

__global__ void fill_kernel(int E) {
    for (int e = blockIdx.x * blockDim.x + threadIdx.x; e < E;
         e += gridDim.x * blockDim.x) {
        int d = g_dst[e];
        int pos = atomicAdd(&g_cursor[d], 1);
        g_csrc[pos] = g_src[e];
    }
}
// after fill_kernel: g_cursor[n] == row end

// ---------------- gather aggregation (warp per node, 4x MLP unroll) ----------------
__global__ void gather1_kernel(int M) {
    int w = (blockIdx.x * blockDim.x + threadIdx.x) >> 5;
    if (w >= M) return;
    int lane = threadIdx.x & 31;
    int e0 = g_rowstart[w], e1 = g_cursor[w];
    float acc[4] = {};
    const __nv_bfloat16* base = g_xb + lane * 4;
    int e = e0;
    for (; e + 4 <= e1; e += 4) {
        int s0 = g_csrc[e], s1 = g_csrc[e + 1], s2 = g_csrc[e + 2], s3 = g_csrc[e + 3];
        uint2 u0 = *(const uint2*)(base + (size_t)s0 * IN_CH);
        uint2 u1 = *(const uint2*)(base + (size_t)s1 * IN_CH);
        uint2 u2 = *(const uint2*)(base + (size_t)s2 * IN_CH);
        uint2 u3 = *(const uint2*)(base + (size_t)s3 * IN_CH);
        accbf4(acc, u0); accbf4(acc, u1); accbf4(acc, u2); accbf4(acc, u3);
    }
    for (; e < e1; e++) {
        int s = g_csrc[e];
        uint2 u = *(const uint2*)(base + (size_t)s * IN_CH);
        accbf4(acc, u);
    }
    uint2 o;
    __nv_bfloat162 b0 = __float22bfloat162_rn(make_float2(acc[0], acc[1]));
    __nv_bfloat162 b1 = __float22bfloat162_rn(make_float2(acc[2], acc[3]));
    o.x = *(const uint32_t*)&b0;
    o.y = *(const uint32_t*)&b1;
    *(uint2*)(g_agg1 + (size_t)w * IN_CH + lane * 4) = o;
}

__global__ void gather2_kernel(int M) {
    int w = (blockIdx.x * blockDim.x + threadIdx.x) >> 5;
    if (w >= M) return;
    int lane = threadIdx.x & 31;
    int e0 = g_rowstart[w], e1 = g_cursor[w];
    float acc[8] = {};
    const __nv_bfloat16* base = g_h + lane * 8;
    int e = e0;
    for (; e + 4 <= e1; e += 4) {
        int s0 = g_csrc[e], s1 = g_csrc[e + 1], s2 = g_csrc[e + 2], s3 = g_csrc[e + 3];
        uint4 u0 = *(const uint4*)(base + (size_t)s0 * HIDDEN);
        uint4 u1 = *(const uint4*)(base + (size_t)s1 * HIDDEN);
        uint4 u2 = *(const uint4*)(base + (size_t)s2 * HIDDEN);
        uint4 u3 = *(const uint4*)(base + (size_t)s3 * HIDDEN);
        accbf8(acc, u0); accbf8(acc, u1); accbf8(acc, u2); accbf8(acc, u3);
    }
    for (; e < e1; e++) {
        int s = g_csrc[e];
        uint4 u = *(const uint4*)(base + (size_t)s * HIDDEN);
        accbf8(acc, u);
    }
    uint4 o;
    uint32_t* po = (uint32_t*)&o;
#pragma unroll
    for (int j = 0; j < 4; j++) {
        __nv_bfloat162 b2 = __float22bfloat162_rn(make_float2(acc[2 * j], acc[2 * j + 1]));
        po[j] = *(const uint32_t*)&b2;
    }
    *(uint4*)(g_agg2 + (size_t)w * HIDDEN + lane * 8) = o;
}

// ---------------- mma.sync tf32 fused SAGE GEMM ----------------
// Out[m,0:256] = (A0[m,:]*invdeg[m]) @ Wl + A1[m,:] @ Wr + b  (opt ReLU)
// A0BF16/A1BF16: operand stored as bf16. OUTBF16: bf16 output.
#define A_STAGE 18432u
#define B_STAGE 36864u
#define GEMM_DSMEM (2 * (A_STAGE + B_STAGE))

template <int KPART, bool RELU, bool A0BF16, bool A1BF16, bool OUTBF16>
__global__ void __launch_bounds__(256, 1)
sage_gemm_mma(const void* __restrict__ A0v, const void* __restrict__ A1v,
              const float* __restrict__ Bt, const float* __restrict__ bias,
              void* __restrict__ OutV, int M)
{
    constexpr int KCAT = 2 * KPART;
    constexpr int NC = KCAT / 32;
    extern __shared__ char sm[];
    const uint32_t smbase = smem_u32(sm);
    const uint32_t Aoff[2] = {0u, A_STAGE};
    const uint32_t Boff[2] = {2 * A_STAGE, 2 * A_STAGE + B_STAGE};

    int tid = threadIdx.x, lane = tid & 31, wid = tid >> 5;
    int m0 = blockIdx.x * 128;
    int warp_m = (wid >> 2) * 64, warp_n = (wid & 3) * 64;

    int arow = tid >> 1;
    int acol = (tid & 1) * 16;
    int grow = m0 + arow;
    bool avalid = grow < M;
    float sdeg = avalid ? g_invdeg[grow] : 0.f;

    float acc[4][8][4] = {};

    auto ldgA = [&](int ci, float4* r) {
        bool p1 = (ci * 32) >= KPART;
        if (!avalid) {
#pragma unroll
            for (int i = 0; i < 4; i++) r[i] = make_float4(0.f, 0.f, 0.f, 0.f);
            return;
        }
        if (!p1) {
            if (A0BF16) {
                ld16bf((const __nv_bfloat16*)A0v + (size_t)grow * KPART + ci * 32 + acol, r);
            } else {
                const float4* src =
                    (const float4*)((const float*)A0v + (size_t)grow * KPART + ci * 32 + acol);
#pragma unroll
                for (int i = 0; i < 4; i++) r[i] = src[i];
            }
#pragma unroll
            for (int i = 0; i < 4; i++) {
                r[i].x *= sdeg; r[i].y *= sdeg; r[i].z *= sdeg; r[i].w *= sdeg;
            }
        } else {
            int kof = ci * 32 - KPART;
            if (A1BF16) {
                ld16bf((const __nv_bfloat16*)A1v + (size_t)grow * KPART + kof + acol, r);
            } else {
                const float4* src =
                    (const float4*)((const float*)A1v + (size_t)grow * KPART + kof + acol);
#pragma unroll
                for (int i = 0; i < 4; i++) r[i] = src[i];
            }
        }
    };
    auto stsA = [&](int buf, const float4* r) {
        uint32_t a = smbase + Aoff[buf] + arow * 144 + acol * 4;
#pragma unroll
        for (int i = 0; i < 4; i++) {
            uint4 u;
            u.x = rna_tf32(r[i].x); u.y = rna_tf32(r[i].y);
            u.z = rna_tf32(r[i].z); u.w = rna_tf32(r[i].w);
            sts128(a + i * 16, u);
        }
    };
    auto cpB = [&](int ci, int buf) {
#pragma unroll
        for (int rr = 0; rr < 8; rr++) {
            int i = tid + 256 * rr;
            int n = i >> 3, kq = i & 7;
            uint32_t dst = smbase + Boff[buf] + n * 144 + kq * 16;
            const float* src = Bt + (size_t)n * KCAT + ci * 32 + kq * 4;
            cp_async16(dst, src);
        }
        cp_commit();
    };
    auto compute = [&](int buf) {
        uint32_t Ab = smbase + Aoff[buf] +
                      (warp_m + (lane & 15)) * 144 + ((lane & 16) ? 16 : 0);
        uint32_t Bb = smbase + Boff[buf] +
                      (warp_n + (lane & 7) + ((lane & 16) >> 1)) * 144 +
                      ((lane & 8) ? 16 : 0);
#pragma unroll
        for (int kk = 0; kk < 4; kk++) {
            uint32_t af[4][4];
#pragma unroll
            for (int ti = 0; ti < 4; ti++) ldsm4(af[ti], Ab + ti * 16 * 144 + kk * 32);
            uint32_t bf[4][4];
#pragma unroll
            for (int tjp = 0; tjp < 4; tjp++) ldsm4(bf[tjp], Bb + tjp * 16 * 144 + kk * 32);
#pragma unroll
            for (int ti = 0; ti < 4; ti++)
#pragma unroll
                for (int tjp = 0; tjp < 4; tjp++) {
                    mma_tf32(acc[ti][2 * tjp],     af[ti], bf[tjp][0], bf[tjp][1]);
                    mma_tf32(acc[ti][2 * tjp + 1], af[ti], bf[tjp][2], bf[tjp][3]);
                }
        }
    };

    float4 areg[4];
    ldgA(0, areg);
    cpB(0, 0);
    stsA(0, areg);

    for (int ci = 0; ci < NC; ci++) {
        int cb = ci & 1;
        float4 areg2[4];
        if (ci + 1 < NC) {
            ldgA(ci + 1, areg2);
            cpB(ci + 1, cb ^ 1);
            cp_wait<1>();
        } else {
            cp_wait<0>();
        }
        __syncthreads();
        compute(cb);
        __syncthreads();
        if (ci + 1 < NC) stsA(cb ^ 1, areg2);
    }

    int r0base = m0 + warp_m + (lane >> 2);
    int colb = warp_n + (lane & 3) * 2;
#pragma unroll
    for (int tj = 0; tj < 8; tj++) {
        int col = colb + tj * 8;
        float2 b2 = *(const float2*)(bias + col);
#pragma unroll
        for (int ti = 0; ti < 4; ti++) {
            int rr[2] = {r0base + ti * 16, r0base + ti * 16 + 8};
#pragma unroll
            for (int hh = 0; hh < 2; hh++) {
                int r = rr[hh];
                if (r >= M) continue;
                float2 v;
                v.x = acc[ti][tj][2 * hh]     + b2.x;
                v.y = acc[ti][tj][2 * hh + 1] + b2.y;
                if (RELU) { v.x = fmaxf(v.x, 0.f); v.y = fmaxf(v.y, 0.f); }
                if (OUTBF16) {
                    __nv_bfloat162 o2 = __float22bfloat162_rn(v);
                    *(__nv_bfloat162*)((__nv_bfloat16*)OutV + (size_t)r * HIDDEN + col) = o2;
                } else {
                    *(float2*)((float*)OutV + (size_t)r * HIDDEN + col) = v;
                }
            }
        }
    }
}

// ---------------- decoder: 2 pairs per warp (bf16 z, fp32 accum) ----------------
__global__ void decode_kernel(float* __restrict__ out, int E2) {
    int w = (blockIdx.x * blockDim.x + threadIdx.x) >> 5;   // warp id
    int p0 = 2 * w, p1 = 2 * w + 1;
    if (p0 >= E2) return;
    int lane = threadIdx.x & 31;
    bool has1 = p1 < E2;

    int a0 = g_ea[p0], b0 = g_eb[p0];
    int a1 = has1 ? g_ea[p1] : a0;
    int b1 = has1 ? g_eb[p1] : b0;

    const uint4* za0 = (const uint4*)((const char*)(g_z + (size_t)a0 * HIDDEN)) + lane;
    const uint4* zb0 = (const uint4*)((const char*)(g_z + (size_t)b0 * HIDDEN)) + lane;
    const uint4* za1 = (const uint4*)((const char*)(g_z + (size_t)a1 * HIDDEN)) + lane;
    const uint4* zb1 = (const uint4*)((const char*)(g_z + (size_t)b1 * HIDDEN)) + lane;
    // 4 independent in-flight loads per lane
    uint4 va0 = *za0;
    uint4 vb0 = *zb0;
    uint4 va1 = *za1;
    uint4 vb1 = *zb1;

    float acc0 = 0.f, acc1 = 0.f;
    dotbf8(acc0, va0, vb0);
    dotbf8(acc1, va1, vb1);
#pragma unroll
    for (int o = 16; o > 0; o >>= 1) {
        acc0 += __shfl_xor_sync(0xffffffffu, acc0, o);
        acc1 += __shfl_xor_sync(0xffffffffu, acc1, o);
    }
    if (lane == 0) {
        out[p0] = acc0;
        if (has1) out[p1] = acc1;
    }
}

// ---------------- launch ----------------
extern "C" void kernel_launch(void* const* d_in, const int* in_sizes, int n_in,
                              void* d_out, int out_size) {
    const float* x   = (const float*)d_in[0];
    const void*  ei  = d_in[1];
    const void*  edg = d_in[2];
    const float* W1l = (const float*)d_in[3];
    const float* b1  = (const float*)d_in[4];
    const float* W1r = (const float*)d_in[5];
    const float* W2l = (const float*)d_in[6];
    const float* b2  = (const float*)d_in[7];
    const float* W2r = (const float*)d_in[8];
    float* out = (float*)d_out;

    int M  = in_sizes[0] / IN_CH;   // 100000
    int E  = in_sizes[1] / 2;       // 1.6M graph edges
    int E2 = out_size;              // 1.6M candidate pairs

    cudaFuncSetAttribute(sage_gemm_mma<128, true, true, true, true>,
                         cudaFuncAttributeMaxDynamicSharedMemorySize, GEMM_DSMEM);
    cudaFuncSetAttribute(sage_gemm_mma<256, false, true, true, true>,
                         cudaFuncAttributeMaxDynamicSharedMemorySize, GEMM_DSMEM);

    void* agg1p; cudaGetSymbolAddress(&agg1p, g_agg1);
    void* agg2p; cudaGetSymbolAddress(&agg2p, g_agg2);
    void* xbp;   cudaGetSymbolAddress(&xbp,   g_xb);
    void* hp;    cudaGetSymbolAddress(&hp,    g_h);
    void* zp;    cudaGetSymbolAddress(&zp,    g_z);
    float* bt1p; cudaGetSymbolAddress((void**)&bt1p, g_Bt1);
    float* bt2p; cudaGetSymbolAddress((void**)&bt2p, g_Bt2);
    void* cntp;  cudaGetSymbolAddress(&cntp,  g_cnt);

    int nb = (M + SCAN_BLK - 1) / SCAN_BLK;   // 391 <= 512
    int n8 = M * IN_CH / 8;                   // 1.6M x-chunks

    detect_kernel<<<1, 256>>>((const int*)ei);
    cudaMemsetAsync(cntp, 0, (size_t)M * sizeof(int));
    convert_kernel<<<4096, 256>>>(ei, edg, E, E2);
    prep_xw_kernel<<<(n8 + 255) / 256, 256>>>(x, n8, W1l, W1r, W2l, W2r);
    scan1_kernel<<<nb, SCAN_BLK>>>(M);
    scan2_kernel<<<1, 512>>>(nb);
    scan3_kernel<<<nb, SCAN_BLK>>>(M);
    fill_kernel<<<2048, 256>>>(E);

    int gtiles = (M + 127) / 128;

    // layer 1  (A0 = agg1 bf16, A1 = x bf16, h written bf16)
    gather1_kernel<<<(M * 32 + 255) / 256, 256>>>(M);
    sage_gemm_mma<128, true, true, true, true><<<gtiles, 256, GEMM_DSMEM>>>(
        agg1p, xbp, bt1p, b1, hp, M);
    // layer 2  (A0 = agg2 bf16, A1 = h bf16, z written bf16)
    gather2_kernel<<<(M * 32 + 255) / 256, 256>>>(M);
    sage_gemm_mma<256, false, true, true, true><<<gtiles, 256, GEMM_DSMEM>>>(
        agg2p, hp, bt2p, b2, zp, M);
    // decode: 2 pairs per warp
    int nwarp = (E2 + 1) / 2;
    decode_kernel<<<(nwarp * 32 + 255) / 256, 256>>>(out, E2);
}

// round 14
// speedup vs baseline: 3.6035x; 1.0361x over previous
#include <cuda_runtime.h>
#include <cuda_bf16.h>
#include <cstdint>

#define N_NODES_MAX 100000
#define IN_CH 128
#define HIDDEN 256
#define N_EDGES_MAX 1600000

// ---------------- scratch (static device globals; no allocation) ----------------
__device__ __nv_bfloat16 g_agg1[(size_t)N_NODES_MAX * IN_CH];  // 25.6 MB (bf16)
__device__ __nv_bfloat16 g_xb[(size_t)N_NODES_MAX * IN_CH];    // 25.6 MB (bf16 x)
__device__ __nv_bfloat16 g_h[(size_t)N_NODES_MAX * HIDDEN];    // 51.2 MB (bf16)
__device__ __nv_bfloat16 g_agg2[(size_t)N_NODES_MAX * HIDDEN]; // 51.2 MB (bf16)
__device__ __nv_bfloat16 g_z[(size_t)N_NODES_MAX * HIDDEN];    // 51.2 MB (decode-only)
__device__ float g_invdeg[N_NODES_MAX];
__device__ int   g_src[N_EDGES_MAX];
__device__ int   g_dst[N_EDGES_MAX];
__device__ int   g_ea [N_EDGES_MAX];
__device__ int   g_eb [N_EDGES_MAX];
__device__ int   g_is64;
// CSR
__device__ int   g_cnt[N_NODES_MAX];
__device__ int   g_rowstart[N_NODES_MAX];
__device__ int   g_cursor[N_NODES_MAX];
__device__ int   g_csrc[N_EDGES_MAX];
__device__ int   g_partial[512];
// pre-transposed, tf32-rounded weights: Bt[n][k_cat]  (k_cat = [Wl rows ; Wr rows])
__device__ float g_Bt1[256 * 256];   // layer1: Kcat=256
__device__ float g_Bt2[256 * 512];   // layer2: Kcat=512

// ---------------- small PTX helpers (sm_80-level features only) ----------------
__device__ __forceinline__ uint32_t smem_u32(const void* p) {
    uint32_t a;
    asm("{ .reg .u64 t; cvta.to.shared.u64 t, %1; cvt.u32.u64 %0, t; }" : "=r"(a) : "l"(p));
    return a;
}
__device__ __forceinline__ uint32_t rna_tf32(float f) {
    uint32_t r; asm("cvt.rna.tf32.f32 %0, %1;" : "=r"(r) : "f"(f)); return r;
}
__device__ __forceinline__ void sts128(uint32_t addr, uint4 v) {
    asm volatile("st.shared.v4.b32 [%0], {%1,%2,%3,%4};"
                 :: "r"(addr), "r"(v.x), "r"(v.y), "r"(v.z), "r"(v.w) : "memory");
}
__device__ __forceinline__ void cp_async16(uint32_t dst, const void* src) {
    asm volatile("cp.async.cg.shared.global [%0], [%1], 16;"
                 :: "r"(dst), "l"(src) : "memory");
}
__device__ __forceinline__ void cp_commit() {
    asm volatile("cp.async.commit_group;" ::: "memory");
}
template <int N>
__device__ __forceinline__ void cp_wait() {
    asm volatile("cp.async.wait_group %0;" :: "n"(N) : "memory");
}
__device__ __forceinline__ void ldsm4(uint32_t* r, uint32_t addr) {
    asm volatile("ldmatrix.sync.aligned.m8n8.x4.shared.b16 {%0,%1,%2,%3}, [%4];"
                 : "=r"(r[0]), "=r"(r[1]), "=r"(r[2]), "=r"(r[3]) : "r"(addr));
}
__device__ __forceinline__ void mma_tf32(float* c, const uint32_t* a,
                                         uint32_t b0, uint32_t b1) {
    asm volatile(
        "mma.sync.aligned.m16n8k8.row.col.f32.tf32.tf32.f32 "
        "{%0,%1,%2,%3}, {%4,%5,%6,%7}, {%8,%9}, {%0,%1,%2,%3};"
        : "+f"(c[0]), "+f"(c[1]), "+f"(c[2]), "+f"(c[3])
        : "r"(a[0]), "r"(a[1]), "r"(a[2]), "r"(a[3]), "r"(b0), "r"(b1));
}
// load 16 consecutive bf16 -> 4x float4
__device__ __forceinline__ void ld16bf(const __nv_bfloat16* p, float4* r) {
    uint4 u0 = *(const uint4*)p;
    uint4 u1 = *(const uint4*)(p + 8);
    const uint32_t* a = (const uint32_t*)&u0;
    const uint32_t* b = (const uint32_t*)&u1;
#pragma unroll
    for (int j = 0; j < 4; j++) {
        float2 f = __bfloat1622float2(*(const __nv_bfloat162*)&a[j]);
        ((float*)&r[j >> 1])[(j & 1) * 2]     = f.x;
        ((float*)&r[j >> 1])[(j & 1) * 2 + 1] = f.y;
    }
#pragma unroll
    for (int j = 0; j < 4; j++) {
        float2 f = __bfloat1622float2(*(const __nv_bfloat162*)&b[j]);
        ((float*)&r[2 + (j >> 1)])[(j & 1) * 2]     = f.x;
        ((float*)&r[2 + (j >> 1)])[(j & 1) * 2 + 1] = f.y;
    }
}
// accumulate 4 bf16 (uint2) into 4 floats
__device__ __forceinline__ void accbf4(float* acc, uint2 u) {
    float2 f0 = __bfloat1622float2(*(const __nv_bfloat162*)&u.x);
    float2 f1 = __bfloat1622float2(*(const __nv_bfloat162*)&u.y);
    acc[0] += f0.x; acc[1] += f0.y; acc[2] += f1.x; acc[3] += f1.y;
}
// accumulate 8 bf16 (uint4) into 8 floats
__device__ __forceinline__ void accbf8(float* acc, uint4 u) {
    const uint32_t* p = (const uint32_t*)&u;
#pragma unroll
    for (int j = 0; j < 4; j++) {
        float2 f = __bfloat1622float2(*(const __nv_bfloat162*)&p[j]);
        acc[2 * j]     += f.x;
        acc[2 * j + 1] += f.y;
    }
}
// dot-accumulate two uint4 bf16 vectors into fp32 scalar
__device__ __forceinline__ void dotbf8(float& acc, uint4 ua, uint4 ub) {
    const uint32_t* pa = (const uint32_t*)&ua;
    const uint32_t* pb = (const uint32_t*)&ub;
#pragma unroll
    for (int j = 0; j < 4; j++) {
        float2 fa = __bfloat1622float2(*(const __nv_bfloat162*)&pa[j]);
        float2 fb = __bfloat1622float2(*(const __nv_bfloat162*)&pb[j]);
        acc = fmaf(fa.x, fb.x, acc);
        acc = fmaf(fa.y, fb.y, acc);
    }
}

// ---------------- dtype detection (int64 vs int32 edge indices) ----------------
__global__ void detect_kernel(const int* __restrict__ ei32) {
    __shared__ int bad;
    if (threadIdx.x == 0) bad = 0;
    __syncthreads();
    for (int i = threadIdx.x; i < 2048; i += blockDim.x)
        if (ei32[2 * i + 1] != 0) bad = 1;
    __syncthreads();
    if (threadIdx.x == 0) g_is64 = bad ? 0 : 1;
}

// convert + histogram fused
__global__ void convert_kernel(const void* __restrict__ ei,
                               const void* __restrict__ edges,
                               int E, int E2) {
    int is64 = g_is64;
    int n = E > E2 ? E : E2;
    for (int e = blockIdx.x * blockDim.x + threadIdx.x; e < n;
         e += gridDim.x * blockDim.x) {
        if (e < E) {
            int s, d;
            if (is64) {
                const long long* p = (const long long*)ei;
                s = (int)p[e];
                d = (int)p[(size_t)e + E];
            } else {
                const int* p = (const int*)ei;
                s = p[e];
                d = p[e + E];
            }
            g_src[e] = s;
            g_dst[e] = d;
            atomicAdd(&g_cnt[d], 1);
        }
        if (e < E2) {
            if (is64) {
                const long long* q = (const long long*)edges;
                g_ea[e] = (int)q[2 * (size_t)e];
                g_eb[e] = (int)q[2 * (size_t)e + 1];
            } else {
                const int* q = (const int*)edges;
                g_ea[e] = q[2 * e];
                g_eb[e] = q[2 * e + 1];
            }
        }
    }
}

// fused: x fp32 -> bf16 staging  +  weights transpose/round
__global__ void prep_xw_kernel(const float* __restrict__ x, int n8,
                               const float* __restrict__ W1l, const float* __restrict__ W1r,
                               const float* __restrict__ W2l, const float* __restrict__ W2r) {
    int i = blockIdx.x * blockDim.x + threadIdx.x;
    if (i < n8) {
        const float4* src = (const float4*)x + 2 * (size_t)i;
        float4 v0 = src[0], v1 = src[1];
        __nv_bfloat162* dst = (__nv_bfloat162*)(g_xb + (size_t)i * 8);
        dst[0] = __float22bfloat162_rn(make_float2(v0.x, v0.y));
        dst[1] = __float22bfloat162_rn(make_float2(v0.z, v0.w));
        dst[2] = __float22bfloat162_rn(make_float2(v1.x, v1.y));
        dst[3] = __float22bfloat162_rn(make_float2(v1.z, v1.w));
    }
    if (i < 256 * 256) {
        int n = i >> 8, k = i & 255;
        float v = (k < 128) ? W1l[k * HIDDEN + n] : W1r[(k - 128) * HIDDEN + n];
        g_Bt1[n * 256 + k] = __uint_as_float(rna_tf32(v));
    }
    if (i < 256 * 512) {
        int n = i >> 9, k = i & 511;
        float v = (k < 256) ? W2l[k * HIDDEN + n] : W2r[(k - 256) * HIDDEN + n];
        g_Bt2[n * 512 + k] = __uint_as_float(rna_tf32(v));
    }
}

// ---------------- CSR build: 2-level exclusive scan + cursor scatter ----------------
#define SCAN_BLK 256

__global__ void scan1_kernel(int M) {
    __shared__ int sd[SCAN_BLK];
    int i = blockIdx.x * SCAN_BLK + threadIdx.x;
    sd[threadIdx.x] = (i < M) ? g_cnt[i] : 0;
    __syncthreads();
#pragma unroll
    for (int s = SCAN_BLK / 2; s > 0; s >>= 1) {
        if (threadIdx.x < s) sd[threadIdx.x] += sd[threadIdx.x + s];
        __syncthreads();
    }
    if (threadIdx.x == 0) g_partial[blockIdx.x] = sd[0];
}

__global__ void scan2_kernel(int nb) {
    __shared__ int sd[512];
    int t = threadIdx.x;
    sd[t] = (t < nb) ? g_partial[t] : 0;
    __syncthreads();
#pragma unroll
    for (int off = 1; off < 512; off <<= 1) {
        int v = (t >= off) ? sd[t - off] : 0;
        __syncthreads();
        sd[t] += v;
        __syncthreads();
    }
    if (t < nb) g_partial[t] = (t == 0) ? 0 : sd[t - 1];
}

__global__ void scan3_kernel(int M) {
    __shared__ int sd[SCAN_BLK];
    int i = blockIdx.x * SCAN_BLK + threadIdx.x;
    int cnt = (i < M) ? g_cnt[i] : 0;
    sd[threadIdx.x] = cnt;
    __syncthreads();
#pragma unroll
    for (int off = 1; off < SCAN_BLK; off <<= 1) {
        int v = (threadIdx.x >= off) ? sd[threadIdx.x - off] : 0;
        __syncthreads();
        sd[threadIdx.x] += v;
        __syncthreads();
    }
    if (i < M) {
        int start = g_partial[blockIdx.x] + sd[threadIdx.x] - cnt;
        g_rowstart[i] = start;
        g_cursor[i] = start;
        g_invdeg[i] = 1.0f / fmaxf((float)cnt, 1.0f);
    }
}

__global__ void fill_kernel(int E) {
    for (int e = blockIdx.x * blockDim.x + threadIdx.x; e < E;
         e += gridDim.x * blockDim.x) {
        int d = g_dst[e];
        int pos = atomicAdd(&g_cursor[d], 1);
        g_csrc[pos] = g_src[e];
    }
}
// after fill_kernel: g_cursor[n] == row end

// ---------------- gather aggregation (warp per node) ----------------
// gather1: 8x MLP unroll (in-flight math: was at ~50% of latency-BW product)
__global__ void gather1_kernel(int M) {
    int w = (blockIdx.x * blockDim.x + threadIdx.x) >> 5;
    if (w >= M) return;
    int lane = threadIdx.x & 31;
    int e0 = g_rowstart[w], e1 = g_cursor[w];
    float acc[4] = {};
    const __nv_bfloat16* base = g_xb + lane * 4;
    int e = e0;
    for (; e + 8 <= e1; e += 8) {
        uint2 u[8];
#pragma unroll
        for (int j = 0; j < 8; j++) {
            int s = g_csrc[e + j];
            u[j] = *(const uint2*)(base + (size_t)s * IN_CH);
        }
#pragma unroll
        for (int j = 0; j < 8; j++) accbf4(acc, u[j]);
    }
    for (; e < e1; e++) {
        int s = g_csrc[e];
        uint2 u = *(const uint2*)(base + (size_t)s * IN_CH);
        accbf4(acc, u);
    }
    uint2 o;
    __nv_bfloat162 b0 = __float22bfloat162_rn(make_float2(acc[0], acc[1]));
    __nv_bfloat162 b1 = __float22bfloat162_rn(make_float2(acc[2], acc[3]));
    o.x = *(const uint32_t*)&b0;
    o.y = *(const uint32_t*)&b1;
    *(uint2*)(g_agg1 + (size_t)w * IN_CH + lane * 4) = o;
}

__global__ void gather2_kernel(int M) {
    int w = (blockIdx.x * blockDim.x + threadIdx.x) >> 5;
    if (w >= M) return;
    int lane = threadIdx.x & 31;
    int e0 = g_rowstart[w], e1 = g_cursor[w];
    float acc[8] = {};
    const __nv_bfloat16* base = g_h + lane * 8;
    int e = e0;
    for (; e + 4 <= e1; e += 4) {
        int s0 = g_csrc[e], s1 = g_csrc[e + 1], s2 = g_csrc[e + 2], s3 = g_csrc[e + 3];
        uint4 u0 = *(const uint4*)(base + (size_t)s0 * HIDDEN);
        uint4 u1 = *(const uint4*)(base + (size_t)s1 * HIDDEN);
        uint4 u2 = *(const uint4*)(base + (size_t)s2 * HIDDEN);
        uint4 u3 = *(const uint4*)(base + (size_t)s3 * HIDDEN);
        accbf8(acc, u0); accbf8(acc, u1); accbf8(acc, u2); accbf8(acc, u3);
    }
    for (; e < e1; e++) {
        int s = g_csrc[e];
        uint4 u = *(const uint4*)(base + (size_t)s * HIDDEN);
        accbf8(acc, u);
    }
    uint4 o;
    uint32_t* po = (uint32_t*)&o;
#pragma unroll
    for (int j = 0; j < 4; j++) {
        __nv_bfloat162 b2 = __float22bfloat162_rn(make_float2(acc[2 * j], acc[2 * j + 1]));
        po[j] = *(const uint32_t*)&b2;
    }
    *(uint4*)(g_agg2 + (size_t)w * HIDDEN + lane * 8) = o;
}

// ---------------- mma.sync tf32 fused SAGE GEMM ----------------
// Out[m,0:256] = (A0[m,:]*invdeg[m]) @ Wl + A1[m,:] @ Wr + b  (opt ReLU)
// A0BF16/A1BF16: operand stored as bf16. OUTBF16: bf16 output.
#define A_STAGE 18432u
#define B_STAGE 36864u
#define GEMM_DSMEM (2 * (A_STAGE + B_STAGE))

template <int KPART, bool RELU, bool A0BF16, bool A1BF16, bool OUTBF16>
__global__ void __launch_bounds__(256, 1)
sage_gemm_mma(const void* __restrict__ A0v, const void* __restrict__ A1v,
              const float* __restrict__ Bt, const float* __restrict__ bias,
              void* __restrict__ OutV, int M)
{
    constexpr int KCAT = 2 * KPART;
    constexpr int NC = KCAT / 32;
    extern __shared__ char sm[];
    const uint32_t smbase = smem_u32(sm);
    const uint32_t Aoff[2] = {0u, A_STAGE};
    const uint32_t Boff[2] = {2 * A_STAGE, 2 * A_STAGE + B_STAGE};

    int tid = threadIdx.x, lane = tid & 31, wid = tid >> 5;
    int m0 = blockIdx.x * 128;
    int warp_m = (wid >> 2) * 64, warp_n = (wid & 3) * 64;

    int arow = tid >> 1;
    int acol = (tid & 1) * 16;
    int grow = m0 + arow;
    bool avalid = grow < M;
    float sdeg = avalid ? g_invdeg[grow] : 0.f;

    float acc[4][8][4] = {};

    auto ldgA = [&](int ci, float4* r) {
        bool p1 = (ci * 32) >= KPART;
        if (!avalid) {
#pragma unroll
            for (int i = 0; i < 4; i++) r[i] = make_float4(0.f, 0.f, 0.f, 0.f);
            return;
        }
        if (!p1) {
            if (A0BF16) {
                ld16bf((const __nv_bfloat16*)A0v + (size_t)grow * KPART + ci * 32 + acol, r);
            } else {
                const float4* src =
                    (const float4*)((const float*)A0v + (size_t)grow * KPART + ci * 32 + acol);
#pragma unroll
                for (int i = 0; i < 4; i++) r[i] = src[i];
            }
#pragma unroll
            for (int i = 0; i < 4; i++) {
                r[i].x *= sdeg; r[i].y *= sdeg; r[i].z *= sdeg; r[i].w *= sdeg;
            }
        } else {
            int kof = ci * 32 - KPART;
            if (A1BF16) {
                ld16bf((const __nv_bfloat16*)A1v + (size_t)grow * KPART + kof + acol, r);
            } else {
                const float4* src =
                    (const float4*)((const float*)A1v + (size_t)grow * KPART + kof + acol);
#pragma unroll
                for (int i = 0; i < 4; i++) r[i] = src[i];
            }
        }
    };
    auto stsA = [&](int buf, const float4* r) {
        uint32_t a = smbase + Aoff[buf] + arow * 144 + acol * 4;
#pragma unroll
        for (int i = 0; i < 4; i++) {
            uint4 u;
            u.x = rna_tf32(r[i].x); u.y = rna_tf32(r[i].y);
            u.z = rna_tf32(r[i].z); u.w = rna_tf32(r[i].w);
            sts128(a + i * 16, u);
        }
    };
    auto cpB = [&](int ci, int buf) {
#pragma unroll
        for (int rr = 0; rr < 8; rr++) {
            int i = tid + 256 * rr;
            int n = i >> 3, kq = i & 7;
            uint32_t dst = smbase + Boff[buf] + n * 144 + kq * 16;
            const float* src = Bt + (size_t)n * KCAT + ci * 32 + kq * 4;
            cp_async16(dst, src);
        }
        cp_commit();
    };
    auto compute = [&](int buf) {
        uint32_t Ab = smbase + Aoff[buf] +
                      (warp_m + (lane & 15)) * 144 + ((lane & 16) ? 16 : 0);
        uint32_t Bb = smbase + Boff[buf] +
                      (warp_n + (lane & 7) + ((lane & 16) >> 1)) * 144 +
                      ((lane & 8) ? 16 : 0);
#pragma unroll
        for (int kk = 0; kk < 4; kk++) {
            uint32_t af[4][4];
#pragma unroll
            for (int ti = 0; ti < 4; ti++) ldsm4(af[ti], Ab + ti * 16 * 144 + kk * 32);
            uint32_t bf[4][4];
#pragma unroll
            for (int tjp = 0; tjp < 4; tjp++) ldsm4(bf[tjp], Bb + tjp * 16 * 144 + kk * 32);
#pragma unroll
            for (int ti = 0; ti < 4; ti++)
#pragma unroll
                for (int tjp = 0; tjp < 4; tjp++) {
                    mma_tf32(acc[ti][2 * tjp],     af[ti], bf[tjp][0], bf[tjp][1]);
                    mma_tf32(acc[ti][2 * tjp + 1], af[ti], bf[tjp][2], bf[tjp][3]);
                }
        }
    };

    float4 areg[4];
    ldgA(0, areg);
    cpB(0, 0);
    stsA(0, areg);

    for (int ci = 0; ci < NC; ci++) {
        int cb = ci & 1;
        float4 areg2[4];
        if (ci + 1 < NC) {
            ldgA(ci + 1, areg2);
            cpB(ci + 1, cb ^ 1);
            cp_wait<1>();
        } else {
            cp_wait<0>();
        }
        __syncthreads();
        compute(cb);
        __syncthreads();
        if (ci + 1 < NC) stsA(cb ^ 1, areg2);
    }

    int r0base = m0 + warp_m + (lane >> 2);
    int colb = warp_n + (lane & 3) * 2;
#pragma unroll
    for (int tj = 0; tj < 8; tj++) {
        int col = colb + tj * 8;
        float2 b2 = *(const float2*)(bias + col);
#pragma unroll
        for (int ti = 0; ti < 4; ti++) {
            int rr[2] = {r0base + ti * 16, r0base + ti * 16 + 8};
#pragma unroll
            for (int hh = 0; hh < 2; hh++) {
                int r = rr[hh];
                if (r >= M) continue;
                float2 v;
                v.x = acc[ti][tj][2 * hh]     + b2.x;
                v.y = acc[ti][tj][2 * hh + 1] + b2.y;
                if (RELU) { v.x = fmaxf(v.x, 0.f); v.y = fmaxf(v.y, 0.f); }
                if (OUTBF16) {
                    __nv_bfloat162 o2 = __float22bfloat162_rn(v);
                    *(__nv_bfloat162*)((__nv_bfloat16*)OutV + (size_t)r * HIDDEN + col) = o2;
                } else {
                    *(float2*)((float*)OutV + (size_t)r * HIDDEN + col) = v;
                }
            }
        }
    }
}

// ---------------- decoder: 4 pairs per warp (bf16 z, fp32 accum) ----------------
__global__ void decode_kernel(float* __restrict__ out, int E2) {
    int w = (blockIdx.x * blockDim.x + threadIdx.x) >> 5;   // warp id
    int p0 = 4 * w;
    if (p0 >= E2) return;
    int lane = threadIdx.x & 31;

    int pa[4], pb[4];
    bool has[4];
#pragma unroll
    for (int i = 0; i < 4; i++) {
        int p = p0 + i;
        has[i] = p < E2;
        int q = has[i] ? p : p0;
        pa[i] = g_ea[q];
        pb[i] = g_eb[q];
    }
    // 8 independent in-flight 16B loads per lane
    uint4 va[4], vb[4];
#pragma unroll
    for (int i = 0; i < 4; i++)
        va[i] = *((const uint4*)((const char*)(g_z + (size_t)pa[i] * HIDDEN)) + lane);
#pragma unroll
    for (int i = 0; i < 4; i++)
        vb[i] = *((const uint4*)((const char*)(g_z + (size_t)pb[i] * HIDDEN)) + lane);

    float acc[4] = {};
#pragma unroll
    for (int i = 0; i < 4; i++) dotbf8(acc[i], va[i], vb[i]);
#pragma unroll
    for (int o = 16; o > 0; o >>= 1) {
#pragma unroll
        for (int i = 0; i < 4; i++)
            acc[i] += __shfl_xor_sync(0xffffffffu, acc[i], o);
    }
    if (lane == 0) {
#pragma unroll
        for (int i = 0; i < 4; i++)
            if (has[i]) out[p0 + i] = acc[i];
    }
}

// ---------------- launch ----------------
extern "C" void kernel_launch(void* const* d_in, const int* in_sizes, int n_in,
                              void* d_out, int out_size) {
    const float* x   = (const float*)d_in[0];
    const void*  ei  = d_in[1];
    const void*  edg = d_in[2];
    const float* W1l = (const float*)d_in[3];
    const float* b1  = (const float*)d_in[4];
    const float* W1r = (const float*)d_in[5];
    const float* W2l = (const float*)d_in[6];
    const float* b2  = (const float*)d_in[7];
    const float* W2r = (const float*)d_in[8];
    float* out = (float*)d_out;

    int M  = in_sizes[0] / IN_CH;   // 100000
    int E  = in_sizes[1] / 2;       // 1.6M graph edges
    int E2 = out_size;              // 1.6M candidate pairs

    cudaFuncSetAttribute(sage_gemm_mma<128, true, true, true, true>,
                         cudaFuncAttributeMaxDynamicSharedMemorySize, GEMM_DSMEM);
    cudaFuncSetAttribute(sage_gemm_mma<256, false, true, true, true>,
                         cudaFuncAttributeMaxDynamicSharedMemorySize, GEMM_DSMEM);

    void* agg1p; cudaGetSymbolAddress(&agg1p, g_agg1);
    void* agg2p; cudaGetSymbolAddress(&agg2p, g_agg2);
    void* xbp;   cudaGetSymbolAddress(&xbp,   g_xb);
    void* hp;    cudaGetSymbolAddress(&hp,    g_h);
    void* zp;    cudaGetSymbolAddress(&zp,    g_z);
    float* bt1p; cudaGetSymbolAddress((void**)&bt1p, g_Bt1);
    float* bt2p; cudaGetSymbolAddress((void**)&bt2p, g_Bt2);
    void* cntp;  cudaGetSymbolAddress(&cntp,  g_cnt);

    int nb = (M + SCAN_BLK - 1) / SCAN_BLK;   // 391 <= 512
    int n8 = M * IN_CH / 8;                   // 1.6M x-chunks

    detect_kernel<<<1, 256>>>((const int*)ei);
    cudaMemsetAsync(cntp, 0, (size_t)M * sizeof(int));
    convert_kernel<<<4096, 256>>>(ei, edg, E, E2);
    prep_xw_kernel<<<(n8 + 255) / 256, 256>>>(x, n8, W1l, W1r, W2l, W2r);
    scan1_kernel<<<nb, SCAN_BLK>>>(M);
    scan2_kernel<<<1, 512>>>(nb);
    scan3_kernel<<<nb, SCAN_BLK>>>(M);
    fill_kernel<<<2048, 256>>>(E);

    int gtiles = (M + 127) / 128;

    // layer 1  (A0 = agg1 bf16, A1 = x bf16, h written bf16)
    gather1_kernel<<<(M * 32 + 255) / 256, 256>>>(M);
    sage_gemm_mma<128, true, true, true, true><<<gtiles, 256, GEMM_DSMEM>>>(
        agg1p, xbp, bt1p, b1, hp, M);
    // layer 2  (A0 = agg2 bf16, A1 = h bf16, z written bf16)
    gather2_kernel<<<(M * 32 + 255) / 256, 256>>>(M);
    sage_gemm_mma<256, false, true, true, true><<<gtiles, 256, GEMM_DSMEM>>>(
        agg2p, hp, bt2p, b2, zp, M);
    // decode: 4 pairs per warp
    int nwarp = (E2 + 3) / 4;
    decode_kernel<<<(nwarp * 32 + 255) / 256, 256>>>(out, E2);
}

// round 15
// speedup vs baseline: 4.5396x; 1.2598x over previous
#include <cuda_runtime.h>
#include <cuda_bf16.h>
#include <cstdint>

#define N_NODES_MAX 100000
#define IN_CH 128
#define HIDDEN 256
#define N_EDGES_MAX 1600000

// ---------------- scratch (static device globals; no allocation) ----------------
__device__ __nv_bfloat16 g_agg1[(size_t)N_NODES_MAX * IN_CH];  // 25.6 MB (bf16, pre-scaled mean)
__device__ __nv_bfloat16 g_xb[(size_t)N_NODES_MAX * IN_CH];    // 25.6 MB (bf16 x)
__device__ __nv_bfloat16 g_h[(size_t)N_NODES_MAX * HIDDEN];    // 51.2 MB (bf16)
__device__ __nv_bfloat16 g_agg2[(size_t)N_NODES_MAX * HIDDEN]; // 51.2 MB (bf16, pre-scaled mean)
__device__ __nv_bfloat16 g_z[(size_t)N_NODES_MAX * HIDDEN];    // 51.2 MB (decode-only)
__device__ float g_invdeg[N_NODES_MAX];
__device__ int   g_src[N_EDGES_MAX];
__device__ int   g_dst[N_EDGES_MAX];
__device__ int   g_ea [N_EDGES_MAX];
__device__ int   g_eb [N_EDGES_MAX];
__device__ int   g_is64;
// CSR
__device__ int   g_cnt[N_NODES_MAX];
__device__ int   g_rowstart[N_NODES_MAX];
__device__ int   g_cursor[N_NODES_MAX];
__device__ int   g_csrc[N_EDGES_MAX];
__device__ int   g_partial[512];
// pre-transposed, bf16-rounded weights: Bt[n][k_cat]  (k_cat = [Wl rows ; Wr rows])
__device__ __nv_bfloat16 g_Bt1[256 * 256];   // layer1: Kcat=256
__device__ __nv_bfloat16 g_Bt2[256 * 512];   // layer2: Kcat=512

// ---------------- small PTX helpers (sm_80-level features only) ----------------
__device__ __forceinline__ uint32_t smem_u32(const void* p) {
    uint32_t a;
    asm("{ .reg .u64 t; cvta.to.shared.u64 t, %1; cvt.u32.u64 %0, t; }" : "=r"(a) : "l"(p));
    return a;
}
__device__ __forceinline__ void sts128(uint32_t addr, uint4 v) {
    asm volatile("st.shared.v4.b32 [%0], {%1,%2,%3,%4};"
                 :: "r"(addr), "r"(v.x), "r"(v.y), "r"(v.z), "r"(v.w) : "memory");
}
__device__ __forceinline__ void cp_async16(uint32_t dst, const void* src) {
    asm volatile("cp.async.cg.shared.global [%0], [%1], 16;"
                 :: "r"(dst), "l"(src) : "memory");
}
__device__ __forceinline__ void cp_commit() {
    asm volatile("cp.async.commit_group;" ::: "memory");
}
template <int N>
__device__ __forceinline__ void cp_wait() {
    asm volatile("cp.async.wait_group %0;" :: "n"(N) : "memory");
}
__device__ __forceinline__ void ldsm4(uint32_t* r, uint32_t addr) {
    asm volatile("ldmatrix.sync.aligned.m8n8.x4.shared.b16 {%0,%1,%2,%3}, [%4];"
                 : "=r"(r[0]), "=r"(r[1]), "=r"(r[2]), "=r"(r[3]) : "r"(addr));
}
// bf16 m16n8k16 MMA, fp32 accumulate
__device__ __forceinline__ void mma_bf16(float* c, const uint32_t* a,
                                         uint32_t b0, uint32_t b1) {
    asm volatile(
        "mma.sync.aligned.m16n8k16.row.col.f32.bf16.bf16.f32 "
        "{%0,%1,%2,%3}, {%4,%5,%6,%7}, {%8,%9}, {%0,%1,%2,%3};"
        : "+f"(c[0]), "+f"(c[1]), "+f"(c[2]), "+f"(c[3])
        : "r"(a[0]), "r"(a[1]), "r"(a[2]), "r"(a[3]), "r"(b0), "r"(b1));
}
// accumulate 4 bf16 (uint2) into 4 floats
__device__ __forceinline__ void accbf4(float* acc, uint2 u) {
    float2 f0 = __bfloat1622float2(*(const __nv_bfloat162*)&u.x);
    float2 f1 = __bfloat1622float2(*(const __nv_bfloat162*)&u.y);
    acc[0] += f0.x; acc[1] += f0.y; acc[2] += f1.x; acc[3] += f1.y;
}
// accumulate 8 bf16 (uint4) into 8 floats
__device__ __forceinline__ void accbf8(float* acc, uint4 u) {
    const uint32_t* p = (const uint32_t*)&u;
#pragma unroll
    for (int j = 0; j < 4; j++) {
        float2 f = __bfloat1622float2(*(const __nv_bfloat162*)&p[j]);
        acc[2 * j]     += f.x;
        acc[2 * j + 1] += f.y;
    }
}
// dot-accumulate two uint4 bf16 vectors into fp32 scalar
__device__ __forceinline__ void dotbf8(float& acc, uint4 ua, uint4 ub) {
    const uint32_t* pa = (const uint32_t*)&ua;
    const uint32_t* pb = (const uint32_t*)&ub;
#pragma unroll
    for (int j = 0; j < 4; j++) {
        float2 fa = __bfloat1622float2(*(const __nv_bfloat162*)&pa[j]);
        float2 fb = __bfloat1622float2(*(const __nv_bfloat162*)&pb[j]);
        acc = fmaf(fa.x, fb.x, acc);
        acc = fmaf(fa.y, fb.y, acc);
    }
}

// ---------------- dtype detection (int64 vs int32 edge indices) ----------------
__global__ void detect_kernel(const int* __restrict__ ei32) {
    __shared__ int bad;
    if (threadIdx.x == 0) bad = 0;
    __syncthreads();
    for (int i = threadIdx.x; i < 2048; i += blockDim.x)
        if (ei32[2 * i + 1] != 0) bad = 1;
    __syncthreads();
    if (threadIdx.x == 0) g_is64 = bad ? 0 : 1;
}

// convert + histogram fused
__global__ void convert_kernel(const void* __restrict__ ei,
                               const void* __restrict__ edges,
                               int E, int E2) {
    int is64 = g_is64;
    int n = E > E2 ? E : E2;
    for (int e = blockIdx.x * blockDim.x + threadIdx.x; e < n;
         e += gridDim.x * blockDim.x) {
        if (e < E) {
            int s, d;
            if (is64) {
                const long long* p = (const long long*)ei;
                s = (int)p[e];
                d = (int)p[(size_t)e + E];
            } else {
                const int* p = (const int*)ei;
                s = p[e];
                d = p[e + E];
            }
            g_src[e] = s;
            g_dst[e] = d;
            atomicAdd(&g_cnt[d], 1);
        }
        if (e < E2) {
            if (is64) {
                const long long* q = (const long long*)edges;
                g_ea[e] = (int)q[2 * (size_t)e];
                g_eb[e] = (int)q[2 * (size_t)e + 1];
            } else {
                const int* q = (const int*)edges;
                g_ea[e] = q[2 * e];
                g_eb[e] = q[2 * e + 1];
            }
        }
    }
}

// fused: x fp32 -> bf16 staging  +  weights transpose/round (bf16)
__global__ void prep_xw_kernel(const float* __restrict__ x, int n8,
                               const float* __restrict__ W1l, const float* __restrict__ W1r,
                               const float* __restrict__ W2l, const float* __restrict__ W2r) {
    int i = blockIdx.x * blockDim.x + threadIdx.x;
    if (i < n8) {
        const float4* src = (const float4*)x + 2 * (size_t)i;
        float4 v0 = src[0], v1 = src[1];
        __nv_bfloat162* dst = (__nv_bfloat162*)(g_xb + (size_t)i * 8);
        dst[0] = __float22bfloat162_rn(make_float2(v0.x, v0.y));
        dst[1] = __float22bfloat162_rn(make_float2(v0.z, v0.w));
        dst[2] = __float22bfloat162_rn(make_float2(v1.x, v1.y));
        dst[3] = __float22bfloat162_rn(make_float2(v1.z, v1.w));
    }
    if (i < 256 * 256) {
        int n = i >> 8, k = i & 255;
        float v = (k < 128) ? W1l[k * HIDDEN + n] : W1r[(k - 128) * HIDDEN + n];
        g_Bt1[n * 256 + k] = __float2bfloat16_rn(v);
    }
    if (i < 256 * 512) {
        int n = i >> 9, k = i & 511;
        float v = (k < 256) ? W2l[k * HIDDEN + n] : W2r[(k - 256) * HIDDEN + n];
        g_Bt2[n * 512 + k] = __float2bfloat16_rn(v);
    }
}

// ---------------- CSR build: 2-level exclusive scan + cursor scatter ----------------
#define SCAN_BLK 256

__global__ void scan1_kernel(int M) {
    __shared__ int sd[SCAN_BLK];
    int i = blockIdx.x * SCAN_BLK + threadIdx.x;
    sd[threadIdx.x] = (i < M) ? g_cnt[i] : 0;
    __syncthreads();
#pragma unroll
    for (int s = SCAN_BLK / 2; s > 0; s >>= 1) {
        if (threadIdx.x < s) sd[threadIdx.x] += sd[threadIdx.x + s];
        __syncthreads();
    }
    if (threadIdx.x == 0) g_partial[blockIdx.x] = sd[0];
}

__global__ void scan2_kernel(int nb) {
    __shared__ int sd[512];
    int t = threadIdx.x;
    sd[t] = (t < nb) ? g_partial[t] : 0;
    __syncthreads();
#pragma unroll
    for (int off = 1; off < 512; off <<= 1) {
        int v = (t >= off) ? sd[t - off] : 0;
        __syncthreads();
        sd[t] += v;
        __syncthreads();
    }
    if (t < nb) g_partial[t] = (t == 0) ? 0 : sd[t - 1];
}

__global__ void scan3_kernel(int M) {
    __shared__ int sd[SCAN_BLK];
    int i = blockIdx.x * SCAN_BLK + threadIdx.x;
    int cnt = (i < M) ? g_cnt[i] : 0;
    sd[threadIdx.x] = cnt;
    __syncthreads();
#pragma unroll
    for (int off = 1; off < SCAN_BLK; off <<= 1) {
        int v = (threadIdx.x >= off) ? sd[threadIdx.x - off] : 0;
        __syncthreads();
        sd[threadIdx.x] += v;
        __syncthreads();
    }
    if (i < M) {
        int start = g_partial[blockIdx.x] + sd[threadIdx.x] - cnt;
        g_rowstart[i] = start;
        g_cursor[i] = start;
        g_invdeg[i] = 1.0f / fmaxf((float)cnt, 1.0f);
    }
}

__global__ void fill_kernel(int E) {
    for (int e = blockIdx.x * blockDim.x + threadIdx.x; e < E;
         e += gridDim.x * blockDim.x) {
        int d = g_dst[e];
        int pos = atomicAdd(&g_cursor[d], 1);
        g_csrc[pos] = g_src[e];
    }
}
// after fill_kernel: g_cursor[n] == row end

// ---------------- gather aggregation (warp per node; writes PRE-SCALED mean) ----------------
__global__ void gather1_kernel(int M) {
    int w = (blockIdx.x * blockDim.x + threadIdx.x) >> 5;
    if (w >= M) return;
    int lane = threadIdx.x & 31;
    int e0 = g_rowstart[w], e1 = g_cursor[w];
    float acc[4] = {};
    const __nv_bfloat16* base = g_xb + lane * 4;
    int e = e0;
    for (; e + 8 <= e1; e += 8) {
        uint2 u[8];
#pragma unroll
        for (int j = 0; j < 8; j++) {
            int s = g_csrc[e + j];
            u[j] = *(const uint2*)(base + (size_t)s * IN_CH);
        }
#pragma unroll
        for (int j = 0; j < 8; j++) accbf4(acc, u[j]);
    }
    for (; e < e1; e++) {
        int s = g_csrc[e];
        uint2 u = *(const uint2*)(base + (size_t)s * IN_CH);
        accbf4(acc, u);
    }
    float inv = g_invdeg[w];
#pragma unroll
    for (int j = 0; j < 4; j++) acc[j] *= inv;
    uint2 o;
    __nv_bfloat162 b0 = __float22bfloat162_rn(make_float2(acc[0], acc[1]));
    __nv_bfloat162 b1 = __float22bfloat162_rn(make_float2(acc[2], acc[3]));
    o.x = *(const uint32_t*)&b0;
    o.y = *(const uint32_t*)&b1;
    *(uint2*)(g_agg1 + (size_t)w * IN_CH + lane * 4) = o;
}

__global__ void gather2_kernel(int M) {
    int w = (blockIdx.x * blockDim.x + threadIdx.x) >> 5;
    if (w >= M) return;
    int lane = threadIdx.x & 31;
    int e0 = g_rowstart[w], e1 = g_cursor[w];
    float acc[8] = {};
    const __nv_bfloat16* base = g_h + lane * 8;
    int e = e0;
    for (; e + 4 <= e1; e += 4) {
        int s0 = g_csrc[e], s1 = g_csrc[e + 1], s2 = g_csrc[e + 2], s3 = g_csrc[e + 3];
        uint4 u0 = *(const uint4*)(base + (size_t)s0 * HIDDEN);
        uint4 u1 = *(const uint4*)(base + (size_t)s1 * HIDDEN);
        uint4 u2 = *(const uint4*)(base + (size_t)s2 * HIDDEN);
        uint4 u3 = *(const uint4*)(base + (size_t)s3 * HIDDEN);
        accbf8(acc, u0); accbf8(acc, u1); accbf8(acc, u2); accbf8(acc, u3);
    }
    for (; e < e1; e++) {
        int s = g_csrc[e];
        uint4 u = *(const uint4*)(base + (size_t)s * HIDDEN);
        accbf8(acc, u);
    }
    float inv = g_invdeg[w];
#pragma unroll
    for (int j = 0; j < 8; j++) acc[j] *= inv;
    uint4 o;
    uint32_t* po = (uint32_t*)&o;
#pragma unroll
    for (int j = 0; j < 4; j++) {
        __nv_bfloat162 b2 = __float22bfloat162_rn(make_float2(acc[2 * j], acc[2 * j + 1]));
        po[j] = *(const uint32_t*)&b2;
    }
    *(uint4*)(g_agg2 + (size_t)w * HIDDEN + lane * 8) = o;
}

// ---------------- bf16 m16n8k16 fused SAGE GEMM ----------------
// Out[m,0:256] = A0mean[m,:] @ Wl + A1[m,:] @ Wr + b  (opt ReLU); all operands bf16.
// CTA 128x256, 8 warps (2x4), warp tile 64x64, BK=32 (2 k16 slices).
// smem rows padded to 80B (5x16B -> conflict-free ldsm).
#define A_ROW 80u
#define A_STAGE (128u * A_ROW)       // 10240
#define B_STAGE (256u * A_ROW)       // 20480
#define GEMM_DSMEM (2 * (A_STAGE + B_STAGE))   // 61440

template <int KPART, bool RELU>
__global__ void __launch_bounds__(256, 1)
sage_gemm_bf16(const __nv_bfloat16* __restrict__ A0,
               const __nv_bfloat16* __restrict__ A1,
               const __nv_bfloat16* __restrict__ Bt,
               const float* __restrict__ bias,
               __nv_bfloat16* __restrict__ Out, int M)
{
    constexpr int KCAT = 2 * KPART;
    constexpr int NC = KCAT / 32;
    extern __shared__ char sm[];
    const uint32_t smbase = smem_u32(sm);
    const uint32_t Aoff[2] = {0u, A_STAGE};
    const uint32_t Boff[2] = {2 * A_STAGE, 2 * A_STAGE + B_STAGE};

    int tid = threadIdx.x, lane = tid & 31, wid = tid >> 5;
    int m0 = blockIdx.x * 128;
    int warp_m = (wid >> 2) * 64, warp_n = (wid & 3) * 64;

    // A staging: thread handles row tid>>1, half (tid&1): 16 bf16 = 32B
    int arow = tid >> 1;
    int ahalf = tid & 1;
    int grow = m0 + arow;
    bool avalid = grow < M;

    float acc[4][8][4] = {};

    auto ldgA = [&](int ci, uint4* u) {
        bool p1 = (ci * 32) >= KPART;
        if (!avalid) {
            u[0] = make_uint4(0, 0, 0, 0);
            u[1] = make_uint4(0, 0, 0, 0);
            return;
        }
        const __nv_bfloat16* A = p1 ? A1 : A0;
        int kof = (p1 ? ci * 32 - KPART : ci * 32) + ahalf * 16;
        const uint4* src = (const uint4*)(A + (size_t)grow * KPART + kof);
        u[0] = src[0];
        u[1] = src[1];
    };
    auto stA = [&](int buf, const uint4* u) {
        uint32_t a = smbase + Aoff[buf] + arow * A_ROW + ahalf * 32;
        sts128(a, u[0]);
        sts128(a + 16, u[1]);
    };
    auto cpB = [&](int ci, int buf) {
#pragma unroll
        for (int rr = 0; rr < 4; rr++) {
            int i = tid + 256 * rr;       // 0..1023
            int n = i >> 2, kq = i & 3;   // 16B unit within 64B row
            uint32_t dst = smbase + Boff[buf] + n * A_ROW + kq * 16;
            const __nv_bfloat16* src = Bt + (size_t)n * KCAT + ci * 32 + kq * 8;
            cp_async16(dst, src);
        }
        cp_commit();
    };
    auto compute = [&](int buf) {
        uint32_t Ab = smbase + Aoff[buf] +
                      (warp_m + (lane & 15)) * A_ROW + ((lane & 16) ? 16 : 0);
        uint32_t Bb = smbase + Boff[buf] +
                      (warp_n + (lane & 15)) * A_ROW + ((lane & 16) ? 16 : 0);
#pragma unroll
        for (int ks = 0; ks < 2; ks++) {
            uint32_t af[4][4];
#pragma unroll
            for (int ti = 0; ti < 4; ti++)
                ldsm4(af[ti], Ab + ti * 16 * A_ROW + ks * 32);
            uint32_t bfr[4][4];
#pragma unroll
            for (int tjp = 0; tjp < 4; tjp++)
                ldsm4(bfr[tjp], Bb + tjp * 16 * A_ROW + ks * 32);
#pragma unroll
            for (int ti = 0; ti < 4; ti++)
#pragma unroll
                for (int tjp = 0; tjp < 4; tjp++) {
                    mma_bf16(acc[ti][2 * tjp],     af[ti], bfr[tjp][0], bfr[tjp][2]);
                    mma_bf16(acc[ti][2 * tjp + 1], af[ti], bfr[tjp][1], bfr[tjp][3]);
                }
        }
    };

    uint4 areg[2];
    ldgA(0, areg);
    cpB(0, 0);
    stA(0, areg);

    for (int ci = 0; ci < NC; ci++) {
        int cb = ci & 1;
        uint4 areg2[2];
        if (ci + 1 < NC) {
            ldgA(ci + 1, areg2);
            cpB(ci + 1, cb ^ 1);
            cp_wait<1>();
        } else {
            cp_wait<0>();
        }
        __syncthreads();
        compute(cb);
        __syncthreads();
        if (ci + 1 < NC) stA(cb ^ 1, areg2);
    }

    int r0base = m0 + warp_m + (lane >> 2);
    int colb = warp_n + (lane & 3) * 2;
#pragma unroll
    for (int tj = 0; tj < 8; tj++) {
        int col = colb + tj * 8;
        float2 b2 = *(const float2*)(bias + col);
#pragma unroll
        for (int ti = 0; ti < 4; ti++) {
            int rr[2] = {r0base + ti * 16, r0base + ti * 16 + 8};
#pragma unroll
            for (int hh = 0; hh < 2; hh++) {
                int r = rr[hh];
                if (r >= M) continue;
                float2 v;
                v.x = acc[ti][tj][2 * hh]     + b2.x;
                v.y = acc[ti][tj][2 * hh + 1] + b2.y;
                if (RELU) { v.x = fmaxf(v.x, 0.f); v.y = fmaxf(v.y, 0.f); }
                __nv_bfloat162 o2 = __float22bfloat162_rn(v);
                *(__nv_bfloat162*)(Out + (size_t)r * HIDDEN + col) = o2;
            }
        }
    }
}

// ---------------- decoder: 4 pairs per warp (bf16 z, fp32 accum) ----------------
__global__ void decode_kernel(float* __restrict__ out, int E2) {
    int w = (blockIdx.x * blockDim.x + threadIdx.x) >> 5;   // warp id
    int p0 = 4 * w;
    if (p0 >= E2) return;
    int lane = threadIdx.x & 31;

    int pa[4], pb[4];
    bool has[4];
#pragma unroll
    for (int i = 0; i < 4; i++) {
        int p = p0 + i;
        has[i] = p < E2;
        int q = has[i] ? p : p0;
        pa[i] = g_ea[q];
        pb[i] = g_eb[q];
    }
    uint4 va[4], vb[4];
#pragma unroll
    for (int i = 0; i < 4; i++)
        va[i] = *((const uint4*)((const char*)(g_z + (size_t)pa[i] * HIDDEN)) + lane);
#pragma unroll
    for (int i = 0; i < 4; i++)
        vb[i] = *((const uint4*)((const char*)(g_z + (size_t)pb[i] * HIDDEN)) + lane);

    float acc[4] = {};
#pragma unroll
    for (int i = 0; i < 4; i++) dotbf8(acc[i], va[i], vb[i]);
#pragma unroll
    for (int o = 16; o > 0; o >>= 1) {
#pragma unroll
        for (int i = 0; i < 4; i++)
            acc[i] += __shfl_xor_sync(0xffffffffu, acc[i], o);
    }
    if (lane == 0) {
#pragma unroll
        for (int i = 0; i < 4; i++)
            if (has[i]) out[p0 + i] = acc[i];
    }
}

// ---------------- launch ----------------
extern "C" void kernel_launch(void* const* d_in, const int* in_sizes, int n_in,
                              void* d_out, int out_size) {
    const float* x   = (const float*)d_in[0];
    const void*  ei  = d_in[1];
    const void*  edg = d_in[2];
    const float* W1l = (const float*)d_in[3];
    const float* b1  = (const float*)d_in[4];
    const float* W1r = (const float*)d_in[5];
    const float* W2l = (const float*)d_in[6];
    const float* b2  = (const float*)d_in[7];
    const float* W2r = (const float*)d_in[8];
    float* out = (float*)d_out;

    int M  = in_sizes[0] / IN_CH;   // 100000
    int E  = in_sizes[1] / 2;       // 1.6M graph edges
    int E2 = out_size;              // 1.6M candidate pairs

    cudaFuncSetAttribute(sage_gemm_bf16<128, true>,
                         cudaFuncAttributeMaxDynamicSharedMemorySize, GEMM_DSMEM);
    cudaFuncSetAttribute(sage_gemm_bf16<256, false>,
                         cudaFuncAttributeMaxDynamicSharedMemorySize, GEMM_DSMEM);

    void* agg1p; cudaGetSymbolAddress(&agg1p, g_agg1);
    void* agg2p; cudaGetSymbolAddress(&agg2p, g_agg2);
    void* xbp;   cudaGetSymbolAddress(&xbp,   g_xb);
    void* hp;    cudaGetSymbolAddress(&hp,    g_h);
    void* zp;    cudaGetSymbolAddress(&zp,    g_z);
    void* bt1p;  cudaGetSymbolAddress(&bt1p,  g_Bt1);
    void* bt2p;  cudaGetSymbolAddress(&bt2p,  g_Bt2);
    void* cntp;  cudaGetSymbolAddress(&cntp,  g_cnt);

    int nb = (M + SCAN_BLK - 1) / SCAN_BLK;   // 391 <= 512
    int n8 = M * IN_CH / 8;                   // 1.6M x-chunks

    detect_kernel<<<1, 256>>>((const int*)ei);
    cudaMemsetAsync(cntp, 0, (size_t)M * sizeof(int));
    convert_kernel<<<4096, 256>>>(ei, edg, E, E2);
    prep_xw_kernel<<<(n8 + 255) / 256, 256>>>(x, n8, W1l, W1r, W2l, W2r);
    scan1_kernel<<<nb, SCAN_BLK>>>(M);
    scan2_kernel<<<1, 512>>>(nb);
    scan3_kernel<<<nb, SCAN_BLK>>>(M);
    fill_kernel<<<2048, 256>>>(E);

    int gtiles = (M + 127) / 128;

    // layer 1  (A0 = pre-scaled agg1 bf16, A1 = x bf16, h written bf16)
    gather1_kernel<<<(M * 32 + 255) / 256, 256>>>(M);
    sage_gemm_bf16<128, true><<<gtiles, 256, GEMM_DSMEM>>>(
        (const __nv_bfloat16*)agg1p, (const __nv_bfloat16*)xbp,
        (const __nv_bfloat16*)bt1p, b1, (__nv_bfloat16*)hp, M);
    // layer 2  (A0 = pre-scaled agg2 bf16, A1 = h bf16, z written bf16)
    gather2_kernel<<<(M * 32 + 255) / 256, 256>>>(M);
    sage_gemm_bf16<256, false><<<gtiles, 256, GEMM_DSMEM>>>(
        (const __nv_bfloat16*)agg2p, (const __nv_bfloat16*)hp,
        (const __nv_bfloat16*)bt2p, b2, (__nv_bfloat16*)zp, M);
    // decode: 4 pairs per warp
    int nwarp = (E2 + 3) / 4;
    decode_kernel<<<(nwarp * 32 + 255) / 256, 256>>>(out, E2);
}